// round 1
// baseline (speedup 1.0000x reference)
#include <cuda_runtime.h>
#include <math.h>

// Problem constants
#define BB 2
#define NN 2048
#define DD 512
#define HH 8
#define FF 8
#define HD 64
#define DA 80   // augmented head dim: 64 (Q/K) + 8 (cos) + 8 (sin)

// ---------------- scratch (device globals; no allocation) ----------------
__device__ float g_Qa[BB*HH*NN*DA];   // augmented Q, pre-scaled by 1/sqrt(HD) on the 64 K-part dims
__device__ float g_Ka[BB*HH*NN*DA];   // augmented K
__device__ float g_V [BB*HH*NN*HD];
__device__ float g_att[BB*NN*DD];     // attended, [B,N,D] with D = h*64+hd

// ---------------- generic 512-K SGEMM: out = (A @ W^T + bias) * scale ----------------
// A: [M,512] row-major, W: [512,512] row-major (out = A W^T), M = 4096
// mode 0: plain out[m*512+o]
// mode 1: Qa layout ld=80, mode 2: Ka layout ld=80, mode 3: V layout ld=64
__global__ __launch_bounds__(256) void gemm512_kernel(
    const float* __restrict__ A, const float* __restrict__ W,
    const float* __restrict__ bias, float* __restrict__ out,
    int mode, float scale)
{
    __shared__ float As[32*68];
    __shared__ float Ws[32*68];

    const int t  = threadIdx.x;
    const int tx = t & 15;
    const int ty = t >> 4;
    const int m0 = blockIdx.y * 64;
    const int o0 = blockIdx.x * 64;

    float acc[4][4];
#pragma unroll
    for (int j = 0; j < 4; j++)
#pragma unroll
        for (int i = 0; i < 4; i++) acc[j][i] = 0.f;

    for (int k0 = 0; k0 < 512; k0 += 32) {
#pragma unroll
        for (int i = 0; i < 2; i++) {
            int idx = t + i * 256;          // 0..511
            int row = idx >> 3;             // 0..63
            int k4  = (idx & 7) << 2;       // 0..28
            float4 av = *(const float4*)&A[(size_t)(m0 + row) * 512 + k0 + k4];
            As[(k4+0)*68 + row] = av.x;
            As[(k4+1)*68 + row] = av.y;
            As[(k4+2)*68 + row] = av.z;
            As[(k4+3)*68 + row] = av.w;
            float4 wv = *(const float4*)&W[(size_t)(o0 + row) * 512 + k0 + k4];
            Ws[(k4+0)*68 + row] = wv.x;
            Ws[(k4+1)*68 + row] = wv.y;
            Ws[(k4+2)*68 + row] = wv.z;
            Ws[(k4+3)*68 + row] = wv.w;
        }
        __syncthreads();
#pragma unroll
        for (int k = 0; k < 32; k++) {
            float4 a4 = *(const float4*)&As[k*68 + ty*4];
            float4 b4 = *(const float4*)&Ws[k*68 + tx*4];
            float a[4] = {a4.x, a4.y, a4.z, a4.w};
            float b[4] = {b4.x, b4.y, b4.z, b4.w};
#pragma unroll
            for (int j = 0; j < 4; j++)
#pragma unroll
                for (int i = 0; i < 4; i++)
                    acc[j][i] = fmaf(a[j], b[i], acc[j][i]);
        }
        __syncthreads();
    }

    float4 bb = *(const float4*)&bias[o0 + tx*4];
#pragma unroll
    for (int j = 0; j < 4; j++) {
        int m = m0 + ty*4 + j;
        float4 v;
        v.x = (acc[j][0] + bb.x) * scale;
        v.y = (acc[j][1] + bb.y) * scale;
        v.z = (acc[j][2] + bb.z) * scale;
        v.w = (acc[j][3] + bb.w) * scale;
        if (mode == 0) {
            *(float4*)&out[(size_t)m * 512 + o0 + tx*4] = v;
        } else {
            int b  = m >> 11;          // /2048
            int n  = m & 2047;
            int o  = o0 + tx*4;
            int h  = o >> 6;
            int hd = o & 63;
            int ld = (mode == 3) ? HD : DA;
            *(float4*)&out[((size_t)((b*HH + h) * NN + n)) * ld + hd] = v;
        }
    }
}

// ---------------- phase augmentation fill ----------------
// Qa[...,64+f] = pb[h,f]*cos(pc), Qa[...,72+f] = pb[h,f]*sin(pc)
// Ka[...,64+f] = cos(pc),         Ka[...,72+f] = sin(pc)
__global__ void phase_fill_kernel(const float* __restrict__ pc,
                                  const float* __restrict__ pb,
                                  float* __restrict__ Qa, float* __restrict__ Ka)
{
    int idx = blockIdx.x * blockDim.x + threadIdx.x;   // 0..B*N-1
    if (idx >= BB * NN) return;
    int b = idx >> 11;
    int n = idx & 2047;

    float c[FF], s[FF];
#pragma unroll
    for (int f = 0; f < FF; f++) {
        float ph = pc[(size_t)idx * FF + f];
        __sincosf(ph, &s[f], &c[f]);
    }
#pragma unroll
    for (int h = 0; h < HH; h++) {
        size_t base = ((size_t)((b*HH + h) * NN + n)) * DA + 64;
#pragma unroll
        for (int f = 0; f < FF; f++) {
            float w = pb[h*FF + f];
            Qa[base + f]     = w * c[f];
            Qa[base + 8 + f] = w * s[f];
            Ka[base + f]     = c[f];
            Ka[base + 8 + f] = s[f];
        }
    }
}

// ---------------- flash attention (fp32, DA=80, HD=64) ----------------
// grid: (N/64, B*H), 256 threads, dynamic smem
#define SM_QS 0
#define SM_KS (DA*68)
#define SM_VS (2*DA*68)
#define SM_PS (2*DA*68 + 64*68)
#define ATTN_SMEM ((2*DA*68 + 2*64*68) * 4)

__global__ __launch_bounds__(256) void attn_kernel(
    const float* __restrict__ Qa, const float* __restrict__ Ka,
    const float* __restrict__ V, float* __restrict__ out)
{
    extern __shared__ float sm[];
    float* Qs = sm + SM_QS;   // [80][68] transposed: Qs[d][q]
    float* Ks = sm + SM_KS;   // [80][68] transposed: Ks[d][k]
    float* Vs = sm + SM_VS;   // [64][68]: Vs[k][d]
    float* Ps = sm + SM_PS;   // [64][68]: Ps[q][k]

    const int t  = threadIdx.x;
    const int tx = t & 15;
    const int ty = t >> 4;
    const int q0 = blockIdx.x * 64;
    const int bh = blockIdx.y;

    const float* Qg = Qa + (size_t)bh * NN * DA;
    const float* Kg = Ka + (size_t)bh * NN * DA;
    const float* Vg = V  + (size_t)bh * NN * HD;

    // load Q tile transposed (64 rows x 80 cols)
#pragma unroll
    for (int i = 0; i < 5; i++) {
        int idx = t + i * 256;          // 0..1279
        int row = idx / 20;
        int c4  = (idx % 20) * 4;
        float4 v = *(const float4*)&Qg[(size_t)(q0 + row) * DA + c4];
        Qs[(c4+0)*68 + row] = v.x;
        Qs[(c4+1)*68 + row] = v.y;
        Qs[(c4+2)*68 + row] = v.z;
        Qs[(c4+3)*68 + row] = v.w;
    }

    float m_r[4], l_r[4], O[4][4];
#pragma unroll
    for (int j = 0; j < 4; j++) {
        m_r[j] = -1e30f;
        l_r[j] = 0.f;
#pragma unroll
        for (int i = 0; i < 4; i++) O[j][i] = 0.f;
    }

    for (int k0 = 0; k0 < NN; k0 += 64) {
        __syncthreads();   // prev PV done before overwriting Ks/Vs (also covers Q-load first iter)
        // load K tile transposed
#pragma unroll
        for (int i = 0; i < 5; i++) {
            int idx = t + i * 256;
            int row = idx / 20;
            int c4  = (idx % 20) * 4;
            float4 v = *(const float4*)&Kg[(size_t)(k0 + row) * DA + c4];
            Ks[(c4+0)*68 + row] = v.x;
            Ks[(c4+1)*68 + row] = v.y;
            Ks[(c4+2)*68 + row] = v.z;
            Ks[(c4+3)*68 + row] = v.w;
        }
        // load V tile (direct)
#pragma unroll
        for (int i = 0; i < 4; i++) {
            int idx = t + i * 256;
            int row = idx >> 4;
            int c4  = (idx & 15) << 2;
            float4 v = *(const float4*)&Vg[(size_t)(k0 + row) * HD + c4];
            *(float4*)&Vs[row*68 + c4] = v;
        }
        __syncthreads();

        // S = Qa . Ka (already includes 1/sqrt(HD) scale + phase bias)
        float s[4][4];
#pragma unroll
        for (int j = 0; j < 4; j++)
#pragma unroll
            for (int i = 0; i < 4; i++) s[j][i] = 0.f;

#pragma unroll 8
        for (int d = 0; d < DA; d++) {
            float4 a4 = *(const float4*)&Qs[d*68 + ty*4];
            float4 b4 = *(const float4*)&Ks[d*68 + tx*4];
            float a[4] = {a4.x, a4.y, a4.z, a4.w};
            float b[4] = {b4.x, b4.y, b4.z, b4.w};
#pragma unroll
            for (int j = 0; j < 4; j++)
#pragma unroll
                for (int i = 0; i < 4; i++)
                    s[j][i] = fmaf(a[j], b[i], s[j][i]);
        }

        // online softmax (row-wise over 64 keys: reduce across 16 tx lanes)
#pragma unroll
        for (int j = 0; j < 4; j++) {
            float rm = fmaxf(fmaxf(s[j][0], s[j][1]), fmaxf(s[j][2], s[j][3]));
#pragma unroll
            for (int off = 8; off >= 1; off >>= 1)
                rm = fmaxf(rm, __shfl_xor_sync(0xffffffffu, rm, off));
            float mn  = fmaxf(m_r[j], rm);
            float fac = __expf(m_r[j] - mn);
            float rs  = 0.f;
#pragma unroll
            for (int i = 0; i < 4; i++) {
                s[j][i] = __expf(s[j][i] - mn);
                rs += s[j][i];
            }
#pragma unroll
            for (int off = 8; off >= 1; off >>= 1)
                rs += __shfl_xor_sync(0xffffffffu, rs, off);
            l_r[j] = l_r[j] * fac + rs;
            m_r[j] = mn;
#pragma unroll
            for (int i = 0; i < 4; i++) O[j][i] *= fac;
            *(float4*)&Ps[(ty*4+j)*68 + tx*4] = make_float4(s[j][0], s[j][1], s[j][2], s[j][3]);
        }
        __syncthreads();

        // O += P @ V
#pragma unroll 8
        for (int c = 0; c < 64; c++) {
            float4 b4 = *(const float4*)&Vs[c*68 + tx*4];
            float bv[4] = {b4.x, b4.y, b4.z, b4.w};
#pragma unroll
            for (int j = 0; j < 4; j++) {
                float a = Ps[(ty*4+j)*68 + c];
#pragma unroll
                for (int i = 0; i < 4; i++)
                    O[j][i] = fmaf(a, bv[i], O[j][i]);
            }
        }
    }

    // epilogue
    int b = bh >> 3;
    int h = bh & 7;
#pragma unroll
    for (int j = 0; j < 4; j++) {
        float inv = 1.0f / l_r[j];
        int n = q0 + ty*4 + j;
        float4 v;
        v.x = O[j][0] * inv;
        v.y = O[j][1] * inv;
        v.z = O[j][2] * inv;
        v.w = O[j][3] * inv;
        *(float4*)&out[((size_t)(b*NN + n)) * DD + h*HD + tx*4] = v;
    }
}

// ---------------- launch ----------------
extern "C" void kernel_launch(void* const* d_in, const int* in_sizes, int n_in,
                              void* d_out, int out_size)
{
    const float* x   = (const float*)d_in[0];
    const float* pc  = (const float*)d_in[1];
    const float* Wq  = (const float*)d_in[2];
    const float* bq  = (const float*)d_in[3];
    const float* Wk  = (const float*)d_in[4];
    const float* bk  = (const float*)d_in[5];
    const float* Wv  = (const float*)d_in[6];
    const float* bv  = (const float*)d_in[7];
    const float* Wo  = (const float*)d_in[8];
    const float* bo  = (const float*)d_in[9];
    const float* pb  = (const float*)d_in[10];
    float* out = (float*)d_out;

    float *qa, *ka, *vv, *att;
    cudaGetSymbolAddress((void**)&qa,  g_Qa);
    cudaGetSymbolAddress((void**)&ka,  g_Ka);
    cudaGetSymbolAddress((void**)&vv,  g_V);
    cudaGetSymbolAddress((void**)&att, g_att);

    static bool attr_set = false;
    // (deterministic each call; setting an attribute twice is harmless)
    cudaFuncSetAttribute(attn_kernel, cudaFuncAttributeMaxDynamicSharedMemorySize, ATTN_SMEM);
    (void)attr_set;

    dim3 ggrid(8, (BB*NN)/64);   // (512/64, 4096/64)
    const float inv_sqrt_hd = 0.125f;   // 1/sqrt(64)

    gemm512_kernel<<<ggrid, 256>>>(x, Wq, bq, qa, 1, inv_sqrt_hd);
    gemm512_kernel<<<ggrid, 256>>>(x, Wk, bk, ka, 2, 1.0f);
    gemm512_kernel<<<ggrid, 256>>>(x, Wv, bv, vv, 3, 1.0f);

    phase_fill_kernel<<<(BB*NN + 127)/128, 128>>>(pc, pb, qa, ka);

    dim3 agrid(NN/64, BB*HH);
    attn_kernel<<<agrid, 256, ATTN_SMEM>>>(qa, ka, vv, att);

    gemm512_kernel<<<ggrid, 256>>>(att, Wo, bo, out, 0, 1.0f);
}

// round 3
// speedup vs baseline: 2.7960x; 2.7960x over previous
#include <cuda_runtime.h>
#include <cuda_bf16.h>
#include <cstdint>
#include <math.h>

// Problem constants
#define BB 2
#define NN 2048
#define DD 512
#define HH 8
#define FF 8
#define HD 64
#define DA 80   // augmented head dim: 64 (Q/K) + 8 (cos) + 8 (sin)
#define BQ 64   // q rows per CTA (attention)
#define BK 64   // keys per tile

// ---------------- scratch (device globals; no allocation) ----------------
__device__ float g_Qa[BB*HH*NN*DA];   // [B,H,N,80], Q-part pre-scaled by 1/8
__device__ float g_Ka[BB*HH*NN*DA];   // [B,H,N,80]
__device__ float g_V [BB*HH*NN*HD];   // [B,H,N,64]
__device__ float g_att[BB*NN*DD];     // attended, [B,N,D]

// ======================= MMA / ldmatrix helpers =======================
__device__ __forceinline__ uint32_t smem_u32(const void* p){
    uint32_t a;
    asm("{ .reg .u64 t; cvta.to.shared.u64 t, %1; cvt.u32.u64 %0, t; }" : "=r"(a) : "l"(p));
    return a;
}
__device__ __forceinline__ void ldsm_x4(uint32_t addr, uint32_t r[4]){
    asm volatile("ldmatrix.sync.aligned.m8n8.x4.shared.b16 {%0,%1,%2,%3}, [%4];"
        : "=r"(r[0]), "=r"(r[1]), "=r"(r[2]), "=r"(r[3]) : "r"(addr));
}
__device__ __forceinline__ void ldsm_x2(uint32_t addr, uint32_t r[2]){
    asm volatile("ldmatrix.sync.aligned.m8n8.x2.shared.b16 {%0,%1}, [%2];"
        : "=r"(r[0]), "=r"(r[1]) : "r"(addr));
}
__device__ __forceinline__ void ldsm_x2t(uint32_t addr, uint32_t r[2]){
    asm volatile("ldmatrix.sync.aligned.m8n8.x2.trans.shared.b16 {%0,%1}, [%2];"
        : "=r"(r[0]), "=r"(r[1]) : "r"(addr));
}
// D = A(16x16 bf16, row) * B(16x8 bf16, col) + D (fp32)
__device__ __forceinline__ void mma16816(float c[4], const uint32_t a[4], const uint32_t b[2]){
    asm volatile("mma.sync.aligned.m16n8k16.row.col.f32.bf16.bf16.f32 "
        "{%0,%1,%2,%3}, {%4,%5,%6,%7}, {%8,%9}, {%0,%1,%2,%3};"
        : "+f"(c[0]), "+f"(c[1]), "+f"(c[2]), "+f"(c[3])
        : "r"(a[0]), "r"(a[1]), "r"(a[2]), "r"(a[3]), "r"(b[0]), "r"(b[1]));
}
__device__ __forceinline__ uint32_t b2u(__nv_bfloat162 v){ return *reinterpret_cast<uint32_t*>(&v); }

// split a float4 into hi/lo bf16x2 pairs and store (8B each) at (row, c4)
__device__ __forceinline__ void cvt_store4(char* smem, uint32_t hi_off, uint32_t lo_off,
                                           int row, int c4, int stride, float4 v){
    __nv_bfloat162 h01 = __floats2bfloat162_rn(v.x, v.y);
    __nv_bfloat162 h23 = __floats2bfloat162_rn(v.z, v.w);
    __nv_bfloat162 l01 = __floats2bfloat162_rn(v.x - __low2float(h01), v.y - __high2float(h01));
    __nv_bfloat162 l23 = __floats2bfloat162_rn(v.z - __low2float(h23), v.w - __high2float(h23));
    uint32_t off = (uint32_t)(row * stride + c4) * 2u;
    uint2 uh; uh.x = b2u(h01); uh.y = b2u(h23);
    uint2 ul; ul.x = b2u(l01); ul.y = b2u(l23);
    *(uint2*)(smem + hi_off + off) = uh;
    *(uint2*)(smem + lo_off + off) = ul;
}

// ================= bf16x3 MMA GEMM: out = (A @ W^T + bias) * scale =================
// A: [4096,512] row-major, W: [512,512] row-major. CTA tile 128x128, 8 warps (64x32 each).
// mode 0: out[m*512+o]; mode 1: [B,H,N,80] head layout; mode 3: [B,H,N,64]
#define AS 40                         // smem stride (elements) for 32-wide k panel
#define GS_AH 0
#define GS_AL (GS_AH + 128*AS*2)      // 10240 B each
#define GS_WH (GS_AL + 128*AS*2)
#define GS_WL (GS_WH + 128*AS*2)
#define GEMM_SMEM (GS_WL + 128*AS*2)  // 40960 B

__global__ __launch_bounds__(256) void gemm_mma_kernel(
    const float* __restrict__ A, const float* __restrict__ W,
    const float* __restrict__ bias, float* __restrict__ out,
    int mode, float scale)
{
    extern __shared__ char smem[];
    uint32_t sb = smem_u32(smem);
    const int t    = threadIdx.x;
    const int lane = t & 31;
    const int w    = t >> 5;
    const int wm   = w >> 2;          // 0..1
    const int wn   = w & 3;           // 0..3
    const int m0   = blockIdx.y * 128;
    const int o0   = blockIdx.x * 128;

    float Cs[4][4][4];
#pragma unroll
    for (int mb = 0; mb < 4; mb++)
#pragma unroll
        for (int nb = 0; nb < 4; nb++)
#pragma unroll
            for (int i = 0; i < 4; i++) Cs[mb][nb][i] = 0.f;

    const int a_r  = (lane & 7) + ((lane & 8) ? 8 : 0);  // ldmatrix row-within-16
    const int a_c8 = (lane & 16) ? 8 : 0;                // ldmatrix col half (x4)
    const int b_r  = lane & 7;
    const int b_c8 = (lane & 8) ? 8 : 0;                 // (x2)

    for (int k0 = 0; k0 < 512; k0 += 32) {
        __syncthreads();
#pragma unroll
        for (int i = 0; i < 4; i++) {
            int idx = t + i * 256;          // 0..1023
            int row = idx >> 3;             // 0..127
            int c4  = (idx & 7) << 2;       // 0..28
            float4 av = *(const float4*)&A[(size_t)(m0 + row) * 512 + k0 + c4];
            cvt_store4(smem, GS_AH, GS_AL, row, c4, AS, av);
            float4 wv = *(const float4*)&W[(size_t)(o0 + row) * 512 + k0 + c4];
            cvt_store4(smem, GS_WH, GS_WL, row, c4, AS, wv);
        }
        __syncthreads();

#pragma unroll
        for (int ks = 0; ks < 2; ks++) {
            uint32_t Ah[4][4], Al[4][4], Wh[4][2], Wl[4][2];
#pragma unroll
            for (int mb = 0; mb < 4; mb++) {
                uint32_t ad = sb + (uint32_t)(((wm*64 + mb*16 + a_r) * AS + ks*16 + a_c8) * 2);
                ldsm_x4(ad + GS_AH, Ah[mb]);
                ldsm_x4(ad + GS_AL, Al[mb]);
            }
#pragma unroll
            for (int nb = 0; nb < 4; nb++) {
                uint32_t wd = sb + (uint32_t)(((wn*32 + nb*8 + b_r) * AS + ks*16 + b_c8) * 2);
                ldsm_x2(wd + GS_WH, Wh[nb]);
                ldsm_x2(wd + GS_WL, Wl[nb]);
            }
#pragma unroll
            for (int mb = 0; mb < 4; mb++)
#pragma unroll
                for (int nb = 0; nb < 4; nb++) {
                    mma16816(Cs[mb][nb], Ah[mb], Wh[nb]);
                    mma16816(Cs[mb][nb], Ah[mb], Wl[nb]);
                    mma16816(Cs[mb][nb], Al[mb], Wh[nb]);
                }
        }
    }

    // epilogue
    const int r0l = lane >> 2;
    const int c0l = (lane & 3) * 2;
#pragma unroll
    for (int mb = 0; mb < 4; mb++) {
#pragma unroll
        for (int nb = 0; nb < 4; nb++) {
            int gc = o0 + wn*32 + nb*8 + c0l;
            float2 bb = *(const float2*)&bias[gc];
#pragma unroll
            for (int half = 0; half < 2; half++) {
                int gr = m0 + wm*64 + mb*16 + r0l + half*8;
                float vx = (Cs[mb][nb][half*2+0] + bb.x) * scale;
                float vy = (Cs[mb][nb][half*2+1] + bb.y) * scale;
                float2 v; v.x = vx; v.y = vy;
                if (mode == 0) {
                    *(float2*)&out[(size_t)gr * 512 + gc] = v;
                } else {
                    int b  = gr >> 11;
                    int n  = gr & 2047;
                    int h  = gc >> 6;
                    int hd = gc & 63;
                    int ld = (mode == 3) ? HD : DA;
                    *(float2*)&out[((size_t)((b*HH + h) * NN + n)) * ld + hd] = v;
                }
            }
        }
    }
}

// ---------------- phase augmentation fill ----------------
__global__ void phase_fill_kernel(const float* __restrict__ pc,
                                  const float* __restrict__ pb,
                                  float* __restrict__ Qa, float* __restrict__ Ka)
{
    int idx = blockIdx.x * blockDim.x + threadIdx.x;
    if (idx >= BB * NN) return;
    int b = idx >> 11;
    int n = idx & 2047;

    float c[FF], s[FF];
#pragma unroll
    for (int f = 0; f < FF; f++) {
        float phv = pc[(size_t)idx * FF + f];
        __sincosf(phv, &s[f], &c[f]);
    }
#pragma unroll
    for (int h = 0; h < HH; h++) {
        size_t base = ((size_t)((b*HH + h) * NN + n)) * DA + 64;
#pragma unroll
        for (int f = 0; f < FF; f++) {
            float w = pb[h*FF + f];
            Qa[base + f]     = w * c[f];
            Qa[base + 8 + f] = w * s[f];
            Ka[base + f]     = c[f];
            Ka[base + 8 + f] = s[f];
        }
    }
}

// =============== bf16x3 warp-MMA flash attention ===============
#define QS 88     // smem stride (elems) for 80-wide Q/K rows
#define VS 72     // smem stride for 64-wide V rows
#define SM_QH 0
#define SM_QL (SM_QH + 64*QS*2)     // 11264 each
#define SM_KH (SM_QL + 64*QS*2)
#define SM_KL (SM_KH + 64*QS*2)
#define SM_VH (SM_KL + 64*QS*2)
#define SM_VL (SM_VH + 64*VS*2)     // 9216 each
#define ATTN_SMEM (SM_VL + 64*VS*2) // 63488 B

__global__ __launch_bounds__(128) void attn_mma_kernel(
    const float* __restrict__ Qa, const float* __restrict__ Ka,
    const float* __restrict__ V, float* __restrict__ out)
{
    extern __shared__ char smem[];
    uint32_t sb = smem_u32(smem);
    const int t    = threadIdx.x;
    const int lane = t & 31;
    const int w    = t >> 5;          // 0..3, warp owns q rows w*16..w*16+15
    const int q0   = blockIdx.x * BQ;
    const int bh   = blockIdx.y;

    const float* Qg = Qa + (size_t)bh * NN * DA + (size_t)q0 * DA;
    const float* Kg = Ka + (size_t)bh * NN * DA;
    const float* Vg = V  + (size_t)bh * NN * HD;

    // ---- load + split Q tile (64 x 80) ----
#pragma unroll
    for (int i = 0; i < 10; i++) {
        int idx = t + i * 128;          // 0..1279
        int row = idx / 20;
        int c4  = (idx % 20) * 4;
        float4 v = *(const float4*)(Qg + (size_t)row * DA + c4);
        cvt_store4(smem, SM_QH, SM_QL, row, c4, QS, v);
    }
    __syncthreads();

    // ---- Q fragments (kept in registers for all tiles) ----
    const int a_r  = (lane & 7) + ((lane & 8) ? 8 : 0);
    const int a_c8 = (lane & 16) ? 8 : 0;
    const int b_r  = lane & 7;
    const int b_c8 = (lane & 8) ? 8 : 0;

    uint32_t Qh[5][4], Ql[5][4];
#pragma unroll
    for (int s = 0; s < 5; s++) {
        uint32_t ad = sb + (uint32_t)(((w*16 + a_r) * QS + s*16 + a_c8) * 2);
        ldsm_x4(ad + SM_QH, Qh[s]);
        ldsm_x4(ad + SM_QL, Ql[s]);
    }

    float mrow[2] = {-1e30f, -1e30f};
    float lrow[2] = {0.f, 0.f};
    float Od[8][4];
#pragma unroll
    for (int db = 0; db < 8; db++)
#pragma unroll
        for (int i = 0; i < 4; i++) Od[db][i] = 0.f;

#pragma unroll 1
    for (int k0 = 0; k0 < NN; k0 += BK) {
        __syncthreads();
        // ---- load + split K (64x80) and V (64x64) ----
#pragma unroll
        for (int i = 0; i < 10; i++) {
            int idx = t + i * 128;
            int row = idx / 20;
            int c4  = (idx % 20) * 4;
            float4 v = *(const float4*)(Kg + (size_t)(k0 + row) * DA + c4);
            cvt_store4(smem, SM_KH, SM_KL, row, c4, QS, v);
        }
#pragma unroll
        for (int i = 0; i < 8; i++) {
            int idx = t + i * 128;
            int row = idx >> 4;
            int c4  = (idx & 15) << 2;
            float4 v = *(const float4*)(Vg + (size_t)(k0 + row) * HD + c4);
            cvt_store4(smem, SM_VH, SM_VL, row, c4, VS, v);
        }
        __syncthreads();

        // ---- S = Q . K^T  (bf16x3) ----
        float Cs[8][4];
#pragma unroll
        for (int nb = 0; nb < 8; nb++)
#pragma unroll
            for (int i = 0; i < 4; i++) Cs[nb][i] = 0.f;

#pragma unroll
        for (int s = 0; s < 5; s++) {
#pragma unroll
            for (int nb = 0; nb < 8; nb++) {
                uint32_t kd = sb + (uint32_t)(((nb*8 + b_r) * QS + s*16 + b_c8) * 2);
                uint32_t bh2[2], bl2[2];
                ldsm_x2(kd + SM_KH, bh2);
                ldsm_x2(kd + SM_KL, bl2);
                mma16816(Cs[nb], Qh[s], bh2);
                mma16816(Cs[nb], Qh[s], bl2);
                mma16816(Cs[nb], Ql[s], bh2);
            }
        }

        // ---- online softmax on C-fragment layout ----
        float mx0 = -1e30f, mx1 = -1e30f;
#pragma unroll
        for (int nb = 0; nb < 8; nb++) {
            mx0 = fmaxf(mx0, fmaxf(Cs[nb][0], Cs[nb][1]));
            mx1 = fmaxf(mx1, fmaxf(Cs[nb][2], Cs[nb][3]));
        }
        mx0 = fmaxf(mx0, __shfl_xor_sync(0xffffffffu, mx0, 1));
        mx0 = fmaxf(mx0, __shfl_xor_sync(0xffffffffu, mx0, 2));
        mx1 = fmaxf(mx1, __shfl_xor_sync(0xffffffffu, mx1, 1));
        mx1 = fmaxf(mx1, __shfl_xor_sync(0xffffffffu, mx1, 2));
        float mn0 = fmaxf(mrow[0], mx0);
        float mn1 = fmaxf(mrow[1], mx1);
        float f0  = __expf(mrow[0] - mn0);
        float f1  = __expf(mrow[1] - mn1);
        mrow[0] = mn0; mrow[1] = mn1;

        float s0 = 0.f, s1 = 0.f;
        uint32_t Ph[4][4], Pl[4][4];
#pragma unroll
        for (int ks = 0; ks < 4; ks++) {
#pragma unroll
            for (int hf = 0; hf < 2; hf++) {
                int nb = 2*ks + hf;
                float p0 = __expf(Cs[nb][0] - mn0);
                float p1 = __expf(Cs[nb][1] - mn0);
                float p2 = __expf(Cs[nb][2] - mn1);
                float p3 = __expf(Cs[nb][3] - mn1);
                s0 += p0 + p1;
                s1 += p2 + p3;
                __nv_bfloat162 h01 = __floats2bfloat162_rn(p0, p1);
                __nv_bfloat162 h23 = __floats2bfloat162_rn(p2, p3);
                __nv_bfloat162 l01 = __floats2bfloat162_rn(p0 - __low2float(h01), p1 - __high2float(h01));
                __nv_bfloat162 l23 = __floats2bfloat162_rn(p2 - __low2float(h23), p3 - __high2float(h23));
                Ph[ks][hf*2+0] = b2u(h01);
                Ph[ks][hf*2+1] = b2u(h23);
                Pl[ks][hf*2+0] = b2u(l01);
                Pl[ks][hf*2+1] = b2u(l23);
            }
        }
        s0 += __shfl_xor_sync(0xffffffffu, s0, 1);
        s0 += __shfl_xor_sync(0xffffffffu, s0, 2);
        s1 += __shfl_xor_sync(0xffffffffu, s1, 1);
        s1 += __shfl_xor_sync(0xffffffffu, s1, 2);
        lrow[0] = lrow[0] * f0 + s0;
        lrow[1] = lrow[1] * f1 + s1;

        // rescale O
#pragma unroll
        for (int db = 0; db < 8; db++) {
            Od[db][0] *= f0; Od[db][1] *= f0;
            Od[db][2] *= f1; Od[db][3] *= f1;
        }

        // ---- O += P . V  (bf16x3; V via ldmatrix.trans) ----
#pragma unroll
        for (int ks = 0; ks < 4; ks++) {
#pragma unroll
            for (int db = 0; db < 8; db++) {
                uint32_t vd = sb + (uint32_t)(((ks*16 + a_r % 16) * VS + db*8) * 2);
                // rows for x2.trans: lanes0-7 -> keys ks*16+0..7, lanes8-15 -> +8
                uint32_t vaddr = sb + (uint32_t)(((ks*16 + b_r + ((lane & 8) ? 8 : 0)) * VS + db*8) * 2);
                (void)vd;
                uint32_t vh2[2], vl2[2];
                ldsm_x2t(vaddr + SM_VH, vh2);
                ldsm_x2t(vaddr + SM_VL, vl2);
                mma16816(Od[db], Ph[ks], vh2);
                mma16816(Od[db], Ph[ks], vl2);
                mma16816(Od[db], Pl[ks], vh2);
            }
        }
    }

    // ---- epilogue ----
    float i0 = 1.0f / lrow[0];
    float i1 = 1.0f / lrow[1];
    int b = bh >> 3, h = bh & 7;
    int r0l = w*16 + (lane >> 2);
    int c0l = (lane & 3) * 2;
#pragma unroll
    for (int db = 0; db < 8; db++) {
        int gc = h*64 + db*8 + c0l;
        float2 v0; v0.x = Od[db][0] * i0; v0.y = Od[db][1] * i0;
        float2 v1; v1.x = Od[db][2] * i1; v1.y = Od[db][3] * i1;
        *(float2*)&out[((size_t)(b*NN + q0 + r0l)) * DD + gc] = v0;
        *(float2*)&out[((size_t)(b*NN + q0 + r0l + 8)) * DD + gc] = v1;
    }
}

// ---------------- launch ----------------
extern "C" void kernel_launch(void* const* d_in, const int* in_sizes, int n_in,
                              void* d_out, int out_size)
{
    const float* x   = (const float*)d_in[0];
    const float* pc  = (const float*)d_in[1];
    const float* Wq  = (const float*)d_in[2];
    const float* bq  = (const float*)d_in[3];
    const float* Wk  = (const float*)d_in[4];
    const float* bk  = (const float*)d_in[5];
    const float* Wv  = (const float*)d_in[6];
    const float* bv  = (const float*)d_in[7];
    const float* Wo  = (const float*)d_in[8];
    const float* bo  = (const float*)d_in[9];
    const float* pb  = (const float*)d_in[10];
    float* out = (float*)d_out;

    float *qa, *ka, *vv, *att;
    cudaGetSymbolAddress((void**)&qa,  g_Qa);
    cudaGetSymbolAddress((void**)&ka,  g_Ka);
    cudaGetSymbolAddress((void**)&vv,  g_V);
    cudaGetSymbolAddress((void**)&att, g_att);

    cudaFuncSetAttribute(attn_mma_kernel, cudaFuncAttributeMaxDynamicSharedMemorySize, ATTN_SMEM);
    cudaFuncSetAttribute(gemm_mma_kernel, cudaFuncAttributeMaxDynamicSharedMemorySize, GEMM_SMEM);

    dim3 ggrid(4, 32);   // (512/128, 4096/128)
    const float inv_sqrt_hd = 0.125f;

    gemm_mma_kernel<<<ggrid, 256, GEMM_SMEM>>>(x, Wq, bq, qa, 1, inv_sqrt_hd);
    gemm_mma_kernel<<<ggrid, 256, GEMM_SMEM>>>(x, Wk, bk, ka, 1, 1.0f);
    gemm_mma_kernel<<<ggrid, 256, GEMM_SMEM>>>(x, Wv, bv, vv, 3, 1.0f);

    phase_fill_kernel<<<(BB*NN + 127)/128, 128>>>(pc, pb, qa, ka);

    dim3 agrid(NN/BQ, BB*HH);   // (32, 16)
    attn_mma_kernel<<<agrid, 128, ATTN_SMEM>>>(qa, ka, vv, att);

    gemm_mma_kernel<<<ggrid, 256, GEMM_SMEM>>>(att, Wo, bo, out, 0, 1.0f);
}

// round 4
// speedup vs baseline: 3.3765x; 1.2076x over previous
#include <cuda_runtime.h>
#include <cuda_bf16.h>
#include <cstdint>
#include <math.h>

// Problem constants
#define BB 2
#define NN 2048
#define DD 512
#define HH 8
#define FF 8
#define HD 64
#define DA 80   // augmented head dim: 64 (Q/K) + 8 (cos) + 8 (sin)
#define BQ 128  // q rows per CTA (attention)
#define BK 64   // keys per tile

// ---------------- scratch (device globals; no allocation) ----------------
__device__ __nv_bfloat16 g_Qh[BB*HH*NN*DA];
__device__ __nv_bfloat16 g_Ql[BB*HH*NN*DA];
__device__ __nv_bfloat16 g_Kh[BB*HH*NN*DA];
__device__ __nv_bfloat16 g_Kl[BB*HH*NN*DA];
__device__ __nv_bfloat16 g_Vh[BB*HH*NN*HD];
__device__ __nv_bfloat16 g_Vl[BB*HH*NN*HD];
__device__ float g_att[BB*NN*DD];     // attended, [B,N,D]

// ======================= MMA / ldmatrix helpers =======================
__device__ __forceinline__ uint32_t smem_u32(const void* p){
    uint32_t a;
    asm("{ .reg .u64 t; cvta.to.shared.u64 t, %1; cvt.u32.u64 %0, t; }" : "=r"(a) : "l"(p));
    return a;
}
__device__ __forceinline__ void ldsm_x4(uint32_t addr, uint32_t r[4]){
    asm volatile("ldmatrix.sync.aligned.m8n8.x4.shared.b16 {%0,%1,%2,%3}, [%4];"
        : "=r"(r[0]), "=r"(r[1]), "=r"(r[2]), "=r"(r[3]) : "r"(addr));
}
__device__ __forceinline__ void ldsm_x2(uint32_t addr, uint32_t r[2]){
    asm volatile("ldmatrix.sync.aligned.m8n8.x2.shared.b16 {%0,%1}, [%2];"
        : "=r"(r[0]), "=r"(r[1]) : "r"(addr));
}
__device__ __forceinline__ void ldsm_x2t(uint32_t addr, uint32_t r[2]){
    asm volatile("ldmatrix.sync.aligned.m8n8.x2.trans.shared.b16 {%0,%1}, [%2];"
        : "=r"(r[0]), "=r"(r[1]) : "r"(addr));
}
__device__ __forceinline__ void mma16816(float c[4], const uint32_t a[4], const uint32_t b[2]){
    asm volatile("mma.sync.aligned.m16n8k16.row.col.f32.bf16.bf16.f32 "
        "{%0,%1,%2,%3}, {%4,%5,%6,%7}, {%8,%9}, {%0,%1,%2,%3};"
        : "+f"(c[0]), "+f"(c[1]), "+f"(c[2]), "+f"(c[3])
        : "r"(a[0]), "r"(a[1]), "r"(a[2]), "r"(a[3]), "r"(b[0]), "r"(b[1]));
}
__device__ __forceinline__ uint32_t b2u(__nv_bfloat162 v){ return *reinterpret_cast<uint32_t*>(&v); }

// split float4 into hi/lo bf16x2 pairs and store into smem (GEMM A/W staging)
__device__ __forceinline__ void cvt_store4(char* smem, uint32_t hi_off, uint32_t lo_off,
                                           int row, int c4, int stride, float4 v){
    __nv_bfloat162 h01 = __floats2bfloat162_rn(v.x, v.y);
    __nv_bfloat162 h23 = __floats2bfloat162_rn(v.z, v.w);
    __nv_bfloat162 l01 = __floats2bfloat162_rn(v.x - __low2float(h01), v.y - __high2float(h01));
    __nv_bfloat162 l23 = __floats2bfloat162_rn(v.z - __low2float(h23), v.w - __high2float(h23));
    uint32_t off = (uint32_t)(row * stride + c4) * 2u;
    uint2 uh; uh.x = b2u(h01); uh.y = b2u(h23);
    uint2 ul; ul.x = b2u(l01); ul.y = b2u(l23);
    *(uint2*)(smem + hi_off + off) = uh;
    *(uint2*)(smem + lo_off + off) = ul;
}

// ================= shared GEMM staging layout =================
#define AS 40
#define GS_AH 0
#define GS_AL (GS_AH + 128*AS*2)
#define GS_WH (GS_AL + 128*AS*2)
#define GS_WL (GS_WH + 128*AS*2)
#define GEMM_SMEM (GS_WL + 128*AS*2)  // 40960 B

// ================= fused QKV projection GEMM (bf16x3 MMA) =================
// grid (4, 32, 3); z=0:Q z=1:K z=2:V. Writes bf16 hi/lo head layouts.
__global__ __launch_bounds__(256) void qkv_mma_kernel(
    const float* __restrict__ x,
    const float* __restrict__ Wq, const float* __restrict__ bq,
    const float* __restrict__ Wk, const float* __restrict__ bk,
    const float* __restrict__ Wv, const float* __restrict__ bv)
{
    extern __shared__ char smem[];
    uint32_t sb = smem_u32(smem);
    const int t    = threadIdx.x;
    const int lane = t & 31;
    const int w    = t >> 5;
    const int wm   = w >> 2;
    const int wn   = w & 3;
    const int m0   = blockIdx.y * 128;
    const int o0   = blockIdx.x * 128;
    const int z    = blockIdx.z;

    const float* W    = (z == 0) ? Wq : (z == 1) ? Wk : Wv;
    const float* bias = (z == 0) ? bq : (z == 1) ? bk : bv;
    __nv_bfloat16* dh = (z == 0) ? g_Qh : (z == 1) ? g_Kh : g_Vh;
    __nv_bfloat16* dl = (z == 0) ? g_Ql : (z == 1) ? g_Kl : g_Vl;
    const float scale = (z == 0) ? 0.125f : 1.0f;
    const int   ld    = (z == 2) ? HD : DA;

    float Cs[4][4][4];
#pragma unroll
    for (int mb = 0; mb < 4; mb++)
#pragma unroll
        for (int nb = 0; nb < 4; nb++)
#pragma unroll
            for (int i = 0; i < 4; i++) Cs[mb][nb][i] = 0.f;

    const int a_r  = (lane & 7) + ((lane & 8) ? 8 : 0);
    const int a_c8 = (lane & 16) ? 8 : 0;
    const int b_r  = lane & 7;
    const int b_c8 = (lane & 8) ? 8 : 0;

    for (int k0 = 0; k0 < 512; k0 += 32) {
        __syncthreads();
#pragma unroll
        for (int i = 0; i < 4; i++) {
            int idx = t + i * 256;
            int row = idx >> 3;
            int c4  = (idx & 7) << 2;
            float4 av = *(const float4*)&x[(size_t)(m0 + row) * 512 + k0 + c4];
            cvt_store4(smem, GS_AH, GS_AL, row, c4, AS, av);
            float4 wv = *(const float4*)&W[(size_t)(o0 + row) * 512 + k0 + c4];
            cvt_store4(smem, GS_WH, GS_WL, row, c4, AS, wv);
        }
        __syncthreads();

#pragma unroll
        for (int ks = 0; ks < 2; ks++) {
            uint32_t Ah[4][4], Al[4][4], Wh[4][2], Wl[4][2];
#pragma unroll
            for (int mb = 0; mb < 4; mb++) {
                uint32_t ad = sb + (uint32_t)(((wm*64 + mb*16 + a_r) * AS + ks*16 + a_c8) * 2);
                ldsm_x4(ad + GS_AH, Ah[mb]);
                ldsm_x4(ad + GS_AL, Al[mb]);
            }
#pragma unroll
            for (int nb = 0; nb < 4; nb++) {
                uint32_t wd = sb + (uint32_t)(((wn*32 + nb*8 + b_r) * AS + ks*16 + b_c8) * 2);
                ldsm_x2(wd + GS_WH, Wh[nb]);
                ldsm_x2(wd + GS_WL, Wl[nb]);
            }
#pragma unroll
            for (int mb = 0; mb < 4; mb++)
#pragma unroll
                for (int nb = 0; nb < 4; nb++) {
                    mma16816(Cs[mb][nb], Ah[mb], Wh[nb]);
                    mma16816(Cs[mb][nb], Ah[mb], Wl[nb]);
                    mma16816(Cs[mb][nb], Al[mb], Wh[nb]);
                }
        }
    }

    const int r0l = lane >> 2;
    const int c0l = (lane & 3) * 2;
#pragma unroll
    for (int mb = 0; mb < 4; mb++) {
#pragma unroll
        for (int nb = 0; nb < 4; nb++) {
            int gc = o0 + wn*32 + nb*8 + c0l;
            float2 bbv = *(const float2*)&bias[gc];
            int h  = gc >> 6;
            int hd = gc & 63;
#pragma unroll
            for (int half = 0; half < 2; half++) {
                int gr = m0 + wm*64 + mb*16 + r0l + half*8;
                float vx = (Cs[mb][nb][half*2+0] + bbv.x) * scale;
                float vy = (Cs[mb][nb][half*2+1] + bbv.y) * scale;
                __nv_bfloat162 hi = __floats2bfloat162_rn(vx, vy);
                __nv_bfloat162 lo = __floats2bfloat162_rn(vx - __low2float(hi), vy - __high2float(hi));
                int b  = gr >> 11;
                int n  = gr & 2047;
                size_t off = ((size_t)((b*HH + h) * NN + n)) * ld + hd;
                *(uint32_t*)&dh[off] = b2u(hi);
                *(uint32_t*)&dl[off] = b2u(lo);
            }
        }
    }
}

// ================= output projection GEMM (fp32 in, fp32 out) =================
__global__ __launch_bounds__(256) void gemm_mma_kernel(
    const float* __restrict__ A, const float* __restrict__ W,
    const float* __restrict__ bias, float* __restrict__ out)
{
    extern __shared__ char smem[];
    uint32_t sb = smem_u32(smem);
    const int t    = threadIdx.x;
    const int lane = t & 31;
    const int w    = t >> 5;
    const int wm   = w >> 2;
    const int wn   = w & 3;
    const int m0   = blockIdx.y * 128;
    const int o0   = blockIdx.x * 128;

    float Cs[4][4][4];
#pragma unroll
    for (int mb = 0; mb < 4; mb++)
#pragma unroll
        for (int nb = 0; nb < 4; nb++)
#pragma unroll
            for (int i = 0; i < 4; i++) Cs[mb][nb][i] = 0.f;

    const int a_r  = (lane & 7) + ((lane & 8) ? 8 : 0);
    const int a_c8 = (lane & 16) ? 8 : 0;
    const int b_r  = lane & 7;
    const int b_c8 = (lane & 8) ? 8 : 0;

    for (int k0 = 0; k0 < 512; k0 += 32) {
        __syncthreads();
#pragma unroll
        for (int i = 0; i < 4; i++) {
            int idx = t + i * 256;
            int row = idx >> 3;
            int c4  = (idx & 7) << 2;
            float4 av = *(const float4*)&A[(size_t)(m0 + row) * 512 + k0 + c4];
            cvt_store4(smem, GS_AH, GS_AL, row, c4, AS, av);
            float4 wv = *(const float4*)&W[(size_t)(o0 + row) * 512 + k0 + c4];
            cvt_store4(smem, GS_WH, GS_WL, row, c4, AS, wv);
        }
        __syncthreads();

#pragma unroll
        for (int ks = 0; ks < 2; ks++) {
            uint32_t Ah[4][4], Al[4][4], Wh[4][2], Wl[4][2];
#pragma unroll
            for (int mb = 0; mb < 4; mb++) {
                uint32_t ad = sb + (uint32_t)(((wm*64 + mb*16 + a_r) * AS + ks*16 + a_c8) * 2);
                ldsm_x4(ad + GS_AH, Ah[mb]);
                ldsm_x4(ad + GS_AL, Al[mb]);
            }
#pragma unroll
            for (int nb = 0; nb < 4; nb++) {
                uint32_t wd = sb + (uint32_t)(((wn*32 + nb*8 + b_r) * AS + ks*16 + b_c8) * 2);
                ldsm_x2(wd + GS_WH, Wh[nb]);
                ldsm_x2(wd + GS_WL, Wl[nb]);
            }
#pragma unroll
            for (int mb = 0; mb < 4; mb++)
#pragma unroll
                for (int nb = 0; nb < 4; nb++) {
                    mma16816(Cs[mb][nb], Ah[mb], Wh[nb]);
                    mma16816(Cs[mb][nb], Ah[mb], Wl[nb]);
                    mma16816(Cs[mb][nb], Al[mb], Wh[nb]);
                }
        }
    }

    const int r0l = lane >> 2;
    const int c0l = (lane & 3) * 2;
#pragma unroll
    for (int mb = 0; mb < 4; mb++) {
#pragma unroll
        for (int nb = 0; nb < 4; nb++) {
            int gc = o0 + wn*32 + nb*8 + c0l;
            float2 bbv = *(const float2*)&bias[gc];
#pragma unroll
            for (int half = 0; half < 2; half++) {
                int gr = m0 + wm*64 + mb*16 + r0l + half*8;
                float2 v;
                v.x = Cs[mb][nb][half*2+0] + bbv.x;
                v.y = Cs[mb][nb][half*2+1] + bbv.y;
                *(float2*)&out[(size_t)gr * 512 + gc] = v;
            }
        }
    }
}

// ---------------- phase augmentation fill (bf16 hi/lo, vectorized) ----------------
__device__ __forceinline__ void pack8(const float* v, uint4& hi, uint4& lo){
    uint32_t h[4], l[4];
#pragma unroll
    for (int i = 0; i < 4; i++) {
        __nv_bfloat162 hh = __floats2bfloat162_rn(v[2*i], v[2*i+1]);
        __nv_bfloat162 ll = __floats2bfloat162_rn(v[2*i]   - __low2float(hh),
                                                  v[2*i+1] - __high2float(hh));
        h[i] = b2u(hh); l[i] = b2u(ll);
    }
    hi.x = h[0]; hi.y = h[1]; hi.z = h[2]; hi.w = h[3];
    lo.x = l[0]; lo.y = l[1]; lo.z = l[2]; lo.w = l[3];
}

__global__ void phase_fill_kernel(const float* __restrict__ pc,
                                  const float* __restrict__ pb)
{
    int tid = blockIdx.x * blockDim.x + threadIdx.x;   // 0..B*N*H-1
    if (tid >= BB * NN * HH) return;
    int h  = tid >> 12;          // / (B*N)
    int bn = tid & 4095;

    float c[FF], s[FF], wc[FF], ws[FF];
#pragma unroll
    for (int f = 0; f < FF; f++)
        __sincosf(pc[(size_t)bn * FF + f], &s[f], &c[f]);
#pragma unroll
    for (int f = 0; f < FF; f++) {
        float wv = pb[h*FF + f];
        wc[f] = wv * c[f];
        ws[f] = wv * s[f];
    }

    int b = bn >> 11, n = bn & 2047;
    size_t base = ((size_t)((b*HH + h) * NN + n)) * DA + 64;

    uint4 hi, lo;
    pack8(c,  hi, lo); *(uint4*)&g_Kh[base]   = hi; *(uint4*)&g_Kl[base]   = lo;
    pack8(s,  hi, lo); *(uint4*)&g_Kh[base+8] = hi; *(uint4*)&g_Kl[base+8] = lo;
    pack8(wc, hi, lo); *(uint4*)&g_Qh[base]   = hi; *(uint4*)&g_Ql[base]   = lo;
    pack8(ws, hi, lo); *(uint4*)&g_Qh[base+8] = hi; *(uint4*)&g_Ql[base+8] = lo;
}

// =============== bf16x3 warp-MMA flash attention (BQ=128, 8 warps) ===============
#define QS 88     // smem stride (elems) for 80-wide Q/K rows
#define VS 72     // smem stride for 64-wide V rows
// Q staging region (reused by K/V after fragment extraction)
#define AQ_H 0
#define AQ_L (128*QS*2)           // 22528
#define AK_H 0
#define AK_L 11264
#define AV_H 22528
#define AV_L (22528 + 9216)       // 31744
#define ATTN_SMEM (2*128*QS*2)    // 45056 B

__global__ __launch_bounds__(256) void attn_mma_kernel(
    const __nv_bfloat16* __restrict__ Qh, const __nv_bfloat16* __restrict__ Ql,
    const __nv_bfloat16* __restrict__ Kh, const __nv_bfloat16* __restrict__ Kl,
    const __nv_bfloat16* __restrict__ Vh, const __nv_bfloat16* __restrict__ Vl,
    float* __restrict__ out)
{
    extern __shared__ char smem[];
    uint32_t sb = smem_u32(smem);
    const int t    = threadIdx.x;
    const int lane = t & 31;
    const int w    = t >> 5;          // 0..7, warp owns q rows w*16..w*16+15
    const int q0   = blockIdx.x * BQ;
    const int bh   = blockIdx.y;

    const __nv_bfloat16* Qgh = Qh + (size_t)bh * NN * DA + (size_t)q0 * DA;
    const __nv_bfloat16* Qgl = Ql + (size_t)bh * NN * DA + (size_t)q0 * DA;
    const __nv_bfloat16* Kgh = Kh + (size_t)bh * NN * DA;
    const __nv_bfloat16* Kgl = Kl + (size_t)bh * NN * DA;
    const __nv_bfloat16* Vgh = Vh + (size_t)bh * NN * HD;
    const __nv_bfloat16* Vgl = Vl + (size_t)bh * NN * HD;

    // ---- stage Q tile (128 x 80 bf16, hi+lo) ----
#pragma unroll
    for (int i = 0; i < 5; i++) {
        int idx = t + i * 256;          // 0..1279
        int row = idx / 10;
        int c8  = (idx % 10) * 8;
        uint32_t soff = (uint32_t)(row * QS + c8) * 2u;
        *(uint4*)(smem + AQ_H + soff) = *(const uint4*)(Qgh + (size_t)row * DA + c8);
        *(uint4*)(smem + AQ_L + soff) = *(const uint4*)(Qgl + (size_t)row * DA + c8);
    }
    __syncthreads();

    const int a_r  = (lane & 7) + ((lane & 8) ? 8 : 0);
    const int a_c8 = (lane & 16) ? 8 : 0;
    const int b_r  = lane & 7;
    const int b_c8 = (lane & 8) ? 8 : 0;

    uint32_t Qfh[5][4], Qfl[5][4];
#pragma unroll
    for (int s = 0; s < 5; s++) {
        uint32_t ad = sb + (uint32_t)(((w*16 + a_r) * QS + s*16 + a_c8) * 2);
        ldsm_x4(ad + AQ_H, Qfh[s]);
        ldsm_x4(ad + AQ_L, Qfl[s]);
    }

    float mrow[2] = {-1e30f, -1e30f};
    float lrow[2] = {0.f, 0.f};
    float Od[8][4];
#pragma unroll
    for (int db = 0; db < 8; db++)
#pragma unroll
        for (int i = 0; i < 4; i++) Od[db][i] = 0.f;

#pragma unroll 1
    for (int k0 = 0; k0 < NN; k0 += BK) {
        __syncthreads();   // previous iter (and Q frag extraction) done before overwrite
        // ---- copy K tile (64x80, hi+lo): 640 uint4 per array ----
#pragma unroll
        for (int i = 0; i < 3; i++) {
            int idx = t + i * 256;
            if (idx < 640) {
                int row = idx / 10;
                int c8  = (idx % 10) * 8;
                uint32_t soff = (uint32_t)(row * QS + c8) * 2u;
                const size_t g = (size_t)(k0 + row) * DA + c8;
                *(uint4*)(smem + AK_H + soff) = *(const uint4*)(Kgh + g);
                *(uint4*)(smem + AK_L + soff) = *(const uint4*)(Kgl + g);
            }
        }
        // ---- copy V tile (64x64, hi+lo): 512 uint4 per array ----
#pragma unroll
        for (int i = 0; i < 2; i++) {
            int idx = t + i * 256;
            int row = idx >> 3;
            int c8  = (idx & 7) * 8;
            uint32_t soff = (uint32_t)(row * VS + c8) * 2u;
            const size_t g = (size_t)(k0 + row) * HD + c8;
            *(uint4*)(smem + AV_H + soff) = *(const uint4*)(Vgh + g);
            *(uint4*)(smem + AV_L + soff) = *(const uint4*)(Vgl + g);
        }
        __syncthreads();

        // ---- S = Q . K^T  (bf16x3) ----
        float Cs[8][4];
#pragma unroll
        for (int nb = 0; nb < 8; nb++)
#pragma unroll
            for (int i = 0; i < 4; i++) Cs[nb][i] = 0.f;

#pragma unroll
        for (int s = 0; s < 5; s++) {
#pragma unroll
            for (int nb = 0; nb < 8; nb++) {
                uint32_t kd = sb + (uint32_t)(((nb*8 + b_r) * QS + s*16 + b_c8) * 2);
                uint32_t bh2[2], bl2[2];
                ldsm_x2(kd + AK_H, bh2);
                ldsm_x2(kd + AK_L, bl2);
                mma16816(Cs[nb], Qfh[s], bh2);
                mma16816(Cs[nb], Qfh[s], bl2);
                mma16816(Cs[nb], Qfl[s], bh2);
            }
        }

        // ---- online softmax ----
        float mx0 = -1e30f, mx1 = -1e30f;
#pragma unroll
        for (int nb = 0; nb < 8; nb++) {
            mx0 = fmaxf(mx0, fmaxf(Cs[nb][0], Cs[nb][1]));
            mx1 = fmaxf(mx1, fmaxf(Cs[nb][2], Cs[nb][3]));
        }
        mx0 = fmaxf(mx0, __shfl_xor_sync(0xffffffffu, mx0, 1));
        mx0 = fmaxf(mx0, __shfl_xor_sync(0xffffffffu, mx0, 2));
        mx1 = fmaxf(mx1, __shfl_xor_sync(0xffffffffu, mx1, 1));
        mx1 = fmaxf(mx1, __shfl_xor_sync(0xffffffffu, mx1, 2));
        float mn0 = fmaxf(mrow[0], mx0);
        float mn1 = fmaxf(mrow[1], mx1);
        float f0  = __expf(mrow[0] - mn0);
        float f1  = __expf(mrow[1] - mn1);
        mrow[0] = mn0; mrow[1] = mn1;

        float s0 = 0.f, s1 = 0.f;
        uint32_t Ph[4][4], Pl[4][4];
#pragma unroll
        for (int ks = 0; ks < 4; ks++) {
#pragma unroll
            for (int hf = 0; hf < 2; hf++) {
                int nb = 2*ks + hf;
                float p0 = __expf(Cs[nb][0] - mn0);
                float p1 = __expf(Cs[nb][1] - mn0);
                float p2 = __expf(Cs[nb][2] - mn1);
                float p3 = __expf(Cs[nb][3] - mn1);
                s0 += p0 + p1;
                s1 += p2 + p3;
                __nv_bfloat162 h01 = __floats2bfloat162_rn(p0, p1);
                __nv_bfloat162 h23 = __floats2bfloat162_rn(p2, p3);
                __nv_bfloat162 l01 = __floats2bfloat162_rn(p0 - __low2float(h01), p1 - __high2float(h01));
                __nv_bfloat162 l23 = __floats2bfloat162_rn(p2 - __low2float(h23), p3 - __high2float(h23));
                Ph[ks][hf*2+0] = b2u(h01);
                Ph[ks][hf*2+1] = b2u(h23);
                Pl[ks][hf*2+0] = b2u(l01);
                Pl[ks][hf*2+1] = b2u(l23);
            }
        }
        s0 += __shfl_xor_sync(0xffffffffu, s0, 1);
        s0 += __shfl_xor_sync(0xffffffffu, s0, 2);
        s1 += __shfl_xor_sync(0xffffffffu, s1, 1);
        s1 += __shfl_xor_sync(0xffffffffu, s1, 2);
        lrow[0] = lrow[0] * f0 + s0;
        lrow[1] = lrow[1] * f1 + s1;

#pragma unroll
        for (int db = 0; db < 8; db++) {
            Od[db][0] *= f0; Od[db][1] *= f0;
            Od[db][2] *= f1; Od[db][3] *= f1;
        }

        // ---- O += P . V  (bf16x3; V via ldmatrix.trans) ----
#pragma unroll
        for (int ks = 0; ks < 4; ks++) {
#pragma unroll
            for (int db = 0; db < 8; db++) {
                uint32_t vaddr = sb + (uint32_t)(((ks*16 + b_r + ((lane & 8) ? 8 : 0)) * VS + db*8) * 2);
                uint32_t vh2[2], vl2[2];
                ldsm_x2t(vaddr + AV_H, vh2);
                ldsm_x2t(vaddr + AV_L, vl2);
                mma16816(Od[db], Ph[ks], vh2);
                mma16816(Od[db], Ph[ks], vl2);
                mma16816(Od[db], Pl[ks], vh2);
            }
        }
    }

    // ---- epilogue ----
    float i0 = 1.0f / lrow[0];
    float i1 = 1.0f / lrow[1];
    int b = bh >> 3, h = bh & 7;
    int r0l = w*16 + (lane >> 2);
    int c0l = (lane & 3) * 2;
#pragma unroll
    for (int db = 0; db < 8; db++) {
        int gc = h*64 + db*8 + c0l;
        float2 v0; v0.x = Od[db][0] * i0; v0.y = Od[db][1] * i0;
        float2 v1; v1.x = Od[db][2] * i1; v1.y = Od[db][3] * i1;
        *(float2*)&out[((size_t)(b*NN + q0 + r0l)) * DD + gc] = v0;
        *(float2*)&out[((size_t)(b*NN + q0 + r0l + 8)) * DD + gc] = v1;
    }
}

// ---------------- launch ----------------
extern "C" void kernel_launch(void* const* d_in, const int* in_sizes, int n_in,
                              void* d_out, int out_size)
{
    const float* x   = (const float*)d_in[0];
    const float* pc  = (const float*)d_in[1];
    const float* Wq  = (const float*)d_in[2];
    const float* bq  = (const float*)d_in[3];
    const float* Wk  = (const float*)d_in[4];
    const float* bk  = (const float*)d_in[5];
    const float* Wv  = (const float*)d_in[6];
    const float* bv  = (const float*)d_in[7];
    const float* Wo  = (const float*)d_in[8];
    const float* bo  = (const float*)d_in[9];
    const float* pb  = (const float*)d_in[10];
    float* out = (float*)d_out;

    __nv_bfloat16 *qh, *ql, *kh, *kl, *vh, *vl;
    float* att;
    cudaGetSymbolAddress((void**)&qh, g_Qh);
    cudaGetSymbolAddress((void**)&ql, g_Ql);
    cudaGetSymbolAddress((void**)&kh, g_Kh);
    cudaGetSymbolAddress((void**)&kl, g_Kl);
    cudaGetSymbolAddress((void**)&vh, g_Vh);
    cudaGetSymbolAddress((void**)&vl, g_Vl);
    cudaGetSymbolAddress((void**)&att, g_att);

    cudaFuncSetAttribute(attn_mma_kernel, cudaFuncAttributeMaxDynamicSharedMemorySize, ATTN_SMEM);
    cudaFuncSetAttribute(qkv_mma_kernel,  cudaFuncAttributeMaxDynamicSharedMemorySize, GEMM_SMEM);
    cudaFuncSetAttribute(gemm_mma_kernel, cudaFuncAttributeMaxDynamicSharedMemorySize, GEMM_SMEM);

    dim3 qgrid(4, 32, 3);
    qkv_mma_kernel<<<qgrid, 256, GEMM_SMEM>>>(x, Wq, bq, Wk, bk, Wv, bv);

    phase_fill_kernel<<<(BB*NN*HH + 255)/256, 256>>>(pc, pb);

    dim3 agrid(NN/BQ, BB*HH);   // (16, 16)
    attn_mma_kernel<<<agrid, 256, ATTN_SMEM>>>(qh, ql, kh, kl, vh, vl, att);

    dim3 ggrid(4, 32);
    gemm_mma_kernel<<<ggrid, 256, GEMM_SMEM>>>(att, Wo, bo, out);
}

// round 5
// speedup vs baseline: 3.5614x; 1.0548x over previous
#include <cuda_runtime.h>
#include <cuda_bf16.h>
#include <cstdint>
#include <math.h>

// Problem constants
#define BB 2
#define NN 2048
#define DD 512
#define HH 8
#define FF 8
#define HD 64
#define DA 80   // augmented head dim: 64 (Q/K) + 8 (cos) + 8 (sin)
#define BQ 128  // q rows per CTA (attention)
#define BK 64   // keys per tile

#define MTOT (BB*NN)          // 4096
#define WELEM (DD*DD)         // 262144

// ---------------- scratch (device globals; no allocation) ----------------
__device__ __nv_bfloat16 g_xh[MTOT*DD], g_xl[MTOT*DD];
__device__ __nv_bfloat16 g_Wh[4*WELEM], g_Wl[4*WELEM];     // Wq,Wk,Wv,Wo
__device__ __nv_bfloat16 g_Qh[BB*HH*NN*DA], g_Ql[BB*HH*NN*DA];
__device__ __nv_bfloat16 g_Kh[BB*HH*NN*DA], g_Kl[BB*HH*NN*DA];
__device__ __nv_bfloat16 g_Vh[BB*HH*NN*HD], g_Vl[BB*HH*NN*HD];
__device__ __nv_bfloat16 g_atth[MTOT*DD], g_attl[MTOT*DD];

// ======================= helpers =======================
__device__ __forceinline__ uint32_t smem_u32(const void* p){
    uint32_t a;
    asm("{ .reg .u64 t; cvta.to.shared.u64 t, %1; cvt.u32.u64 %0, t; }" : "=r"(a) : "l"(p));
    return a;
}
__device__ __forceinline__ void ldsm_x4(uint32_t addr, uint32_t r[4]){
    asm volatile("ldmatrix.sync.aligned.m8n8.x4.shared.b16 {%0,%1,%2,%3}, [%4];"
        : "=r"(r[0]), "=r"(r[1]), "=r"(r[2]), "=r"(r[3]) : "r"(addr));
}
__device__ __forceinline__ void ldsm_x2(uint32_t addr, uint32_t r[2]){
    asm volatile("ldmatrix.sync.aligned.m8n8.x2.shared.b16 {%0,%1}, [%2];"
        : "=r"(r[0]), "=r"(r[1]) : "r"(addr));
}
__device__ __forceinline__ void ldsm_x2t(uint32_t addr, uint32_t r[2]){
    asm volatile("ldmatrix.sync.aligned.m8n8.x2.trans.shared.b16 {%0,%1}, [%2];"
        : "=r"(r[0]), "=r"(r[1]) : "r"(addr));
}
__device__ __forceinline__ void mma16816(float c[4], const uint32_t a[4], const uint32_t b[2]){
    asm volatile("mma.sync.aligned.m16n8k16.row.col.f32.bf16.bf16.f32 "
        "{%0,%1,%2,%3}, {%4,%5,%6,%7}, {%8,%9}, {%0,%1,%2,%3};"
        : "+f"(c[0]), "+f"(c[1]), "+f"(c[2]), "+f"(c[3])
        : "r"(a[0]), "r"(a[1]), "r"(a[2]), "r"(a[3]), "r"(b[0]), "r"(b[1]));
}
__device__ __forceinline__ uint32_t b2u(__nv_bfloat162 v){ return *reinterpret_cast<uint32_t*>(&v); }
__device__ __forceinline__ void cp16(uint32_t dst, const void* src){
    asm volatile("cp.async.cg.shared.global [%0], [%1], 16;" :: "r"(dst), "l"(src));
}
#define CP_COMMIT asm volatile("cp.async.commit_group;" ::: "memory")
#define CP_WAIT1  asm volatile("cp.async.wait_group 1;" ::: "memory")
#define CP_WAIT0  asm volatile("cp.async.wait_group 0;" ::: "memory")

__device__ __forceinline__ void pack2(float vx, float vy, uint32_t& hi, uint32_t& lo){
    __nv_bfloat162 h = __floats2bfloat162_rn(vx, vy);
    __nv_bfloat162 l = __floats2bfloat162_rn(vx - __low2float(h), vy - __high2float(h));
    hi = b2u(h); lo = b2u(l);
}

// ================= fp32 -> bf16 hi/lo conversion =================
#define XC ((MTOT*DD)/4)        // 524288 float4s
#define WC (WELEM/4)            // 65536 float4s
__global__ void convert_kernel(const float* __restrict__ x,
                               const float* __restrict__ Wq, const float* __restrict__ Wk,
                               const float* __restrict__ Wv, const float* __restrict__ Wo)
{
    int i = blockIdx.x * blockDim.x + threadIdx.x;
    const float* src;
    __nv_bfloat16 *dh, *dl;
    int off;
    if (i < XC) { src = x; dh = g_xh; dl = g_xl; off = i; }
    else {
        int j = i - XC;
        int w = j >> 16;          // / WC
        off   = j & (WC - 1);
        src = (w == 0) ? Wq : (w == 1) ? Wk : (w == 2) ? Wv : Wo;
        dh = g_Wh + (size_t)w * WELEM;
        dl = g_Wl + (size_t)w * WELEM;
    }
    float4 v = ((const float4*)src)[off];
    uint2 uh, ul;
    pack2(v.x, v.y, uh.x, ul.x);
    pack2(v.z, v.w, uh.y, ul.y);
    *(uint2*)&dh[4*(size_t)off] = uh;
    *(uint2*)&dl[4*(size_t)off] = ul;
}

// ================= GEMM staging layout (per stage 40960 B, 2 stages) =================
#define AS 40
#define GB_AH 0
#define GB_AL 10240
#define GB_WH 20480
#define GB_WL 30720
#define STG   40960
#define GEMM_SMEM (2*STG)   // 81920

// ---- stage loader: 8 cp.async per thread ----
__device__ __forceinline__ void gemm_stage(
    uint32_t sb, int stage, int t, int m0, int o0, int k0,
    const __nv_bfloat16* Ahg, const __nv_bfloat16* Alg,
    const __nv_bfloat16* Whg, const __nv_bfloat16* Wlg)
{
    uint32_t sa = sb + (uint32_t)stage * STG;
#pragma unroll
    for (int i = 0; i < 2; i++) {
        int c   = t + i * 256;            // 0..511
        int row = c >> 2;
        int ce  = (c & 3) << 3;
        uint32_t so = (uint32_t)(row * AS + ce) * 2u;
        cp16(sa + GB_AH + so, Ahg + (size_t)(m0 + row) * DD + k0 + ce);
        cp16(sa + GB_AL + so, Alg + (size_t)(m0 + row) * DD + k0 + ce);
        cp16(sa + GB_WH + so, Whg + (size_t)(o0 + row) * DD + k0 + ce);
        cp16(sa + GB_WL + so, Wlg + (size_t)(o0 + row) * DD + k0 + ce);
    }
    CP_COMMIT;
}

// ---- shared mainloop compute on one stage ----
__device__ __forceinline__ void gemm_compute(
    uint32_t sb, int stage, float Cs[4][4][4],
    int wm, int wn, int a_r, int a_c8, int b_r, int b_c8)
{
    uint32_t sa = sb + (uint32_t)stage * STG;
#pragma unroll
    for (int ks = 0; ks < 2; ks++) {
        uint32_t Ah[4][4], Al[4][4], Wh[4][2], Wl[4][2];
#pragma unroll
        for (int mb = 0; mb < 4; mb++) {
            uint32_t ad = sa + (uint32_t)(((wm*64 + mb*16 + a_r) * AS + ks*16 + a_c8) * 2);
            ldsm_x4(ad + GB_AH, Ah[mb]);
            ldsm_x4(ad + GB_AL, Al[mb]);
        }
#pragma unroll
        for (int nb = 0; nb < 4; nb++) {
            uint32_t wd = sa + (uint32_t)(((wn*32 + nb*8 + b_r) * AS + ks*16 + b_c8) * 2);
            ldsm_x2(wd + GB_WH, Wh[nb]);
            ldsm_x2(wd + GB_WL, Wl[nb]);
        }
#pragma unroll
        for (int mb = 0; mb < 4; mb++)
#pragma unroll
            for (int nb = 0; nb < 4; nb++) {
                mma16816(Cs[mb][nb], Ah[mb], Wh[nb]);
                mma16816(Cs[mb][nb], Ah[mb], Wl[nb]);
                mma16816(Cs[mb][nb], Al[mb], Wh[nb]);
            }
    }
}

// ================= fused QKV projection (bf16 in, bf16 hi/lo head layouts out) =================
__global__ __launch_bounds__(256) void qkv_mma_kernel(
    const float* __restrict__ bq, const float* __restrict__ bk, const float* __restrict__ bv)
{
    extern __shared__ char smem[];
    uint32_t sb = smem_u32(smem);
    const int t    = threadIdx.x;
    const int lane = t & 31;
    const int w    = t >> 5;
    const int wm   = w >> 2;
    const int wn   = w & 3;
    const int m0   = blockIdx.y * 128;
    const int o0   = blockIdx.x * 128;
    const int z    = blockIdx.z;

    const __nv_bfloat16* Whg = g_Wh + (size_t)z * WELEM;
    const __nv_bfloat16* Wlg = g_Wl + (size_t)z * WELEM;
    const float* bias = (z == 0) ? bq : (z == 1) ? bk : bv;
    __nv_bfloat16* dh = (z == 0) ? g_Qh : (z == 1) ? g_Kh : g_Vh;
    __nv_bfloat16* dl = (z == 0) ? g_Ql : (z == 1) ? g_Kl : g_Vl;
    const float scale = (z == 0) ? 0.125f : 1.0f;
    const int   ld    = (z == 2) ? HD : DA;

    float Cs[4][4][4];
#pragma unroll
    for (int mb = 0; mb < 4; mb++)
#pragma unroll
        for (int nb = 0; nb < 4; nb++)
#pragma unroll
            for (int i = 0; i < 4; i++) Cs[mb][nb][i] = 0.f;

    const int a_r  = (lane & 7) + ((lane & 8) ? 8 : 0);
    const int a_c8 = (lane & 16) ? 8 : 0;
    const int b_r  = lane & 7;
    const int b_c8 = (lane & 8) ? 8 : 0;

    gemm_stage(sb, 0, t, m0, o0, 0, g_xh, g_xl, Whg, Wlg);
    for (int kk = 0; kk < 16; kk++) {
        if (kk + 1 < 16) {
            gemm_stage(sb, (kk+1)&1, t, m0, o0, (kk+1)*32, g_xh, g_xl, Whg, Wlg);
            CP_WAIT1;
        } else {
            CP_WAIT0;
        }
        __syncthreads();
        gemm_compute(sb, kk & 1, Cs, wm, wn, a_r, a_c8, b_r, b_c8);
        __syncthreads();
    }

    const int r0l = lane >> 2;
    const int c0l = (lane & 3) * 2;
#pragma unroll
    for (int mb = 0; mb < 4; mb++) {
#pragma unroll
        for (int nb = 0; nb < 4; nb++) {
            int gc = o0 + wn*32 + nb*8 + c0l;
            float2 bbv = *(const float2*)&bias[gc];
            int h  = gc >> 6;
            int hd = gc & 63;
#pragma unroll
            for (int half = 0; half < 2; half++) {
                int gr = m0 + wm*64 + mb*16 + r0l + half*8;
                float vx = (Cs[mb][nb][half*2+0] + bbv.x) * scale;
                float vy = (Cs[mb][nb][half*2+1] + bbv.y) * scale;
                uint32_t hi, lo;
                pack2(vx, vy, hi, lo);
                int b  = gr >> 11;
                int n  = gr & 2047;
                size_t off = ((size_t)((b*HH + h) * NN + n)) * ld + hd;
                *(uint32_t*)&dh[off] = hi;
                *(uint32_t*)&dl[off] = lo;
            }
        }
    }
}

// ================= output projection (bf16 in, fp32 out) =================
__global__ __launch_bounds__(256) void oproj_mma_kernel(
    const float* __restrict__ bias, float* __restrict__ out)
{
    extern __shared__ char smem[];
    uint32_t sb = smem_u32(smem);
    const int t    = threadIdx.x;
    const int lane = t & 31;
    const int w    = t >> 5;
    const int wm   = w >> 2;
    const int wn   = w & 3;
    const int m0   = blockIdx.y * 128;
    const int o0   = blockIdx.x * 128;

    const __nv_bfloat16* Whg = g_Wh + (size_t)3 * WELEM;
    const __nv_bfloat16* Wlg = g_Wl + (size_t)3 * WELEM;

    float Cs[4][4][4];
#pragma unroll
    for (int mb = 0; mb < 4; mb++)
#pragma unroll
        for (int nb = 0; nb < 4; nb++)
#pragma unroll
            for (int i = 0; i < 4; i++) Cs[mb][nb][i] = 0.f;

    const int a_r  = (lane & 7) + ((lane & 8) ? 8 : 0);
    const int a_c8 = (lane & 16) ? 8 : 0;
    const int b_r  = lane & 7;
    const int b_c8 = (lane & 8) ? 8 : 0;

    gemm_stage(sb, 0, t, m0, o0, 0, g_atth, g_attl, Whg, Wlg);
    for (int kk = 0; kk < 16; kk++) {
        if (kk + 1 < 16) {
            gemm_stage(sb, (kk+1)&1, t, m0, o0, (kk+1)*32, g_atth, g_attl, Whg, Wlg);
            CP_WAIT1;
        } else {
            CP_WAIT0;
        }
        __syncthreads();
        gemm_compute(sb, kk & 1, Cs, wm, wn, a_r, a_c8, b_r, b_c8);
        __syncthreads();
    }

    const int r0l = lane >> 2;
    const int c0l = (lane & 3) * 2;
#pragma unroll
    for (int mb = 0; mb < 4; mb++) {
#pragma unroll
        for (int nb = 0; nb < 4; nb++) {
            int gc = o0 + wn*32 + nb*8 + c0l;
            float2 bbv = *(const float2*)&bias[gc];
#pragma unroll
            for (int half = 0; half < 2; half++) {
                int gr = m0 + wm*64 + mb*16 + r0l + half*8;
                float2 v;
                v.x = Cs[mb][nb][half*2+0] + bbv.x;
                v.y = Cs[mb][nb][half*2+1] + bbv.y;
                *(float2*)&out[(size_t)gr * DD + gc] = v;
            }
        }
    }
}

// ---------------- phase augmentation fill ----------------
__device__ __forceinline__ void pack8(const float* v, uint4& hi, uint4& lo){
    uint32_t h[4], l[4];
#pragma unroll
    for (int i = 0; i < 4; i++) pack2(v[2*i], v[2*i+1], h[i], l[i]);
    hi.x = h[0]; hi.y = h[1]; hi.z = h[2]; hi.w = h[3];
    lo.x = l[0]; lo.y = l[1]; lo.z = l[2]; lo.w = l[3];
}

__global__ void phase_fill_kernel(const float* __restrict__ pc,
                                  const float* __restrict__ pb)
{
    int tid = blockIdx.x * blockDim.x + threadIdx.x;
    if (tid >= BB * NN * HH) return;
    int h  = tid >> 12;
    int bn = tid & 4095;

    float c[FF], s[FF], wc[FF], ws[FF];
#pragma unroll
    for (int f = 0; f < FF; f++)
        __sincosf(pc[(size_t)bn * FF + f], &s[f], &c[f]);
#pragma unroll
    for (int f = 0; f < FF; f++) {
        float wv = pb[h*FF + f];
        wc[f] = wv * c[f];
        ws[f] = wv * s[f];
    }

    int b = bn >> 11, n = bn & 2047;
    size_t base = ((size_t)((b*HH + h) * NN + n)) * DA + 64;

    uint4 hi, lo;
    pack8(c,  hi, lo); *(uint4*)&g_Kh[base]   = hi; *(uint4*)&g_Kl[base]   = lo;
    pack8(s,  hi, lo); *(uint4*)&g_Kh[base+8] = hi; *(uint4*)&g_Kl[base+8] = lo;
    pack8(wc, hi, lo); *(uint4*)&g_Qh[base]   = hi; *(uint4*)&g_Ql[base]   = lo;
    pack8(ws, hi, lo); *(uint4*)&g_Qh[base+8] = hi; *(uint4*)&g_Ql[base+8] = lo;
}

// =============== bf16x3 warp-MMA flash attention, cp.async pipelined ===============
#define QS 88
#define VS 72
#define AKH 0
#define AKL 11264
#define AVH 22528
#define AVL 31744
#define ASTG 40960
#define ATTN_SMEM (2*ASTG)   // 81920

__global__ __launch_bounds__(256) void attn_mma_kernel()
{
    extern __shared__ char smem[];
    uint32_t sb = smem_u32(smem);
    const int t    = threadIdx.x;
    const int lane = t & 31;
    const int w    = t >> 5;
    const int q0   = blockIdx.x * BQ;
    const int bh   = blockIdx.y;

    const __nv_bfloat16* Qgh = g_Qh + (size_t)bh * NN * DA + (size_t)q0 * DA;
    const __nv_bfloat16* Qgl = g_Ql + (size_t)bh * NN * DA + (size_t)q0 * DA;
    const __nv_bfloat16* Kgh = g_Kh + (size_t)bh * NN * DA;
    const __nv_bfloat16* Kgl = g_Kl + (size_t)bh * NN * DA;
    const __nv_bfloat16* Vgh = g_Vh + (size_t)bh * NN * HD;
    const __nv_bfloat16* Vgl = g_Vl + (size_t)bh * NN * HD;

    // ---- stage Q tile (128 x 80 hi+lo) into smem base, extract fragments ----
#pragma unroll
    for (int i = 0; i < 5; i++) {
        int idx = t + i * 256;          // 0..1279
        int row = idx / 10;
        int c8  = (idx % 10) * 8;
        uint32_t soff = (uint32_t)(row * QS + c8) * 2u;
        *(uint4*)(smem + soff)         = *(const uint4*)(Qgh + (size_t)row * DA + c8);
        *(uint4*)(smem + 45056 + soff) = *(const uint4*)(Qgl + (size_t)row * DA + c8);
    }
    __syncthreads();

    const int a_r  = (lane & 7) + ((lane & 8) ? 8 : 0);
    const int a_c8 = (lane & 16) ? 8 : 0;
    const int b_r  = lane & 7;
    const int b_c8 = (lane & 8) ? 8 : 0;

    uint32_t Qfh[5][4], Qfl[5][4];
#pragma unroll
    for (int s = 0; s < 5; s++) {
        uint32_t ad = sb + (uint32_t)(((w*16 + a_r) * QS + s*16 + a_c8) * 2);
        ldsm_x4(ad, Qfh[s]);
        ldsm_x4(ad + 45056, Qfl[s]);
    }
    __syncthreads();

    auto prefetch = [&](int stage, int k0){
        uint32_t sa = sb + (uint32_t)stage * ASTG;
#pragma unroll
        for (int i = 0; i < 3; i++) {
            int idx = t + i * 256;
            if (idx < 640) {
                int row = idx / 10;
                int c8  = (idx % 10) * 8;
                uint32_t so = (uint32_t)(row * QS + c8) * 2u;
                const size_t g = (size_t)(k0 + row) * DA + c8;
                cp16(sa + AKH + so, Kgh + g);
                cp16(sa + AKL + so, Kgl + g);
            }
        }
#pragma unroll
        for (int i = 0; i < 2; i++) {
            int idx = t + i * 256;
            int row = idx >> 3;
            int c8  = (idx & 7) * 8;
            uint32_t so = (uint32_t)(row * VS + c8) * 2u;
            const size_t g = (size_t)(k0 + row) * HD + c8;
            cp16(sa + AVH + so, Vgh + g);
            cp16(sa + AVL + so, Vgl + g);
        }
        CP_COMMIT;
    };

    float mrow[2] = {-1e30f, -1e30f};
    float lrow[2] = {0.f, 0.f};
    float Od[8][4];
#pragma unroll
    for (int db = 0; db < 8; db++)
#pragma unroll
        for (int i = 0; i < 4; i++) Od[db][i] = 0.f;

    prefetch(0, 0);
#pragma unroll 1
    for (int kt = 0; kt < NN/BK; kt++) {
        if (kt + 1 < NN/BK) {
            prefetch((kt+1) & 1, (kt+1) * BK);
            CP_WAIT1;
        } else {
            CP_WAIT0;
        }
        __syncthreads();
        uint32_t sa = sb + (uint32_t)(kt & 1) * ASTG;

        // ---- S = Q . K^T  (bf16x3) ----
        float Cs[8][4];
#pragma unroll
        for (int nb = 0; nb < 8; nb++)
#pragma unroll
            for (int i = 0; i < 4; i++) Cs[nb][i] = 0.f;

#pragma unroll
        for (int s = 0; s < 5; s++) {
#pragma unroll
            for (int nb = 0; nb < 8; nb++) {
                uint32_t kd = sa + (uint32_t)(((nb*8 + b_r) * QS + s*16 + b_c8) * 2);
                uint32_t bh2[2], bl2[2];
                ldsm_x2(kd + AKH, bh2);
                ldsm_x2(kd + AKL, bl2);
                mma16816(Cs[nb], Qfh[s], bh2);
                mma16816(Cs[nb], Qfh[s], bl2);
                mma16816(Cs[nb], Qfl[s], bh2);
            }
        }

        // ---- online softmax ----
        float mx0 = -1e30f, mx1 = -1e30f;
#pragma unroll
        for (int nb = 0; nb < 8; nb++) {
            mx0 = fmaxf(mx0, fmaxf(Cs[nb][0], Cs[nb][1]));
            mx1 = fmaxf(mx1, fmaxf(Cs[nb][2], Cs[nb][3]));
        }
        mx0 = fmaxf(mx0, __shfl_xor_sync(0xffffffffu, mx0, 1));
        mx0 = fmaxf(mx0, __shfl_xor_sync(0xffffffffu, mx0, 2));
        mx1 = fmaxf(mx1, __shfl_xor_sync(0xffffffffu, mx1, 1));
        mx1 = fmaxf(mx1, __shfl_xor_sync(0xffffffffu, mx1, 2));
        float mn0 = fmaxf(mrow[0], mx0);
        float mn1 = fmaxf(mrow[1], mx1);
        float f0  = __expf(mrow[0] - mn0);
        float f1  = __expf(mrow[1] - mn1);
        mrow[0] = mn0; mrow[1] = mn1;

        float s0 = 0.f, s1 = 0.f;
        uint32_t Ph[4][4], Pl[4][4];
#pragma unroll
        for (int ks = 0; ks < 4; ks++) {
#pragma unroll
            for (int hf = 0; hf < 2; hf++) {
                int nb = 2*ks + hf;
                float p0 = __expf(Cs[nb][0] - mn0);
                float p1 = __expf(Cs[nb][1] - mn0);
                float p2 = __expf(Cs[nb][2] - mn1);
                float p3 = __expf(Cs[nb][3] - mn1);
                s0 += p0 + p1;
                s1 += p2 + p3;
                pack2(p0, p1, Ph[ks][hf*2+0], Pl[ks][hf*2+0]);
                pack2(p2, p3, Ph[ks][hf*2+1], Pl[ks][hf*2+1]);
            }
        }
        s0 += __shfl_xor_sync(0xffffffffu, s0, 1);
        s0 += __shfl_xor_sync(0xffffffffu, s0, 2);
        s1 += __shfl_xor_sync(0xffffffffu, s1, 1);
        s1 += __shfl_xor_sync(0xffffffffu, s1, 2);
        lrow[0] = lrow[0] * f0 + s0;
        lrow[1] = lrow[1] * f1 + s1;

#pragma unroll
        for (int db = 0; db < 8; db++) {
            Od[db][0] *= f0; Od[db][1] *= f0;
            Od[db][2] *= f1; Od[db][3] *= f1;
        }

        // ---- O += P . V  (bf16x3; V via ldmatrix.trans) ----
#pragma unroll
        for (int ks = 0; ks < 4; ks++) {
#pragma unroll
            for (int db = 0; db < 8; db++) {
                uint32_t vaddr = sa + (uint32_t)(((ks*16 + b_r + ((lane & 8) ? 8 : 0)) * VS + db*8) * 2);
                uint32_t vh2[2], vl2[2];
                ldsm_x2t(vaddr + AVH, vh2);
                ldsm_x2t(vaddr + AVL, vl2);
                mma16816(Od[db], Ph[ks], vh2);
                mma16816(Od[db], Ph[ks], vl2);
                mma16816(Od[db], Pl[ks], vh2);
            }
        }
        __syncthreads();
    }

    // ---- epilogue: write att as bf16 hi/lo ----
    float i0 = 1.0f / lrow[0];
    float i1 = 1.0f / lrow[1];
    int b = bh >> 3, h = bh & 7;
    int r0l = w*16 + (lane >> 2);
    int c0l = (lane & 3) * 2;
#pragma unroll
    for (int db = 0; db < 8; db++) {
        int gc = h*64 + db*8 + c0l;
        uint32_t hi0, lo0, hi1, lo1;
        pack2(Od[db][0] * i0, Od[db][1] * i0, hi0, lo0);
        pack2(Od[db][2] * i1, Od[db][3] * i1, hi1, lo1);
        size_t o0r = ((size_t)(b*NN + q0 + r0l)) * DD + gc;
        size_t o1r = ((size_t)(b*NN + q0 + r0l + 8)) * DD + gc;
        *(uint32_t*)&g_atth[o0r] = hi0;
        *(uint32_t*)&g_attl[o0r] = lo0;
        *(uint32_t*)&g_atth[o1r] = hi1;
        *(uint32_t*)&g_attl[o1r] = lo1;
    }
}

// ---------------- launch ----------------
extern "C" void kernel_launch(void* const* d_in, const int* in_sizes, int n_in,
                              void* d_out, int out_size)
{
    const float* x   = (const float*)d_in[0];
    const float* pc  = (const float*)d_in[1];
    const float* Wq  = (const float*)d_in[2];
    const float* bq  = (const float*)d_in[3];
    const float* Wk  = (const float*)d_in[4];
    const float* bk  = (const float*)d_in[5];
    const float* Wv  = (const float*)d_in[6];
    const float* bv  = (const float*)d_in[7];
    const float* Wo  = (const float*)d_in[8];
    const float* bo  = (const float*)d_in[9];
    const float* pb  = (const float*)d_in[10];
    float* out = (float*)d_out;

    cudaFuncSetAttribute(attn_mma_kernel,  cudaFuncAttributeMaxDynamicSharedMemorySize, ATTN_SMEM);
    cudaFuncSetAttribute(qkv_mma_kernel,   cudaFuncAttributeMaxDynamicSharedMemorySize, GEMM_SMEM);
    cudaFuncSetAttribute(oproj_mma_kernel, cudaFuncAttributeMaxDynamicSharedMemorySize, GEMM_SMEM);

    int totc = XC + 4*WC;   // 786432
    convert_kernel<<<(totc + 255)/256, 256>>>(x, Wq, Wk, Wv, Wo);

    dim3 qgrid(4, 32, 3);
    qkv_mma_kernel<<<qgrid, 256, GEMM_SMEM>>>(bq, bk, bv);

    phase_fill_kernel<<<(BB*NN*HH + 255)/256, 256>>>(pc, pb);

    dim3 agrid(NN/BQ, BB*HH);   // (16, 16)
    attn_mma_kernel<<<agrid, 256, ATTN_SMEM>>>();

    dim3 ggrid(4, 32);
    oproj_mma_kernel<<<ggrid, 256, GEMM_SMEM>>>(bo, out);
}

// round 6
// speedup vs baseline: 3.6327x; 1.0200x over previous
#include <cuda_runtime.h>
#include <cuda_bf16.h>
#include <cstdint>
#include <math.h>

// Problem constants
#define BB 2
#define NN 2048
#define DD 512
#define HH 8
#define FF 8
#define HD 64
#define DA 80   // augmented head dim: 64 (Q/K) + 8 (cos) + 8 (sin)
#define BQ 64   // q rows per CTA (attention)
#define BK 64   // keys per tile

#define MTOT (BB*NN)          // 4096
#define WELEM (DD*DD)         // 262144

// ---------------- scratch (device globals; no allocation) ----------------
__device__ __nv_bfloat16 g_xh[MTOT*DD], g_xl[MTOT*DD];
__device__ __nv_bfloat16 g_Wh[4*WELEM], g_Wl[4*WELEM];     // Wq,Wk,Wv,Wo
__device__ __nv_bfloat16 g_Qh[BB*HH*NN*DA], g_Ql[BB*HH*NN*DA];
__device__ __nv_bfloat16 g_Kh[BB*HH*NN*DA], g_Kl[BB*HH*NN*DA];
__device__ __nv_bfloat16 g_Vh[BB*HH*NN*HD], g_Vl[BB*HH*NN*HD];
__device__ __nv_bfloat16 g_atth[MTOT*DD], g_attl[MTOT*DD];

// ======================= helpers =======================
__device__ __forceinline__ uint32_t smem_u32(const void* p){
    uint32_t a;
    asm("{ .reg .u64 t; cvta.to.shared.u64 t, %1; cvt.u32.u64 %0, t; }" : "=r"(a) : "l"(p));
    return a;
}
__device__ __forceinline__ void ldsm_x4(uint32_t addr, uint32_t r[4]){
    asm volatile("ldmatrix.sync.aligned.m8n8.x4.shared.b16 {%0,%1,%2,%3}, [%4];"
        : "=r"(r[0]), "=r"(r[1]), "=r"(r[2]), "=r"(r[3]) : "r"(addr));
}
__device__ __forceinline__ void ldsm_x2(uint32_t addr, uint32_t r[2]){
    asm volatile("ldmatrix.sync.aligned.m8n8.x2.shared.b16 {%0,%1}, [%2];"
        : "=r"(r[0]), "=r"(r[1]) : "r"(addr));
}
__device__ __forceinline__ void ldsm_x2t(uint32_t addr, uint32_t r[2]){
    asm volatile("ldmatrix.sync.aligned.m8n8.x2.trans.shared.b16 {%0,%1}, [%2];"
        : "=r"(r[0]), "=r"(r[1]) : "r"(addr));
}
__device__ __forceinline__ void mma16816(float c[4], const uint32_t a[4], const uint32_t b[2]){
    asm volatile("mma.sync.aligned.m16n8k16.row.col.f32.bf16.bf16.f32 "
        "{%0,%1,%2,%3}, {%4,%5,%6,%7}, {%8,%9}, {%0,%1,%2,%3};"
        : "+f"(c[0]), "+f"(c[1]), "+f"(c[2]), "+f"(c[3])
        : "r"(a[0]), "r"(a[1]), "r"(a[2]), "r"(a[3]), "r"(b[0]), "r"(b[1]));
}
__device__ __forceinline__ uint32_t b2u(__nv_bfloat162 v){ return *reinterpret_cast<uint32_t*>(&v); }
__device__ __forceinline__ void cp16(uint32_t dst, const void* src){
    asm volatile("cp.async.cg.shared.global [%0], [%1], 16;" :: "r"(dst), "l"(src));
}
#define CP_COMMIT asm volatile("cp.async.commit_group;" ::: "memory")
#define CP_WAIT1  asm volatile("cp.async.wait_group 1;" ::: "memory")
#define CP_WAIT0  asm volatile("cp.async.wait_group 0;" ::: "memory")

__device__ __forceinline__ void pack2(float vx, float vy, uint32_t& hi, uint32_t& lo){
    __nv_bfloat162 h = __floats2bfloat162_rn(vx, vy);
    __nv_bfloat162 l = __floats2bfloat162_rn(vx - __low2float(h), vy - __high2float(h));
    hi = b2u(h); lo = b2u(l);
}

// ================= fp32 -> bf16 hi/lo conversion =================
#define XC ((MTOT*DD)/4)        // 524288 float4s
#define WC (WELEM/4)            // 65536 float4s
__global__ void convert_kernel(const float* __restrict__ x,
                               const float* __restrict__ Wq, const float* __restrict__ Wk,
                               const float* __restrict__ Wv, const float* __restrict__ Wo)
{
    int i = blockIdx.x * blockDim.x + threadIdx.x;
    const float* src;
    __nv_bfloat16 *dh, *dl;
    int off;
    if (i < XC) { src = x; dh = g_xh; dl = g_xl; off = i; }
    else {
        int j = i - XC;
        int w = j >> 16;          // / WC
        off   = j & (WC - 1);
        src = (w == 0) ? Wq : (w == 1) ? Wk : (w == 2) ? Wv : Wo;
        dh = g_Wh + (size_t)w * WELEM;
        dl = g_Wl + (size_t)w * WELEM;
    }
    float4 v = ((const float4*)src)[off];
    uint2 uh, ul;
    pack2(v.x, v.y, uh.x, ul.x);
    pack2(v.z, v.w, uh.y, ul.y);
    *(uint2*)&dh[4*(size_t)off] = uh;
    *(uint2*)&dl[4*(size_t)off] = ul;
}

// ================= GEMM staging layout (per stage 40960 B, 2 stages) =================
#define AS 40
#define GB_AH 0
#define GB_AL 10240
#define GB_WH 20480
#define GB_WL 30720
#define STG   40960
#define GEMM_SMEM (2*STG)   // 81920

__device__ __forceinline__ void gemm_stage(
    uint32_t sb, int stage, int t, int m0, int o0, int k0,
    const __nv_bfloat16* Ahg, const __nv_bfloat16* Alg,
    const __nv_bfloat16* Whg, const __nv_bfloat16* Wlg)
{
    uint32_t sa = sb + (uint32_t)stage * STG;
#pragma unroll
    for (int i = 0; i < 2; i++) {
        int c   = t + i * 256;            // 0..511
        int row = c >> 2;
        int ce  = (c & 3) << 3;
        uint32_t so = (uint32_t)(row * AS + ce) * 2u;
        cp16(sa + GB_AH + so, Ahg + (size_t)(m0 + row) * DD + k0 + ce);
        cp16(sa + GB_AL + so, Alg + (size_t)(m0 + row) * DD + k0 + ce);
        cp16(sa + GB_WH + so, Whg + (size_t)(o0 + row) * DD + k0 + ce);
        cp16(sa + GB_WL + so, Wlg + (size_t)(o0 + row) * DD + k0 + ce);
    }
    CP_COMMIT;
}

__device__ __forceinline__ void gemm_compute(
    uint32_t sb, int stage, float Cs[4][4][4],
    int wm, int wn, int a_r, int a_c8, int b_r, int b_c8)
{
    uint32_t sa = sb + (uint32_t)stage * STG;
#pragma unroll
    for (int ks = 0; ks < 2; ks++) {
        uint32_t Ah[4][4], Al[4][4], Wh[4][2], Wl[4][2];
#pragma unroll
        for (int mb = 0; mb < 4; mb++) {
            uint32_t ad = sa + (uint32_t)(((wm*64 + mb*16 + a_r) * AS + ks*16 + a_c8) * 2);
            ldsm_x4(ad + GB_AH, Ah[mb]);
            ldsm_x4(ad + GB_AL, Al[mb]);
        }
#pragma unroll
        for (int nb = 0; nb < 4; nb++) {
            uint32_t wd = sa + (uint32_t)(((wn*32 + nb*8 + b_r) * AS + ks*16 + b_c8) * 2);
            ldsm_x2(wd + GB_WH, Wh[nb]);
            ldsm_x2(wd + GB_WL, Wl[nb]);
        }
#pragma unroll
        for (int mb = 0; mb < 4; mb++)
#pragma unroll
            for (int nb = 0; nb < 4; nb++) {
                mma16816(Cs[mb][nb], Ah[mb], Wh[nb]);
                mma16816(Cs[mb][nb], Ah[mb], Wl[nb]);
                mma16816(Cs[mb][nb], Al[mb], Wh[nb]);
            }
    }
}

// ================= fused QKV projection =================
__global__ __launch_bounds__(256, 2) void qkv_mma_kernel(
    const float* __restrict__ bq, const float* __restrict__ bk, const float* __restrict__ bv)
{
    extern __shared__ char smem[];
    uint32_t sb = smem_u32(smem);
    const int t    = threadIdx.x;
    const int lane = t & 31;
    const int w    = t >> 5;
    const int wm   = w >> 2;
    const int wn   = w & 3;
    const int m0   = blockIdx.y * 128;
    const int o0   = blockIdx.x * 128;
    const int z    = blockIdx.z;

    const __nv_bfloat16* Whg = g_Wh + (size_t)z * WELEM;
    const __nv_bfloat16* Wlg = g_Wl + (size_t)z * WELEM;
    const float* bias = (z == 0) ? bq : (z == 1) ? bk : bv;
    __nv_bfloat16* dh = (z == 0) ? g_Qh : (z == 1) ? g_Kh : g_Vh;
    __nv_bfloat16* dl = (z == 0) ? g_Ql : (z == 1) ? g_Kl : g_Vl;
    const float scale = (z == 0) ? 0.125f : 1.0f;
    const int   ld    = (z == 2) ? HD : DA;

    float Cs[4][4][4];
#pragma unroll
    for (int mb = 0; mb < 4; mb++)
#pragma unroll
        for (int nb = 0; nb < 4; nb++)
#pragma unroll
            for (int i = 0; i < 4; i++) Cs[mb][nb][i] = 0.f;

    const int a_r  = (lane & 7) + ((lane & 8) ? 8 : 0);
    const int a_c8 = (lane & 16) ? 8 : 0;
    const int b_r  = lane & 7;
    const int b_c8 = (lane & 8) ? 8 : 0;

    gemm_stage(sb, 0, t, m0, o0, 0, g_xh, g_xl, Whg, Wlg);
    for (int kk = 0; kk < 16; kk++) {
        if (kk + 1 < 16) {
            gemm_stage(sb, (kk+1)&1, t, m0, o0, (kk+1)*32, g_xh, g_xl, Whg, Wlg);
            CP_WAIT1;
        } else {
            CP_WAIT0;
        }
        __syncthreads();
        gemm_compute(sb, kk & 1, Cs, wm, wn, a_r, a_c8, b_r, b_c8);
        __syncthreads();
    }

    const int r0l = lane >> 2;
    const int c0l = (lane & 3) * 2;
#pragma unroll
    for (int mb = 0; mb < 4; mb++) {
#pragma unroll
        for (int nb = 0; nb < 4; nb++) {
            int gc = o0 + wn*32 + nb*8 + c0l;
            float2 bbv = *(const float2*)&bias[gc];
            int h  = gc >> 6;
            int hd = gc & 63;
#pragma unroll
            for (int half = 0; half < 2; half++) {
                int gr = m0 + wm*64 + mb*16 + r0l + half*8;
                float vx = (Cs[mb][nb][half*2+0] + bbv.x) * scale;
                float vy = (Cs[mb][nb][half*2+1] + bbv.y) * scale;
                uint32_t hi, lo;
                pack2(vx, vy, hi, lo);
                int b  = gr >> 11;
                int n  = gr & 2047;
                size_t off = ((size_t)((b*HH + h) * NN + n)) * ld + hd;
                *(uint32_t*)&dh[off] = hi;
                *(uint32_t*)&dl[off] = lo;
            }
        }
    }
}

// ================= output projection =================
__global__ __launch_bounds__(256, 2) void oproj_mma_kernel(
    const float* __restrict__ bias, float* __restrict__ out)
{
    extern __shared__ char smem[];
    uint32_t sb = smem_u32(smem);
    const int t    = threadIdx.x;
    const int lane = t & 31;
    const int w    = t >> 5;
    const int wm   = w >> 2;
    const int wn   = w & 3;
    const int m0   = blockIdx.y * 128;
    const int o0   = blockIdx.x * 128;

    const __nv_bfloat16* Whg = g_Wh + (size_t)3 * WELEM;
    const __nv_bfloat16* Wlg = g_Wl + (size_t)3 * WELEM;

    float Cs[4][4][4];
#pragma unroll
    for (int mb = 0; mb < 4; mb++)
#pragma unroll
        for (int nb = 0; nb < 4; nb++)
#pragma unroll
            for (int i = 0; i < 4; i++) Cs[mb][nb][i] = 0.f;

    const int a_r  = (lane & 7) + ((lane & 8) ? 8 : 0);
    const int a_c8 = (lane & 16) ? 8 : 0;
    const int b_r  = lane & 7;
    const int b_c8 = (lane & 8) ? 8 : 0;

    gemm_stage(sb, 0, t, m0, o0, 0, g_atth, g_attl, Whg, Wlg);
    for (int kk = 0; kk < 16; kk++) {
        if (kk + 1 < 16) {
            gemm_stage(sb, (kk+1)&1, t, m0, o0, (kk+1)*32, g_atth, g_attl, Whg, Wlg);
            CP_WAIT1;
        } else {
            CP_WAIT0;
        }
        __syncthreads();
        gemm_compute(sb, kk & 1, Cs, wm, wn, a_r, a_c8, b_r, b_c8);
        __syncthreads();
    }

    const int r0l = lane >> 2;
    const int c0l = (lane & 3) * 2;
#pragma unroll
    for (int mb = 0; mb < 4; mb++) {
#pragma unroll
        for (int nb = 0; nb < 4; nb++) {
            int gc = o0 + wn*32 + nb*8 + c0l;
            float2 bbv = *(const float2*)&bias[gc];
#pragma unroll
            for (int half = 0; half < 2; half++) {
                int gr = m0 + wm*64 + mb*16 + r0l + half*8;
                float2 v;
                v.x = Cs[mb][nb][half*2+0] + bbv.x;
                v.y = Cs[mb][nb][half*2+1] + bbv.y;
                *(float2*)&out[(size_t)gr * DD + gc] = v;
            }
        }
    }
}

// ---------------- phase augmentation fill ----------------
__device__ __forceinline__ void pack8(const float* v, uint4& hi, uint4& lo){
    uint32_t h[4], l[4];
#pragma unroll
    for (int i = 0; i < 4; i++) pack2(v[2*i], v[2*i+1], h[i], l[i]);
    hi.x = h[0]; hi.y = h[1]; hi.z = h[2]; hi.w = h[3];
    lo.x = l[0]; lo.y = l[1]; lo.z = l[2]; lo.w = l[3];
}

__global__ void phase_fill_kernel(const float* __restrict__ pc,
                                  const float* __restrict__ pb)
{
    int tid = blockIdx.x * blockDim.x + threadIdx.x;
    if (tid >= BB * NN * HH) return;
    int h  = tid >> 12;
    int bn = tid & 4095;

    float c[FF], s[FF], wc[FF], ws[FF];
#pragma unroll
    for (int f = 0; f < FF; f++)
        __sincosf(pc[(size_t)bn * FF + f], &s[f], &c[f]);
#pragma unroll
    for (int f = 0; f < FF; f++) {
        float wv = pb[h*FF + f];
        wc[f] = wv * c[f];
        ws[f] = wv * s[f];
    }

    int b = bn >> 11, n = bn & 2047;
    size_t base = ((size_t)((b*HH + h) * NN + n)) * DA + 64;

    uint4 hi, lo;
    pack8(c,  hi, lo); *(uint4*)&g_Kh[base]   = hi; *(uint4*)&g_Kl[base]   = lo;
    pack8(s,  hi, lo); *(uint4*)&g_Kh[base+8] = hi; *(uint4*)&g_Kl[base+8] = lo;
    pack8(wc, hi, lo); *(uint4*)&g_Qh[base]   = hi; *(uint4*)&g_Ql[base]   = lo;
    pack8(ws, hi, lo); *(uint4*)&g_Qh[base+8] = hi; *(uint4*)&g_Ql[base+8] = lo;
}

// =============== bf16x3 warp-MMA flash attention, BQ=64, 128 thr, 2 CTAs/SM ===============
#define QS 88
#define VS 72
#define AKH 0
#define AKL 11264
#define AVH 22528
#define AVL 31744
#define ASTG 40960
#define ATTN_SMEM (2*ASTG)   // 81920

__global__ __launch_bounds__(128, 2) void attn_mma_kernel()
{
    extern __shared__ char smem[];
    uint32_t sb = smem_u32(smem);
    const int t    = threadIdx.x;
    const int lane = t & 31;
    const int w    = t >> 5;          // 0..3, warp owns q rows w*16..w*16+15
    const int q0   = blockIdx.x * BQ;
    const int bh   = blockIdx.y;

    const __nv_bfloat16* Qgh = g_Qh + (size_t)bh * NN * DA + (size_t)q0 * DA;
    const __nv_bfloat16* Qgl = g_Ql + (size_t)bh * NN * DA + (size_t)q0 * DA;
    const __nv_bfloat16* Kgh = g_Kh + (size_t)bh * NN * DA;
    const __nv_bfloat16* Kgl = g_Kl + (size_t)bh * NN * DA;
    const __nv_bfloat16* Vgh = g_Vh + (size_t)bh * NN * HD;
    const __nv_bfloat16* Vgl = g_Vl + (size_t)bh * NN * HD;

    // ---- stage Q tile (64 x 80 hi+lo), extract fragments ----
#pragma unroll
    for (int i = 0; i < 5; i++) {
        int idx = t + i * 128;          // 0..639
        int row = idx / 10;
        int c8  = (idx % 10) * 8;
        uint32_t soff = (uint32_t)(row * QS + c8) * 2u;
        *(uint4*)(smem + soff)         = *(const uint4*)(Qgh + (size_t)row * DA + c8);
        *(uint4*)(smem + AKL + soff)   = *(const uint4*)(Qgl + (size_t)row * DA + c8);
    }
    __syncthreads();

    const int a_r  = (lane & 7) + ((lane & 8) ? 8 : 0);
    const int a_c8 = (lane & 16) ? 8 : 0;
    const int b_r  = lane & 7;
    const int b_c8 = (lane & 8) ? 8 : 0;

    uint32_t Qfh[5][4], Qfl[5][4];
#pragma unroll
    for (int s = 0; s < 5; s++) {
        uint32_t ad = sb + (uint32_t)(((w*16 + a_r) * QS + s*16 + a_c8) * 2);
        ldsm_x4(ad, Qfh[s]);
        ldsm_x4(ad + AKL, Qfl[s]);
    }
    __syncthreads();

    auto prefetch = [&](int stage, int k0){
        uint32_t sa = sb + (uint32_t)stage * ASTG;
#pragma unroll
        for (int i = 0; i < 5; i++) {
            int idx = t + i * 128;      // 0..639
            int row = idx / 10;
            int c8  = (idx % 10) * 8;
            uint32_t so = (uint32_t)(row * QS + c8) * 2u;
            const size_t g = (size_t)(k0 + row) * DA + c8;
            cp16(sa + AKH + so, Kgh + g);
            cp16(sa + AKL + so, Kgl + g);
        }
#pragma unroll
        for (int i = 0; i < 4; i++) {
            int idx = t + i * 128;      // 0..511
            int row = idx >> 3;
            int c8  = (idx & 7) * 8;
            uint32_t so = (uint32_t)(row * VS + c8) * 2u;
            const size_t g = (size_t)(k0 + row) * HD + c8;
            cp16(sa + AVH + so, Vgh + g);
            cp16(sa + AVL + so, Vgl + g);
        }
        CP_COMMIT;
    };

    float mrow[2] = {-1e30f, -1e30f};
    float lrow[2] = {0.f, 0.f};
    float Od[8][4];
#pragma unroll
    for (int db = 0; db < 8; db++)
#pragma unroll
        for (int i = 0; i < 4; i++) Od[db][i] = 0.f;

    prefetch(0, 0);
#pragma unroll 1
    for (int kt = 0; kt < NN/BK; kt++) {
        if (kt + 1 < NN/BK) {
            prefetch((kt+1) & 1, (kt+1) * BK);
            CP_WAIT1;
        } else {
            CP_WAIT0;
        }
        __syncthreads();
        uint32_t sa = sb + (uint32_t)(kt & 1) * ASTG;

        // ---- S = Q . K^T  (bf16x3) ----
        float Cs[8][4];
#pragma unroll
        for (int nb = 0; nb < 8; nb++)
#pragma unroll
            for (int i = 0; i < 4; i++) Cs[nb][i] = 0.f;

#pragma unroll
        for (int s = 0; s < 5; s++) {
#pragma unroll
            for (int nb = 0; nb < 8; nb++) {
                uint32_t kd = sa + (uint32_t)(((nb*8 + b_r) * QS + s*16 + b_c8) * 2);
                uint32_t bh2[2], bl2[2];
                ldsm_x2(kd + AKH, bh2);
                ldsm_x2(kd + AKL, bl2);
                mma16816(Cs[nb], Qfh[s], bh2);
                mma16816(Cs[nb], Qfh[s], bl2);
                mma16816(Cs[nb], Qfl[s], bh2);
            }
        }

        // ---- online softmax ----
        float mx0 = -1e30f, mx1 = -1e30f;
#pragma unroll
        for (int nb = 0; nb < 8; nb++) {
            mx0 = fmaxf(mx0, fmaxf(Cs[nb][0], Cs[nb][1]));
            mx1 = fmaxf(mx1, fmaxf(Cs[nb][2], Cs[nb][3]));
        }
        mx0 = fmaxf(mx0, __shfl_xor_sync(0xffffffffu, mx0, 1));
        mx0 = fmaxf(mx0, __shfl_xor_sync(0xffffffffu, mx0, 2));
        mx1 = fmaxf(mx1, __shfl_xor_sync(0xffffffffu, mx1, 1));
        mx1 = fmaxf(mx1, __shfl_xor_sync(0xffffffffu, mx1, 2));
        float mn0 = fmaxf(mrow[0], mx0);
        float mn1 = fmaxf(mrow[1], mx1);
        float f0  = __expf(mrow[0] - mn0);
        float f1  = __expf(mrow[1] - mn1);
        mrow[0] = mn0; mrow[1] = mn1;

        float s0 = 0.f, s1 = 0.f;
        uint32_t Ph[4][4], Pl[4][4];
#pragma unroll
        for (int ks = 0; ks < 4; ks++) {
#pragma unroll
            for (int hf = 0; hf < 2; hf++) {
                int nb = 2*ks + hf;
                float p0 = __expf(Cs[nb][0] - mn0);
                float p1 = __expf(Cs[nb][1] - mn0);
                float p2 = __expf(Cs[nb][2] - mn1);
                float p3 = __expf(Cs[nb][3] - mn1);
                s0 += p0 + p1;
                s1 += p2 + p3;
                pack2(p0, p1, Ph[ks][hf*2+0], Pl[ks][hf*2+0]);
                pack2(p2, p3, Ph[ks][hf*2+1], Pl[ks][hf*2+1]);
            }
        }
        s0 += __shfl_xor_sync(0xffffffffu, s0, 1);
        s0 += __shfl_xor_sync(0xffffffffu, s0, 2);
        s1 += __shfl_xor_sync(0xffffffffu, s1, 1);
        s1 += __shfl_xor_sync(0xffffffffu, s1, 2);
        lrow[0] = lrow[0] * f0 + s0;
        lrow[1] = lrow[1] * f1 + s1;

#pragma unroll
        for (int db = 0; db < 8; db++) {
            Od[db][0] *= f0; Od[db][1] *= f0;
            Od[db][2] *= f1; Od[db][3] *= f1;
        }

        // ---- O += P . V  (bf16x3; V via ldmatrix.trans) ----
#pragma unroll
        for (int ks = 0; ks < 4; ks++) {
#pragma unroll
            for (int db = 0; db < 8; db++) {
                uint32_t vaddr = sa + (uint32_t)(((ks*16 + b_r + ((lane & 8) ? 8 : 0)) * VS + db*8) * 2);
                uint32_t vh2[2], vl2[2];
                ldsm_x2t(vaddr + AVH, vh2);
                ldsm_x2t(vaddr + AVL, vl2);
                mma16816(Od[db], Ph[ks], vh2);
                mma16816(Od[db], Ph[ks], vl2);
                mma16816(Od[db], Pl[ks], vh2);
            }
        }
        __syncthreads();
    }

    // ---- epilogue: write att as bf16 hi/lo ----
    float i0 = 1.0f / lrow[0];
    float i1 = 1.0f / lrow[1];
    int b = bh >> 3, h = bh & 7;
    int r0l = w*16 + (lane >> 2);
    int c0l = (lane & 3) * 2;
#pragma unroll
    for (int db = 0; db < 8; db++) {
        int gc = h*64 + db*8 + c0l;
        uint32_t hi0, lo0, hi1, lo1;
        pack2(Od[db][0] * i0, Od[db][1] * i0, hi0, lo0);
        pack2(Od[db][2] * i1, Od[db][3] * i1, hi1, lo1);
        size_t o0r = ((size_t)(b*NN + q0 + r0l)) * DD + gc;
        size_t o1r = ((size_t)(b*NN + q0 + r0l + 8)) * DD + gc;
        *(uint32_t*)&g_atth[o0r] = hi0;
        *(uint32_t*)&g_attl[o0r] = lo0;
        *(uint32_t*)&g_atth[o1r] = hi1;
        *(uint32_t*)&g_attl[o1r] = lo1;
    }
}

// ---------------- launch ----------------
extern "C" void kernel_launch(void* const* d_in, const int* in_sizes, int n_in,
                              void* d_out, int out_size)
{
    const float* x   = (const float*)d_in[0];
    const float* pc  = (const float*)d_in[1];
    const float* Wq  = (const float*)d_in[2];
    const float* bq  = (const float*)d_in[3];
    const float* Wk  = (const float*)d_in[4];
    const float* bk  = (const float*)d_in[5];
    const float* Wv  = (const float*)d_in[6];
    const float* bv  = (const float*)d_in[7];
    const float* Wo  = (const float*)d_in[8];
    const float* bo  = (const float*)d_in[9];
    const float* pb  = (const float*)d_in[10];
    float* out = (float*)d_out;

    cudaFuncSetAttribute(attn_mma_kernel,  cudaFuncAttributeMaxDynamicSharedMemorySize, ATTN_SMEM);
    cudaFuncSetAttribute(qkv_mma_kernel,   cudaFuncAttributeMaxDynamicSharedMemorySize, GEMM_SMEM);
    cudaFuncSetAttribute(oproj_mma_kernel, cudaFuncAttributeMaxDynamicSharedMemorySize, GEMM_SMEM);

    int totc = XC + 4*WC;   // 786432
    convert_kernel<<<(totc + 255)/256, 256>>>(x, Wq, Wk, Wv, Wo);

    dim3 qgrid(4, 32, 3);
    qkv_mma_kernel<<<qgrid, 256, GEMM_SMEM>>>(bq, bk, bv);

    phase_fill_kernel<<<(BB*NN*HH + 255)/256, 256>>>(pc, pb);

    dim3 agrid(NN/BQ, BB*HH);   // (32, 16)
    attn_mma_kernel<<<agrid, 128, ATTN_SMEM>>>();

    dim3 ggrid(4, 32);
    oproj_mma_kernel<<<ggrid, 256, GEMM_SMEM>>>(bo, out);
}

// round 7
// speedup vs baseline: 3.7036x; 1.0195x over previous
#include <cuda_runtime.h>
#include <cuda_bf16.h>
#include <cstdint>
#include <math.h>

// Problem constants
#define BB 2
#define NN 2048
#define DD 512
#define HH 8
#define FF 8
#define HD 64
#define DA 80   // augmented head dim: 64 (Q/K) + 8 (cos) + 8 (sin)
#define BQ 64   // q rows per CTA (attention)
#define BK 64   // keys per tile
#define NT (NN/BK)   // 32 key tiles

#define MTOT (BB*NN)          // 4096
#define WELEM (DD*DD)         // 262144
#define LOG2E 1.4426950408889634f

// ---------------- scratch (device globals; no allocation) ----------------
__device__ __nv_bfloat16 g_xh[MTOT*DD], g_xl[MTOT*DD];
__device__ __nv_bfloat16 g_Wh[4*WELEM], g_Wl[4*WELEM];     // Wq,Wk,Wv,Wo
__device__ __nv_bfloat16 g_Qh[BB*HH*NN*DA], g_Ql[BB*HH*NN*DA];
__device__ __nv_bfloat16 g_Kh[BB*HH*NN*DA], g_Kl[BB*HH*NN*DA];
__device__ __nv_bfloat16 g_Vh[BB*HH*NN*HD], g_Vl[BB*HH*NN*HD];
__device__ __nv_bfloat16 g_atth[MTOT*DD], g_attl[MTOT*DD];

// ======================= helpers =======================
__device__ __forceinline__ uint32_t smem_u32(const void* p){
    uint32_t a;
    asm("{ .reg .u64 t; cvta.to.shared.u64 t, %1; cvt.u32.u64 %0, t; }" : "=r"(a) : "l"(p));
    return a;
}
__device__ __forceinline__ void ldsm_x4(uint32_t addr, uint32_t r[4]){
    asm volatile("ldmatrix.sync.aligned.m8n8.x4.shared.b16 {%0,%1,%2,%3}, [%4];"
        : "=r"(r[0]), "=r"(r[1]), "=r"(r[2]), "=r"(r[3]) : "r"(addr));
}
__device__ __forceinline__ void ldsm_x4t(uint32_t addr, uint32_t r[4]){
    asm volatile("ldmatrix.sync.aligned.m8n8.x4.trans.shared.b16 {%0,%1,%2,%3}, [%4];"
        : "=r"(r[0]), "=r"(r[1]), "=r"(r[2]), "=r"(r[3]) : "r"(addr));
}
__device__ __forceinline__ void mma16816(float c[4], const uint32_t a[4], const uint32_t b[2]){
    asm volatile("mma.sync.aligned.m16n8k16.row.col.f32.bf16.bf16.f32 "
        "{%0,%1,%2,%3}, {%4,%5,%6,%7}, {%8,%9}, {%0,%1,%2,%3};"
        : "+f"(c[0]), "+f"(c[1]), "+f"(c[2]), "+f"(c[3])
        : "r"(a[0]), "r"(a[1]), "r"(a[2]), "r"(a[3]), "r"(b[0]), "r"(b[1]));
}
__device__ __forceinline__ uint32_t b2u(__nv_bfloat162 v){ return *reinterpret_cast<uint32_t*>(&v); }
__device__ __forceinline__ void cp16(uint32_t dst, const void* src){
    asm volatile("cp.async.cg.shared.global [%0], [%1], 16;" :: "r"(dst), "l"(src));
}
#define CP_COMMIT asm volatile("cp.async.commit_group;" ::: "memory")
#define CP_WAIT1  asm volatile("cp.async.wait_group 1;" ::: "memory")
#define CP_WAIT0  asm volatile("cp.async.wait_group 0;" ::: "memory")

__device__ __forceinline__ float ex2(float x){
    float r; asm("ex2.approx.ftz.f32 %0, %1;" : "=f"(r) : "f"(x)); return r;
}
__device__ __forceinline__ void pack2(float vx, float vy, uint32_t& hi, uint32_t& lo){
    __nv_bfloat162 h = __floats2bfloat162_rn(vx, vy);
    __nv_bfloat162 l = __floats2bfloat162_rn(vx - __low2float(h), vy - __high2float(h));
    hi = b2u(h); lo = b2u(l);
}

// ================= fp32 -> bf16 hi/lo conversion =================
#define XC ((MTOT*DD)/4)
#define WC (WELEM/4)
__global__ void convert_kernel(const float* __restrict__ x,
                               const float* __restrict__ Wq, const float* __restrict__ Wk,
                               const float* __restrict__ Wv, const float* __restrict__ Wo)
{
    int i = blockIdx.x * blockDim.x + threadIdx.x;
    const float* src;
    __nv_bfloat16 *dh, *dl;
    int off;
    if (i < XC) { src = x; dh = g_xh; dl = g_xl; off = i; }
    else {
        int j = i - XC;
        int w = j >> 16;
        off   = j & (WC - 1);
        src = (w == 0) ? Wq : (w == 1) ? Wk : (w == 2) ? Wv : Wo;
        dh = g_Wh + (size_t)w * WELEM;
        dl = g_Wl + (size_t)w * WELEM;
    }
    float4 v = ((const float4*)src)[off];
    uint2 uh, ul;
    pack2(v.x, v.y, uh.x, ul.x);
    pack2(v.z, v.w, uh.y, ul.y);
    *(uint2*)&dh[4*(size_t)off] = uh;
    *(uint2*)&dl[4*(size_t)off] = ul;
}

// ================= GEMM staging (2 stages x 40960 B) =================
#define AS 40
#define GB_AH 0
#define GB_AL 10240
#define GB_WH 20480
#define GB_WL 30720
#define STG   40960
#define GEMM_SMEM (2*STG)

__device__ __forceinline__ void gemm_stage(
    uint32_t sb, int stage, int t, int m0, int o0, int k0,
    const __nv_bfloat16* Ahg, const __nv_bfloat16* Alg,
    const __nv_bfloat16* Whg, const __nv_bfloat16* Wlg)
{
    uint32_t sa = sb + (uint32_t)stage * STG;
#pragma unroll
    for (int i = 0; i < 2; i++) {
        int c   = t + i * 256;
        int row = c >> 2;
        int ce  = (c & 3) << 3;
        uint32_t so = (uint32_t)(row * AS + ce) * 2u;
        cp16(sa + GB_AH + so, Ahg + (size_t)(m0 + row) * DD + k0 + ce);
        cp16(sa + GB_AL + so, Alg + (size_t)(m0 + row) * DD + k0 + ce);
        cp16(sa + GB_WH + so, Whg + (size_t)(o0 + row) * DD + k0 + ce);
        cp16(sa + GB_WL + so, Wlg + (size_t)(o0 + row) * DD + k0 + ce);
    }
    CP_COMMIT;
}

__device__ __forceinline__ void gemm_compute(
    uint32_t sb, int stage, float Cs[4][4][4],
    int wm, int wn, int a_r, int a_c8, int b_r, int b_c8, int b_r16)
{
    uint32_t sa = sb + (uint32_t)stage * STG;
#pragma unroll
    for (int ks = 0; ks < 2; ks++) {
        uint32_t Ah[4][4], Al[4][4], WH[2][4], WL[2][4];
#pragma unroll
        for (int mb = 0; mb < 4; mb++) {
            uint32_t ad = sa + (uint32_t)(((wm*64 + mb*16 + a_r) * AS + ks*16 + a_c8) * 2);
            ldsm_x4(ad + GB_AH, Ah[mb]);
            ldsm_x4(ad + GB_AL, Al[mb]);
        }
#pragma unroll
        for (int j = 0; j < 2; j++) {
            uint32_t wd = sa + (uint32_t)(((wn*32 + j*16 + b_r + b_r16) * AS + ks*16 + b_c8) * 2);
            ldsm_x4(wd + GB_WH, WH[j]);
            ldsm_x4(wd + GB_WL, WL[j]);
        }
#pragma unroll
        for (int mb = 0; mb < 4; mb++)
#pragma unroll
            for (int nb = 0; nb < 4; nb++) {
                const uint32_t* bh = &WH[nb>>1][(nb&1)*2];
                const uint32_t* bl = &WL[nb>>1][(nb&1)*2];
                mma16816(Cs[mb][nb], Ah[mb], bh);
                mma16816(Cs[mb][nb], Ah[mb], bl);
                mma16816(Cs[mb][nb], Al[mb], bh);
            }
    }
}

// ================= fused QKV projection =================
__global__ __launch_bounds__(256, 2) void qkv_mma_kernel(
    const float* __restrict__ bq, const float* __restrict__ bk, const float* __restrict__ bv)
{
    extern __shared__ char smem[];
    uint32_t sb = smem_u32(smem);
    const int t    = threadIdx.x;
    const int lane = t & 31;
    const int w    = t >> 5;
    const int wm   = w >> 2;
    const int wn   = w & 3;
    const int m0   = blockIdx.y * 128;
    const int o0   = blockIdx.x * 128;
    const int z    = blockIdx.z;

    const __nv_bfloat16* Whg = g_Wh + (size_t)z * WELEM;
    const __nv_bfloat16* Wlg = g_Wl + (size_t)z * WELEM;
    const float* bias = (z == 0) ? bq : (z == 1) ? bk : bv;
    __nv_bfloat16* dh = (z == 0) ? g_Qh : (z == 1) ? g_Kh : g_Vh;
    __nv_bfloat16* dl = (z == 0) ? g_Ql : (z == 1) ? g_Kl : g_Vl;
    const float scale = (z == 0) ? 0.125f * LOG2E : 1.0f;   // fold log2e into Q
    const int   ld    = (z == 2) ? HD : DA;

    float Cs[4][4][4];
#pragma unroll
    for (int mb = 0; mb < 4; mb++)
#pragma unroll
        for (int nb = 0; nb < 4; nb++)
#pragma unroll
            for (int i = 0; i < 4; i++) Cs[mb][nb][i] = 0.f;

    const int a_r   = (lane & 7) + ((lane & 8) ? 8 : 0);
    const int a_c8  = (lane & 16) ? 8 : 0;
    const int b_r   = lane & 7;
    const int b_c8  = (lane & 8) ? 8 : 0;
    const int b_r16 = (lane & 16) ? 8 : 0;

    gemm_stage(sb, 0, t, m0, o0, 0, g_xh, g_xl, Whg, Wlg);
    for (int kk = 0; kk < 16; kk++) {
        if (kk + 1 < 16) {
            gemm_stage(sb, (kk+1)&1, t, m0, o0, (kk+1)*32, g_xh, g_xl, Whg, Wlg);
            CP_WAIT1;
        } else {
            CP_WAIT0;
        }
        __syncthreads();
        gemm_compute(sb, kk & 1, Cs, wm, wn, a_r, a_c8, b_r, b_c8, b_r16);
        __syncthreads();
    }

    const int r0l = lane >> 2;
    const int c0l = (lane & 3) * 2;
#pragma unroll
    for (int mb = 0; mb < 4; mb++) {
#pragma unroll
        for (int nb = 0; nb < 4; nb++) {
            int gc = o0 + wn*32 + nb*8 + c0l;
            float2 bbv = *(const float2*)&bias[gc];
            int h  = gc >> 6;
            int hd = gc & 63;
#pragma unroll
            for (int half = 0; half < 2; half++) {
                int gr = m0 + wm*64 + mb*16 + r0l + half*8;
                float vx = (Cs[mb][nb][half*2+0] + bbv.x) * scale;
                float vy = (Cs[mb][nb][half*2+1] + bbv.y) * scale;
                uint32_t hi, lo;
                pack2(vx, vy, hi, lo);
                int b  = gr >> 11;
                int n  = gr & 2047;
                size_t off = ((size_t)((b*HH + h) * NN + n)) * ld + hd;
                *(uint32_t*)&dh[off] = hi;
                *(uint32_t*)&dl[off] = lo;
            }
        }
    }
}

// ================= output projection =================
__global__ __launch_bounds__(256, 2) void oproj_mma_kernel(
    const float* __restrict__ bias, float* __restrict__ out)
{
    extern __shared__ char smem[];
    uint32_t sb = smem_u32(smem);
    const int t    = threadIdx.x;
    const int lane = t & 31;
    const int w    = t >> 5;
    const int wm   = w >> 2;
    const int wn   = w & 3;
    const int m0   = blockIdx.y * 128;
    const int o0   = blockIdx.x * 128;

    const __nv_bfloat16* Whg = g_Wh + (size_t)3 * WELEM;
    const __nv_bfloat16* Wlg = g_Wl + (size_t)3 * WELEM;

    float Cs[4][4][4];
#pragma unroll
    for (int mb = 0; mb < 4; mb++)
#pragma unroll
        for (int nb = 0; nb < 4; nb++)
#pragma unroll
            for (int i = 0; i < 4; i++) Cs[mb][nb][i] = 0.f;

    const int a_r   = (lane & 7) + ((lane & 8) ? 8 : 0);
    const int a_c8  = (lane & 16) ? 8 : 0;
    const int b_r   = lane & 7;
    const int b_c8  = (lane & 8) ? 8 : 0;
    const int b_r16 = (lane & 16) ? 8 : 0;

    gemm_stage(sb, 0, t, m0, o0, 0, g_atth, g_attl, Whg, Wlg);
    for (int kk = 0; kk < 16; kk++) {
        if (kk + 1 < 16) {
            gemm_stage(sb, (kk+1)&1, t, m0, o0, (kk+1)*32, g_atth, g_attl, Whg, Wlg);
            CP_WAIT1;
        } else {
            CP_WAIT0;
        }
        __syncthreads();
        gemm_compute(sb, kk & 1, Cs, wm, wn, a_r, a_c8, b_r, b_c8, b_r16);
        __syncthreads();
    }

    const int r0l = lane >> 2;
    const int c0l = (lane & 3) * 2;
#pragma unroll
    for (int mb = 0; mb < 4; mb++) {
#pragma unroll
        for (int nb = 0; nb < 4; nb++) {
            int gc = o0 + wn*32 + nb*8 + c0l;
            float2 bbv = *(const float2*)&bias[gc];
#pragma unroll
            for (int half = 0; half < 2; half++) {
                int gr = m0 + wm*64 + mb*16 + r0l + half*8;
                float2 v;
                v.x = Cs[mb][nb][half*2+0] + bbv.x;
                v.y = Cs[mb][nb][half*2+1] + bbv.y;
                *(float2*)&out[(size_t)gr * DD + gc] = v;
            }
        }
    }
}

// ---------------- phase augmentation fill (log2e folded into Q weights) ----------------
__device__ __forceinline__ void pack8(const float* v, uint4& hi, uint4& lo){
    uint32_t h[4], l[4];
#pragma unroll
    for (int i = 0; i < 4; i++) pack2(v[2*i], v[2*i+1], h[i], l[i]);
    hi.x = h[0]; hi.y = h[1]; hi.z = h[2]; hi.w = h[3];
    lo.x = l[0]; lo.y = l[1]; lo.z = l[2]; lo.w = l[3];
}

__global__ void phase_fill_kernel(const float* __restrict__ pc,
                                  const float* __restrict__ pb)
{
    int tid = blockIdx.x * blockDim.x + threadIdx.x;
    if (tid >= BB * NN * HH) return;
    int h  = tid >> 12;
    int bn = tid & 4095;

    float c[FF], s[FF], wc[FF], ws[FF];
#pragma unroll
    for (int f = 0; f < FF; f++)
        __sincosf(pc[(size_t)bn * FF + f], &s[f], &c[f]);
#pragma unroll
    for (int f = 0; f < FF; f++) {
        float wv = pb[h*FF + f] * LOG2E;
        wc[f] = wv * c[f];
        ws[f] = wv * s[f];
    }

    int b = bn >> 11, n = bn & 2047;
    size_t base = ((size_t)((b*HH + h) * NN + n)) * DA + 64;

    uint4 hi, lo;
    pack8(c,  hi, lo); *(uint4*)&g_Kh[base]   = hi; *(uint4*)&g_Kl[base]   = lo;
    pack8(s,  hi, lo); *(uint4*)&g_Kh[base+8] = hi; *(uint4*)&g_Kl[base+8] = lo;
    pack8(wc, hi, lo); *(uint4*)&g_Qh[base]   = hi; *(uint4*)&g_Ql[base]   = lo;
    pack8(ws, hi, lo); *(uint4*)&g_Qh[base+8] = hi; *(uint4*)&g_Ql[base+8] = lo;
}

// =============== pipelined bf16x3 warp-MMA flash attention ===============
// smem: K ring (2 stages) + V ring (3 stages)
#define QS 88
#define VS 72
#define K_L   11264
#define KSTG  22528
#define VBASE 45056
#define V_L   9216
#define VSTG  18432
#define ATTN_SMEM (VBASE + 3*VSTG)   // 100352

__device__ __forceinline__ void qk_tile(uint32_t ka, float Cs[8][4],
    const uint32_t Qfh[5][4], const uint32_t Qfl[5][4], int b_r, int roff, int coff)
{
#pragma unroll
    for (int nb = 0; nb < 8; nb++)
#pragma unroll
        for (int i = 0; i < 4; i++) Cs[nb][i] = 0.f;
#pragma unroll
    for (int s = 0; s < 5; s++) {
#pragma unroll
        for (int j = 0; j < 4; j++) {
            uint32_t kd = ka + (uint32_t)(((j*16 + b_r + roff) * QS + s*16 + coff) * 2);
            uint32_t h4[4], l4[4];
            ldsm_x4(kd, h4);
            ldsm_x4(kd + K_L, l4);
            mma16816(Cs[2*j],   Qfh[s], h4+0);
            mma16816(Cs[2*j],   Qfh[s], l4+0);
            mma16816(Cs[2*j],   Qfl[s], h4+0);
            mma16816(Cs[2*j+1], Qfh[s], h4+2);
            mma16816(Cs[2*j+1], Qfh[s], l4+2);
            mma16816(Cs[2*j+1], Qfl[s], h4+2);
        }
    }
}

__device__ __forceinline__ void softmax_tile(const float Cs[8][4],
    float mrow[2], float lrow[2],
    uint32_t Ph[4][4], uint32_t Pl[4][4], float& f0o, float& f1o)
{
    float mx0 = -1e30f, mx1 = -1e30f;
#pragma unroll
    for (int nb = 0; nb < 8; nb++) {
        mx0 = fmaxf(mx0, fmaxf(Cs[nb][0], Cs[nb][1]));
        mx1 = fmaxf(mx1, fmaxf(Cs[nb][2], Cs[nb][3]));
    }
    mx0 = fmaxf(mx0, __shfl_xor_sync(0xffffffffu, mx0, 1));
    mx0 = fmaxf(mx0, __shfl_xor_sync(0xffffffffu, mx0, 2));
    mx1 = fmaxf(mx1, __shfl_xor_sync(0xffffffffu, mx1, 1));
    mx1 = fmaxf(mx1, __shfl_xor_sync(0xffffffffu, mx1, 2));
    float mn0 = fmaxf(mrow[0], mx0);
    float mn1 = fmaxf(mrow[1], mx1);
    f0o = ex2(mrow[0] - mn0);
    f1o = ex2(mrow[1] - mn1);
    mrow[0] = mn0; mrow[1] = mn1;

    float s0 = 0.f, s1 = 0.f;
#pragma unroll
    for (int ks = 0; ks < 4; ks++) {
#pragma unroll
        for (int hf = 0; hf < 2; hf++) {
            int nb = 2*ks + hf;
            float p0 = ex2(Cs[nb][0] - mn0);
            float p1 = ex2(Cs[nb][1] - mn0);
            float p2 = ex2(Cs[nb][2] - mn1);
            float p3 = ex2(Cs[nb][3] - mn1);
            s0 += p0 + p1;
            s1 += p2 + p3;
            pack2(p0, p1, Ph[ks][hf*2+0], Pl[ks][hf*2+0]);
            pack2(p2, p3, Ph[ks][hf*2+1], Pl[ks][hf*2+1]);
        }
    }
    s0 += __shfl_xor_sync(0xffffffffu, s0, 1);
    s0 += __shfl_xor_sync(0xffffffffu, s0, 2);
    s1 += __shfl_xor_sync(0xffffffffu, s1, 1);
    s1 += __shfl_xor_sync(0xffffffffu, s1, 2);
    lrow[0] = lrow[0] * f0o + s0;
    lrow[1] = lrow[1] * f1o + s1;
}

__device__ __forceinline__ void pv_tile(uint32_t va, float Od[8][4],
    const uint32_t Ph[4][4], const uint32_t Pl[4][4],
    float f0, float f1, int b_r, int roff8, int coff16)
{
#pragma unroll
    for (int db = 0; db < 8; db++) {
        Od[db][0] *= f0; Od[db][1] *= f0;
        Od[db][2] *= f1; Od[db][3] *= f1;
    }
#pragma unroll
    for (int ks = 0; ks < 4; ks++) {
#pragma unroll
        for (int j = 0; j < 4; j++) {
            uint32_t vd = va + (uint32_t)(((ks*16 + b_r + roff8) * VS + j*16 + coff16) * 2);
            uint32_t h4[4], l4[4];
            ldsm_x4t(vd, h4);
            ldsm_x4t(vd + V_L, l4);
            mma16816(Od[2*j],   Ph[ks], h4+0);
            mma16816(Od[2*j],   Ph[ks], l4+0);
            mma16816(Od[2*j],   Pl[ks], h4+0);
            mma16816(Od[2*j+1], Ph[ks], h4+2);
            mma16816(Od[2*j+1], Ph[ks], l4+2);
            mma16816(Od[2*j+1], Pl[ks], h4+2);
        }
    }
}

__global__ __launch_bounds__(128, 2) void attn_mma_kernel()
{
    extern __shared__ char smem[];
    uint32_t sb = smem_u32(smem);
    const int t    = threadIdx.x;
    const int lane = t & 31;
    const int w    = t >> 5;
    const int q0   = blockIdx.x * BQ;
    const int bh   = blockIdx.y;

    const __nv_bfloat16* Qgh = g_Qh + (size_t)bh * NN * DA + (size_t)q0 * DA;
    const __nv_bfloat16* Qgl = g_Ql + (size_t)bh * NN * DA + (size_t)q0 * DA;
    const __nv_bfloat16* Kgh = g_Kh + (size_t)bh * NN * DA;
    const __nv_bfloat16* Kgl = g_Kl + (size_t)bh * NN * DA;
    const __nv_bfloat16* Vgh = g_Vh + (size_t)bh * NN * HD;
    const __nv_bfloat16* Vgl = g_Vl + (size_t)bh * NN * HD;

    auto prefetch = [&](int kt){
        uint32_t ka = sb + (uint32_t)(kt & 1) * KSTG;
        uint32_t va = sb + VBASE + (uint32_t)(kt % 3) * VSTG;
        int k0 = kt * BK;
#pragma unroll
        for (int i = 0; i < 5; i++) {
            int idx = t + i * 128;
            int row = idx / 10;
            int c8  = (idx % 10) * 8;
            uint32_t so = (uint32_t)(row * QS + c8) * 2u;
            const size_t g = (size_t)(k0 + row) * DA + c8;
            cp16(ka + so, Kgh + g);
            cp16(ka + K_L + so, Kgl + g);
        }
#pragma unroll
        for (int i = 0; i < 4; i++) {
            int idx = t + i * 128;
            int row = idx >> 3;
            int c8  = (idx & 7) * 8;
            uint32_t so = (uint32_t)(row * VS + c8) * 2u;
            const size_t g = (size_t)(k0 + row) * HD + c8;
            cp16(va + so, Vgh + g);
            cp16(va + V_L + so, Vgl + g);
        }
        CP_COMMIT;
    };

    // prefetch tile 0, stage Q into V-ring slots 1 (hi) and 2 (lo)
    prefetch(0);
    {
        uint32_t qh_off = VBASE + VSTG;
        uint32_t ql_off = VBASE + 2*VSTG;
#pragma unroll
        for (int i = 0; i < 5; i++) {
            int idx = t + i * 128;
            int row = idx / 10;
            int c8  = (idx % 10) * 8;
            uint32_t soff = (uint32_t)(row * QS + c8) * 2u;
            *(uint4*)(smem + qh_off + soff) = *(const uint4*)(Qgh + (size_t)row * DA + c8);
            *(uint4*)(smem + ql_off + soff) = *(const uint4*)(Qgl + (size_t)row * DA + c8);
        }
    }
    __syncthreads();

    const int a_r   = (lane & 7) + ((lane & 8) ? 8 : 0);
    const int a_c8  = (lane & 16) ? 8 : 0;
    const int b_r   = lane & 7;
    const int b_c8  = (lane & 8) ? 8 : 0;
    const int b_r16 = (lane & 16) ? 8 : 0;
    const int v_r8  = (lane & 8) ? 8 : 0;

    uint32_t Qfh[5][4], Qfl[5][4];
#pragma unroll
    for (int s = 0; s < 5; s++) {
        uint32_t ad = sb + VBASE + VSTG + (uint32_t)(((w*16 + a_r) * QS + s*16 + a_c8) * 2);
        ldsm_x4(ad, Qfh[s]);
        ldsm_x4(ad + VSTG, Qfl[s]);
    }
    __syncthreads();

    float mrow[2] = {-1e30f, -1e30f};
    float lrow[2] = {0.f, 0.f};
    float Od[8][4];
#pragma unroll
    for (int db = 0; db < 8; db++)
#pragma unroll
        for (int i = 0; i < 4; i++) Od[db][i] = 0.f;

    uint32_t Pph[4][4], Ppl[4][4];
    float f0p, f1p;

    // ---- peeled iteration 0: QK + softmax only ----
    prefetch(1);
    CP_WAIT1;
    __syncthreads();
    {
        float Cs[8][4];
        qk_tile(sb + 0*KSTG, Cs, Qfh, Qfl, b_r, b_r16, b_c8);
        softmax_tile(Cs, mrow, lrow, Pph, Ppl, f0p, f1p);
    }
    __syncthreads();

    // ---- pipelined mainloop kt = 1..NT-1 ----
#pragma unroll 1
    for (int kt = 1; kt < NT; kt++) {
        if (kt + 1 < NT) {
            prefetch(kt + 1);
            CP_WAIT1;
        } else {
            CP_WAIT0;
        }
        __syncthreads();

        float Cs[8][4];
        qk_tile(sb + (uint32_t)(kt & 1) * KSTG, Cs, Qfh, Qfl, b_r, b_r16, b_c8);
        // PV of previous tile — independent of Cs; overlaps softmax below
        pv_tile(sb + VBASE + (uint32_t)((kt - 1) % 3) * VSTG, Od, Pph, Ppl,
                f0p, f1p, b_r, v_r8, b_r16);
        softmax_tile(Cs, mrow, lrow, Pph, Ppl, f0p, f1p);
        __syncthreads();
    }

    // ---- final PV (tile NT-1) ----
    pv_tile(sb + VBASE + (uint32_t)((NT - 1) % 3) * VSTG, Od, Pph, Ppl,
            f0p, f1p, b_r, v_r8, b_r16);

    // ---- epilogue: write att as bf16 hi/lo ----
    float i0 = 1.0f / lrow[0];
    float i1 = 1.0f / lrow[1];
    int b = bh >> 3, h = bh & 7;
    int r0l = w*16 + (lane >> 2);
    int c0l = (lane & 3) * 2;
#pragma unroll
    for (int db = 0; db < 8; db++) {
        int gc = h*64 + db*8 + c0l;
        uint32_t hi0, lo0, hi1, lo1;
        pack2(Od[db][0] * i0, Od[db][1] * i0, hi0, lo0);
        pack2(Od[db][2] * i1, Od[db][3] * i1, hi1, lo1);
        size_t o0r = ((size_t)(b*NN + q0 + r0l)) * DD + gc;
        size_t o1r = ((size_t)(b*NN + q0 + r0l + 8)) * DD + gc;
        *(uint32_t*)&g_atth[o0r] = hi0;
        *(uint32_t*)&g_attl[o0r] = lo0;
        *(uint32_t*)&g_atth[o1r] = hi1;
        *(uint32_t*)&g_attl[o1r] = lo1;
    }
}

// ---------------- launch ----------------
extern "C" void kernel_launch(void* const* d_in, const int* in_sizes, int n_in,
                              void* d_out, int out_size)
{
    const float* x   = (const float*)d_in[0];
    const float* pc  = (const float*)d_in[1];
    const float* Wq  = (const float*)d_in[2];
    const float* bq  = (const float*)d_in[3];
    const float* Wk  = (const float*)d_in[4];
    const float* bk  = (const float*)d_in[5];
    const float* Wv  = (const float*)d_in[6];
    const float* bv  = (const float*)d_in[7];
    const float* Wo  = (const float*)d_in[8];
    const float* bo  = (const float*)d_in[9];
    const float* pb  = (const float*)d_in[10];
    float* out = (float*)d_out;

    cudaFuncSetAttribute(attn_mma_kernel,  cudaFuncAttributeMaxDynamicSharedMemorySize, ATTN_SMEM);
    cudaFuncSetAttribute(qkv_mma_kernel,   cudaFuncAttributeMaxDynamicSharedMemorySize, GEMM_SMEM);
    cudaFuncSetAttribute(oproj_mma_kernel, cudaFuncAttributeMaxDynamicSharedMemorySize, GEMM_SMEM);

    int totc = XC + 4*WC;
    convert_kernel<<<(totc + 255)/256, 256>>>(x, Wq, Wk, Wv, Wo);

    dim3 qgrid(4, 32, 3);
    qkv_mma_kernel<<<qgrid, 256, GEMM_SMEM>>>(bq, bk, bv);

    phase_fill_kernel<<<(BB*NN*HH + 255)/256, 256>>>(pc, pb);

    dim3 agrid(NN/BQ, BB*HH);   // (32, 16)
    attn_mma_kernel<<<agrid, 128, ATTN_SMEM>>>();

    dim3 ggrid(4, 32);
    oproj_mma_kernel<<<ggrid, 256, GEMM_SMEM>>>(bo, out);
}

// round 8
// speedup vs baseline: 3.8490x; 1.0393x over previous
#include <cuda_runtime.h>
#include <cuda_bf16.h>
#include <cstdint>
#include <math.h>

// Problem constants
#define BB 2
#define NN 2048
#define DD 512
#define HH 8
#define FF 8
#define HD 64
#define DA 80   // augmented head dim: 64 (Q/K) + 8 (cos) + 8 (sin)
#define BQ 128  // q rows per CTA (attention)
#define BK 128  // keys per mainloop iteration
#define NT2 (NN/BK)   // 16 iterations

#define MTOT (BB*NN)          // 4096
#define WELEM (DD*DD)         // 262144
#define LOG2E 1.4426950408889634f

// ---------------- scratch (device globals; no allocation) ----------------
__device__ __nv_bfloat16 g_xh[MTOT*DD], g_xl[MTOT*DD];
__device__ __nv_bfloat16 g_Wh[4*WELEM], g_Wl[4*WELEM];     // Wq,Wk,Wv,Wo
__device__ __nv_bfloat16 g_Qh[BB*HH*NN*DA], g_Ql[BB*HH*NN*DA];
__device__ __nv_bfloat16 g_Kh[BB*HH*NN*DA], g_Kl[BB*HH*NN*DA];
__device__ __nv_bfloat16 g_Vh[BB*HH*NN*HD], g_Vl[BB*HH*NN*HD];
__device__ __nv_bfloat16 g_atth[MTOT*DD], g_attl[MTOT*DD];

// ======================= helpers =======================
__device__ __forceinline__ uint32_t smem_u32(const void* p){
    uint32_t a;
    asm("{ .reg .u64 t; cvta.to.shared.u64 t, %1; cvt.u32.u64 %0, t; }" : "=r"(a) : "l"(p));
    return a;
}
__device__ __forceinline__ void ldsm_x4(uint32_t addr, uint32_t r[4]){
    asm volatile("ldmatrix.sync.aligned.m8n8.x4.shared.b16 {%0,%1,%2,%3}, [%4];"
        : "=r"(r[0]), "=r"(r[1]), "=r"(r[2]), "=r"(r[3]) : "r"(addr));
}
__device__ __forceinline__ void ldsm_x4t(uint32_t addr, uint32_t r[4]){
    asm volatile("ldmatrix.sync.aligned.m8n8.x4.trans.shared.b16 {%0,%1,%2,%3}, [%4];"
        : "=r"(r[0]), "=r"(r[1]), "=r"(r[2]), "=r"(r[3]) : "r"(addr));
}
__device__ __forceinline__ void mma16816(float c[4], const uint32_t a[4], const uint32_t b[2]){
    asm volatile("mma.sync.aligned.m16n8k16.row.col.f32.bf16.bf16.f32 "
        "{%0,%1,%2,%3}, {%4,%5,%6,%7}, {%8,%9}, {%0,%1,%2,%3};"
        : "+f"(c[0]), "+f"(c[1]), "+f"(c[2]), "+f"(c[3])
        : "r"(a[0]), "r"(a[1]), "r"(a[2]), "r"(a[3]), "r"(b[0]), "r"(b[1]));
}
__device__ __forceinline__ uint32_t b2u(__nv_bfloat162 v){ return *reinterpret_cast<uint32_t*>(&v); }
__device__ __forceinline__ void cp16(uint32_t dst, const void* src){
    asm volatile("cp.async.cg.shared.global [%0], [%1], 16;" :: "r"(dst), "l"(src));
}
#define CP_COMMIT asm volatile("cp.async.commit_group;" ::: "memory")
#define CP_WAIT1  asm volatile("cp.async.wait_group 1;" ::: "memory")
#define CP_WAIT0  asm volatile("cp.async.wait_group 0;" ::: "memory")

__device__ __forceinline__ float ex2(float x){
    float r; asm("ex2.approx.ftz.f32 %0, %1;" : "=f"(r) : "f"(x)); return r;
}
__device__ __forceinline__ void pack2(float vx, float vy, uint32_t& hi, uint32_t& lo){
    __nv_bfloat162 h = __floats2bfloat162_rn(vx, vy);
    __nv_bfloat162 l = __floats2bfloat162_rn(vx - __low2float(h), vy - __high2float(h));
    hi = b2u(h); lo = b2u(l);
}

// ================= fp32 -> bf16 hi/lo conversion =================
#define XC ((MTOT*DD)/4)
#define WC (WELEM/4)
__global__ void convert_kernel(const float* __restrict__ x,
                               const float* __restrict__ Wq, const float* __restrict__ Wk,
                               const float* __restrict__ Wv, const float* __restrict__ Wo)
{
    int i = blockIdx.x * blockDim.x + threadIdx.x;
    const float* src;
    __nv_bfloat16 *dh, *dl;
    int off;
    if (i < XC) { src = x; dh = g_xh; dl = g_xl; off = i; }
    else {
        int j = i - XC;
        int w = j >> 16;
        off   = j & (WC - 1);
        src = (w == 0) ? Wq : (w == 1) ? Wk : (w == 2) ? Wv : Wo;
        dh = g_Wh + (size_t)w * WELEM;
        dl = g_Wl + (size_t)w * WELEM;
    }
    float4 v = ((const float4*)src)[off];
    uint2 uh, ul;
    pack2(v.x, v.y, uh.x, ul.x);
    pack2(v.z, v.w, uh.y, ul.y);
    *(uint2*)&dh[4*(size_t)off] = uh;
    *(uint2*)&dl[4*(size_t)off] = ul;
}

// ================= GEMM staging (2 stages x 40960 B) =================
#define AS 40
#define GB_AH 0
#define GB_AL 10240
#define GB_WH 20480
#define GB_WL 30720
#define STG   40960
#define GEMM_SMEM (2*STG)

__device__ __forceinline__ void gemm_stage(
    uint32_t sb, int stage, int t, int m0, int o0, int k0,
    const __nv_bfloat16* Ahg, const __nv_bfloat16* Alg,
    const __nv_bfloat16* Whg, const __nv_bfloat16* Wlg)
{
    uint32_t sa = sb + (uint32_t)stage * STG;
#pragma unroll
    for (int i = 0; i < 2; i++) {
        int c   = t + i * 256;
        int row = c >> 2;
        int ce  = (c & 3) << 3;
        uint32_t so = (uint32_t)(row * AS + ce) * 2u;
        cp16(sa + GB_AH + so, Ahg + (size_t)(m0 + row) * DD + k0 + ce);
        cp16(sa + GB_AL + so, Alg + (size_t)(m0 + row) * DD + k0 + ce);
        cp16(sa + GB_WH + so, Whg + (size_t)(o0 + row) * DD + k0 + ce);
        cp16(sa + GB_WL + so, Wlg + (size_t)(o0 + row) * DD + k0 + ce);
    }
    CP_COMMIT;
}

__device__ __forceinline__ void gemm_compute(
    uint32_t sb, int stage, float Cs[4][4][4],
    int wm, int wn, int a_r, int a_c8, int b_r, int b_c8, int b_r16)
{
    uint32_t sa = sb + (uint32_t)stage * STG;
#pragma unroll
    for (int ks = 0; ks < 2; ks++) {
        uint32_t Ah[4][4], Al[4][4], WH[2][4], WL[2][4];
#pragma unroll
        for (int mb = 0; mb < 4; mb++) {
            uint32_t ad = sa + (uint32_t)(((wm*64 + mb*16 + a_r) * AS + ks*16 + a_c8) * 2);
            ldsm_x4(ad + GB_AH, Ah[mb]);
            ldsm_x4(ad + GB_AL, Al[mb]);
        }
#pragma unroll
        for (int j = 0; j < 2; j++) {
            uint32_t wd = sa + (uint32_t)(((wn*32 + j*16 + b_r + b_r16) * AS + ks*16 + b_c8) * 2);
            ldsm_x4(wd + GB_WH, WH[j]);
            ldsm_x4(wd + GB_WL, WL[j]);
        }
#pragma unroll
        for (int mb = 0; mb < 4; mb++)
#pragma unroll
            for (int nb = 0; nb < 4; nb++) {
                const uint32_t* bh = &WH[nb>>1][(nb&1)*2];
                const uint32_t* bl = &WL[nb>>1][(nb&1)*2];
                mma16816(Cs[mb][nb], Ah[mb], bh);
                mma16816(Cs[mb][nb], Ah[mb], bl);
                mma16816(Cs[mb][nb], Al[mb], bh);
            }
    }
}

// ================= fused QKV projection =================
__global__ __launch_bounds__(256, 2) void qkv_mma_kernel(
    const float* __restrict__ bq, const float* __restrict__ bk, const float* __restrict__ bv)
{
    extern __shared__ char smem[];
    uint32_t sb = smem_u32(smem);
    const int t    = threadIdx.x;
    const int lane = t & 31;
    const int w    = t >> 5;
    const int wm   = w >> 2;
    const int wn   = w & 3;
    const int m0   = blockIdx.y * 128;
    const int o0   = blockIdx.x * 128;
    const int z    = blockIdx.z;

    const __nv_bfloat16* Whg = g_Wh + (size_t)z * WELEM;
    const __nv_bfloat16* Wlg = g_Wl + (size_t)z * WELEM;
    const float* bias = (z == 0) ? bq : (z == 1) ? bk : bv;
    __nv_bfloat16* dh = (z == 0) ? g_Qh : (z == 1) ? g_Kh : g_Vh;
    __nv_bfloat16* dl = (z == 0) ? g_Ql : (z == 1) ? g_Kl : g_Vl;
    const float scale = (z == 0) ? 0.125f * LOG2E : 1.0f;
    const int   ld    = (z == 2) ? HD : DA;

    float Cs[4][4][4];
#pragma unroll
    for (int mb = 0; mb < 4; mb++)
#pragma unroll
        for (int nb = 0; nb < 4; nb++)
#pragma unroll
            for (int i = 0; i < 4; i++) Cs[mb][nb][i] = 0.f;

    const int a_r   = (lane & 7) + ((lane & 8) ? 8 : 0);
    const int a_c8  = (lane & 16) ? 8 : 0;
    const int b_r   = lane & 7;
    const int b_c8  = (lane & 8) ? 8 : 0;
    const int b_r16 = (lane & 16) ? 8 : 0;

    gemm_stage(sb, 0, t, m0, o0, 0, g_xh, g_xl, Whg, Wlg);
    for (int kk = 0; kk < 16; kk++) {
        if (kk + 1 < 16) {
            gemm_stage(sb, (kk+1)&1, t, m0, o0, (kk+1)*32, g_xh, g_xl, Whg, Wlg);
            CP_WAIT1;
        } else {
            CP_WAIT0;
        }
        __syncthreads();
        gemm_compute(sb, kk & 1, Cs, wm, wn, a_r, a_c8, b_r, b_c8, b_r16);
        __syncthreads();
    }

    const int r0l = lane >> 2;
    const int c0l = (lane & 3) * 2;
#pragma unroll
    for (int mb = 0; mb < 4; mb++) {
#pragma unroll
        for (int nb = 0; nb < 4; nb++) {
            int gc = o0 + wn*32 + nb*8 + c0l;
            float2 bbv = *(const float2*)&bias[gc];
            int h  = gc >> 6;
            int hd = gc & 63;
#pragma unroll
            for (int half = 0; half < 2; half++) {
                int gr = m0 + wm*64 + mb*16 + r0l + half*8;
                float vx = (Cs[mb][nb][half*2+0] + bbv.x) * scale;
                float vy = (Cs[mb][nb][half*2+1] + bbv.y) * scale;
                uint32_t hi, lo;
                pack2(vx, vy, hi, lo);
                int b  = gr >> 11;
                int n  = gr & 2047;
                size_t off = ((size_t)((b*HH + h) * NN + n)) * ld + hd;
                *(uint32_t*)&dh[off] = hi;
                *(uint32_t*)&dl[off] = lo;
            }
        }
    }
}

// ================= output projection =================
__global__ __launch_bounds__(256, 2) void oproj_mma_kernel(
    const float* __restrict__ bias, float* __restrict__ out)
{
    extern __shared__ char smem[];
    uint32_t sb = smem_u32(smem);
    const int t    = threadIdx.x;
    const int lane = t & 31;
    const int w    = t >> 5;
    const int wm   = w >> 2;
    const int wn   = w & 3;
    const int m0   = blockIdx.y * 128;
    const int o0   = blockIdx.x * 128;

    const __nv_bfloat16* Whg = g_Wh + (size_t)3 * WELEM;
    const __nv_bfloat16* Wlg = g_Wl + (size_t)3 * WELEM;

    float Cs[4][4][4];
#pragma unroll
    for (int mb = 0; mb < 4; mb++)
#pragma unroll
        for (int nb = 0; nb < 4; nb++)
#pragma unroll
            for (int i = 0; i < 4; i++) Cs[mb][nb][i] = 0.f;

    const int a_r   = (lane & 7) + ((lane & 8) ? 8 : 0);
    const int a_c8  = (lane & 16) ? 8 : 0;
    const int b_r   = lane & 7;
    const int b_c8  = (lane & 8) ? 8 : 0;
    const int b_r16 = (lane & 16) ? 8 : 0;

    gemm_stage(sb, 0, t, m0, o0, 0, g_atth, g_attl, Whg, Wlg);
    for (int kk = 0; kk < 16; kk++) {
        if (kk + 1 < 16) {
            gemm_stage(sb, (kk+1)&1, t, m0, o0, (kk+1)*32, g_atth, g_attl, Whg, Wlg);
            CP_WAIT1;
        } else {
            CP_WAIT0;
        }
        __syncthreads();
        gemm_compute(sb, kk & 1, Cs, wm, wn, a_r, a_c8, b_r, b_c8, b_r16);
        __syncthreads();
    }

    const int r0l = lane >> 2;
    const int c0l = (lane & 3) * 2;
#pragma unroll
    for (int mb = 0; mb < 4; mb++) {
#pragma unroll
        for (int nb = 0; nb < 4; nb++) {
            int gc = o0 + wn*32 + nb*8 + c0l;
            float2 bbv = *(const float2*)&bias[gc];
#pragma unroll
            for (int half = 0; half < 2; half++) {
                int gr = m0 + wm*64 + mb*16 + r0l + half*8;
                float2 v;
                v.x = Cs[mb][nb][half*2+0] + bbv.x;
                v.y = Cs[mb][nb][half*2+1] + bbv.y;
                *(float2*)&out[(size_t)gr * DD + gc] = v;
            }
        }
    }
}

// ---------------- phase augmentation fill ----------------
__device__ __forceinline__ void pack8(const float* v, uint4& hi, uint4& lo){
    uint32_t h[4], l[4];
#pragma unroll
    for (int i = 0; i < 4; i++) pack2(v[2*i], v[2*i+1], h[i], l[i]);
    hi.x = h[0]; hi.y = h[1]; hi.z = h[2]; hi.w = h[3];
    lo.x = l[0]; lo.y = l[1]; lo.z = l[2]; lo.w = l[3];
}

__global__ void phase_fill_kernel(const float* __restrict__ pc,
                                  const float* __restrict__ pb)
{
    int tid = blockIdx.x * blockDim.x + threadIdx.x;
    if (tid >= BB * NN * HH) return;
    int h  = tid >> 12;
    int bn = tid & 4095;

    float c[FF], s[FF], wc[FF], ws[FF];
#pragma unroll
    for (int f = 0; f < FF; f++)
        __sincosf(pc[(size_t)bn * FF + f], &s[f], &c[f]);
#pragma unroll
    for (int f = 0; f < FF; f++) {
        float wv = pb[h*FF + f] * LOG2E;
        wc[f] = wv * c[f];
        ws[f] = wv * s[f];
    }

    int b = bn >> 11, n = bn & 2047;
    size_t base = ((size_t)((b*HH + h) * NN + n)) * DA + 64;

    uint4 hi, lo;
    pack8(c,  hi, lo); *(uint4*)&g_Kh[base]   = hi; *(uint4*)&g_Kl[base]   = lo;
    pack8(s,  hi, lo); *(uint4*)&g_Kh[base+8] = hi; *(uint4*)&g_Kl[base+8] = lo;
    pack8(wc, hi, lo); *(uint4*)&g_Qh[base]   = hi; *(uint4*)&g_Ql[base]   = lo;
    pack8(ws, hi, lo); *(uint4*)&g_Qh[base+8] = hi; *(uint4*)&g_Ql[base+8] = lo;
}

// =============== BQ=128 x BK=128 bf16x3 warp-MMA flash attention ===============
// smem: K ring 2 stages of 128 rows, V ring 2 stages of 128 rows
#define QS 88
#define VS 72
#define K_L   (128*QS*2)          // 22528
#define KSTG  (2*K_L)             // 45056
#define VBASE (2*KSTG)            // 90112
#define V_L   (128*VS*2)          // 18432
#define VSTG  (2*V_L)             // 36864
#define ATTN_SMEM (VBASE + 2*VSTG)  // 163840

__global__ __launch_bounds__(256, 1) void attn_mma_kernel()
{
    extern __shared__ char smem[];
    uint32_t sb = smem_u32(smem);
    const int t    = threadIdx.x;
    const int lane = t & 31;
    const int w    = t >> 5;          // 0..7, warp owns q rows w*16..w*16+15
    const int q0   = blockIdx.x * BQ;
    const int bh   = blockIdx.y;

    const __nv_bfloat16* Qgh = g_Qh + (size_t)bh * NN * DA + (size_t)q0 * DA;
    const __nv_bfloat16* Qgl = g_Ql + (size_t)bh * NN * DA + (size_t)q0 * DA;
    const __nv_bfloat16* Kgh = g_Kh + (size_t)bh * NN * DA;
    const __nv_bfloat16* Kgl = g_Kl + (size_t)bh * NN * DA;
    const __nv_bfloat16* Vgh = g_Vh + (size_t)bh * NN * HD;
    const __nv_bfloat16* Vgl = g_Vl + (size_t)bh * NN * HD;

    auto prefetch = [&](int kt){
        uint32_t ka = sb + (uint32_t)(kt & 1) * KSTG;
        uint32_t va = sb + VBASE + (uint32_t)(kt & 1) * VSTG;
        int k0 = kt * BK;
#pragma unroll
        for (int i = 0; i < 5; i++) {
            int idx = t + i * 256;      // 0..1279 (128 rows x 10 chunks)
            int row = idx / 10;
            int c8  = (idx % 10) * 8;
            uint32_t so = (uint32_t)(row * QS + c8) * 2u;
            const size_t g = (size_t)(k0 + row) * DA + c8;
            cp16(ka + so, Kgh + g);
            cp16(ka + K_L + so, Kgl + g);
        }
#pragma unroll
        for (int i = 0; i < 4; i++) {
            int idx = t + i * 256;      // 0..1023 (128 rows x 8 chunks)
            int row = idx >> 3;
            int c8  = (idx & 7) * 8;
            uint32_t so = (uint32_t)(row * VS + c8) * 2u;
            const size_t g = (size_t)(k0 + row) * HD + c8;
            cp16(va + so, Vgh + g);
            cp16(va + V_L + so, Vgl + g);
        }
        CP_COMMIT;
    };

    // prefetch pair 0 into stage 0; stage Q (128 x 80 hi/lo) into K stage 1 area
    prefetch(0);
    {
        uint32_t qh_off = KSTG;
        uint32_t ql_off = KSTG + K_L;
#pragma unroll
        for (int i = 0; i < 5; i++) {
            int idx = t + i * 256;
            int row = idx / 10;
            int c8  = (idx % 10) * 8;
            uint32_t soff = (uint32_t)(row * QS + c8) * 2u;
            *(uint4*)(smem + qh_off + soff) = *(const uint4*)(Qgh + (size_t)row * DA + c8);
            *(uint4*)(smem + ql_off + soff) = *(const uint4*)(Qgl + (size_t)row * DA + c8);
        }
    }
    __syncthreads();

    const int a_r   = (lane & 7) + ((lane & 8) ? 8 : 0);
    const int a_c8  = (lane & 16) ? 8 : 0;
    const int b_r   = lane & 7;
    const int b_c8  = (lane & 8) ? 8 : 0;
    const int b_r16 = (lane & 16) ? 8 : 0;
    const int v_r8  = (lane & 8) ? 8 : 0;

    uint32_t Qfh[5][4], Qfl[5][4];
#pragma unroll
    for (int s = 0; s < 5; s++) {
        uint32_t ad = sb + KSTG + (uint32_t)(((w*16 + a_r) * QS + s*16 + a_c8) * 2);
        ldsm_x4(ad, Qfh[s]);
        ldsm_x4(ad + K_L, Qfl[s]);
    }
    __syncthreads();   // Q area free before prefetch(1) overwrites stage 1

    float mrow[2] = {-1e30f, -1e30f};
    float lrow[2] = {0.f, 0.f};
    float Od[8][4];
#pragma unroll
    for (int db = 0; db < 8; db++)
#pragma unroll
        for (int i = 0; i < 4; i++) Od[db][i] = 0.f;

#pragma unroll 1
    for (int kt = 0; kt < NT2; kt++) {
        if (kt + 1 < NT2) {
            prefetch(kt + 1);
            CP_WAIT1;
        } else {
            CP_WAIT0;
        }
        __syncthreads();
        uint32_t ka = sb + (uint32_t)(kt & 1) * KSTG;
        uint32_t va = sb + VBASE + (uint32_t)(kt & 1) * VSTG;

        // ---- S = Q . K^T over 128 keys (16 n-blocks, bf16x3) ----
        float Cs[16][4];
#pragma unroll
        for (int nb = 0; nb < 16; nb++)
#pragma unroll
            for (int i = 0; i < 4; i++) Cs[nb][i] = 0.f;

#pragma unroll
        for (int s = 0; s < 5; s++) {
#pragma unroll
            for (int j = 0; j < 8; j++) {
                uint32_t kd = ka + (uint32_t)(((j*16 + b_r + b_r16) * QS + s*16 + b_c8) * 2);
                uint32_t h4[4], l4[4];
                ldsm_x4(kd, h4);
                ldsm_x4(kd + K_L, l4);
                mma16816(Cs[2*j],   Qfh[s], h4+0);
                mma16816(Cs[2*j],   Qfh[s], l4+0);
                mma16816(Cs[2*j],   Qfl[s], h4+0);
                mma16816(Cs[2*j+1], Qfh[s], h4+2);
                mma16816(Cs[2*j+1], Qfh[s], l4+2);
                mma16816(Cs[2*j+1], Qfl[s], h4+2);
            }
        }

        // ---- joint max over all 128 keys ----
        float mx0 = -1e30f, mx1 = -1e30f;
#pragma unroll
        for (int nb = 0; nb < 16; nb++) {
            mx0 = fmaxf(mx0, fmaxf(Cs[nb][0], Cs[nb][1]));
            mx1 = fmaxf(mx1, fmaxf(Cs[nb][2], Cs[nb][3]));
        }
        mx0 = fmaxf(mx0, __shfl_xor_sync(0xffffffffu, mx0, 1));
        mx0 = fmaxf(mx0, __shfl_xor_sync(0xffffffffu, mx0, 2));
        mx1 = fmaxf(mx1, __shfl_xor_sync(0xffffffffu, mx1, 1));
        mx1 = fmaxf(mx1, __shfl_xor_sync(0xffffffffu, mx1, 2));
        float mn0 = fmaxf(mrow[0], mx0);
        float mn1 = fmaxf(mrow[1], mx1);
        float f0  = ex2(mrow[0] - mn0);
        float f1  = ex2(mrow[1] - mn1);
        mrow[0] = mn0; mrow[1] = mn1;

        // rescale O once per 128 keys
#pragma unroll
        for (int db = 0; db < 8; db++) {
            Od[db][0] *= f0; Od[db][1] *= f0;
            Od[db][2] *= f1; Od[db][3] *= f1;
        }

        float s0 = 0.f, s1 = 0.f;
        // ---- two 64-key halves: softmax(h) then PV(h); PV(A) drains under softmax(B) ----
#pragma unroll
        for (int h = 0; h < 2; h++) {
            uint32_t Ph[4][4], Pl[4][4];
#pragma unroll
            for (int ks = 0; ks < 4; ks++) {
#pragma unroll
                for (int hf = 0; hf < 2; hf++) {
                    int nb = h*8 + 2*ks + hf;
                    float p0 = ex2(Cs[nb][0] - mn0);
                    float p1 = ex2(Cs[nb][1] - mn0);
                    float p2 = ex2(Cs[nb][2] - mn1);
                    float p3 = ex2(Cs[nb][3] - mn1);
                    s0 += p0 + p1;
                    s1 += p2 + p3;
                    pack2(p0, p1, Ph[ks][hf*2+0], Pl[ks][hf*2+0]);
                    pack2(p2, p3, Ph[ks][hf*2+1], Pl[ks][hf*2+1]);
                }
            }
#pragma unroll
            for (int ks = 0; ks < 4; ks++) {
#pragma unroll
                for (int j = 0; j < 4; j++) {
                    uint32_t vd = va + (uint32_t)(((h*64 + ks*16 + b_r + v_r8) * VS + j*16 + b_r16) * 2);
                    uint32_t h4[4], l4[4];
                    ldsm_x4t(vd, h4);
                    ldsm_x4t(vd + V_L, l4);
                    mma16816(Od[2*j],   Ph[ks], h4+0);
                    mma16816(Od[2*j],   Ph[ks], l4+0);
                    mma16816(Od[2*j],   Pl[ks], h4+0);
                    mma16816(Od[2*j+1], Ph[ks], h4+2);
                    mma16816(Od[2*j+1], Ph[ks], l4+2);
                    mma16816(Od[2*j+1], Pl[ks], h4+2);
                }
            }
        }

        // deferred l update (shuffles hide under PV drain)
        s0 += __shfl_xor_sync(0xffffffffu, s0, 1);
        s0 += __shfl_xor_sync(0xffffffffu, s0, 2);
        s1 += __shfl_xor_sync(0xffffffffu, s1, 1);
        s1 += __shfl_xor_sync(0xffffffffu, s1, 2);
        lrow[0] = lrow[0] * f0 + s0;
        lrow[1] = lrow[1] * f1 + s1;
        __syncthreads();
    }

    // ---- epilogue: write att as bf16 hi/lo ----
    float i0 = 1.0f / lrow[0];
    float i1 = 1.0f / lrow[1];
    int b = bh >> 3, h = bh & 7;
    int r0l = w*16 + (lane >> 2);
    int c0l = (lane & 3) * 2;
#pragma unroll
    for (int db = 0; db < 8; db++) {
        int gc = h*64 + db*8 + c0l;
        uint32_t hi0, lo0, hi1, lo1;
        pack2(Od[db][0] * i0, Od[db][1] * i0, hi0, lo0);
        pack2(Od[db][2] * i1, Od[db][3] * i1, hi1, lo1);
        size_t o0r = ((size_t)(b*NN + q0 + r0l)) * DD + gc;
        size_t o1r = ((size_t)(b*NN + q0 + r0l + 8)) * DD + gc;
        *(uint32_t*)&g_atth[o0r] = hi0;
        *(uint32_t*)&g_attl[o0r] = lo0;
        *(uint32_t*)&g_atth[o1r] = hi1;
        *(uint32_t*)&g_attl[o1r] = lo1;
    }
}

// ---------------- launch ----------------
extern "C" void kernel_launch(void* const* d_in, const int* in_sizes, int n_in,
                              void* d_out, int out_size)
{
    const float* x   = (const float*)d_in[0];
    const float* pc  = (const float*)d_in[1];
    const float* Wq  = (const float*)d_in[2];
    const float* bq  = (const float*)d_in[3];
    const float* Wk  = (const float*)d_in[4];
    const float* bk  = (const float*)d_in[5];
    const float* Wv  = (const float*)d_in[6];
    const float* bv  = (const float*)d_in[7];
    const float* Wo  = (const float*)d_in[8];
    const float* bo  = (const float*)d_in[9];
    const float* pb  = (const float*)d_in[10];
    float* out = (float*)d_out;

    cudaFuncSetAttribute(attn_mma_kernel,  cudaFuncAttributeMaxDynamicSharedMemorySize, ATTN_SMEM);
    cudaFuncSetAttribute(qkv_mma_kernel,   cudaFuncAttributeMaxDynamicSharedMemorySize, GEMM_SMEM);
    cudaFuncSetAttribute(oproj_mma_kernel, cudaFuncAttributeMaxDynamicSharedMemorySize, GEMM_SMEM);

    int totc = XC + 4*WC;
    convert_kernel<<<(totc + 255)/256, 256>>>(x, Wq, Wk, Wv, Wo);

    dim3 qgrid(4, 32, 3);
    qkv_mma_kernel<<<qgrid, 256, GEMM_SMEM>>>(bq, bk, bv);

    phase_fill_kernel<<<(BB*NN*HH + 255)/256, 256>>>(pc, pb);

    dim3 agrid(NN/BQ, BB*HH);   // (16, 16)
    attn_mma_kernel<<<agrid, 256, ATTN_SMEM>>>();

    dim3 ggrid(4, 32);
    oproj_mma_kernel<<<ggrid, 256, GEMM_SMEM>>>(bo, out);
}

// round 10
// speedup vs baseline: 4.2979x; 1.1166x over previous
#include <cuda_runtime.h>
#include <cuda_bf16.h>
#include <cuda_fp16.h>
#include <cstdint>
#include <math.h>

// Problem constants
#define BB 2
#define NN 2048
#define DD 512
#define HH 8
#define FF 8
#define HD 64
#define DA 80   // augmented head dim: 64 (Q/K) + 8 (cos) + 8 (sin)
#define BQ 128  // q rows per CTA (attention)
#define BK 128  // keys per mainloop iteration
#define NT2 (NN/BK)   // 16 iterations

#define MTOT (BB*NN)          // 4096
#define WELEM (DD*DD)         // 262144
#define LOG2E 1.4426950408889634f

// ---------------- scratch (device globals; no allocation) ----------------
__device__ __nv_bfloat16 g_xh[MTOT*DD], g_xl[MTOT*DD];
__device__ __nv_bfloat16 g_Wh[3*WELEM], g_Wl[3*WELEM];     // Wq,Wk,Wv (bf16 x3 path)
__device__ __half g_Woh[WELEM], g_Wol[WELEM];              // Wo (fp16 x2 path)
__device__ __half g_Qh[BB*HH*NN*DA], g_Ql[BB*HH*NN*DA];
__device__ __half g_Kh[BB*HH*NN*DA], g_Kl[BB*HH*NN*DA];
__device__ __half g_Vh[BB*HH*NN*HD], g_Vl[BB*HH*NN*HD];
__device__ __half g_att[MTOT*DD];                          // attended, fp16 single

// ======================= helpers =======================
__device__ __forceinline__ uint32_t smem_u32(const void* p){
    uint32_t a;
    asm("{ .reg .u64 t; cvta.to.shared.u64 t, %1; cvt.u32.u64 %0, t; }" : "=r"(a) : "l"(p));
    return a;
}
__device__ __forceinline__ void ldsm_x4(uint32_t addr, uint32_t r[4]){
    asm volatile("ldmatrix.sync.aligned.m8n8.x4.shared.b16 {%0,%1,%2,%3}, [%4];"
        : "=r"(r[0]), "=r"(r[1]), "=r"(r[2]), "=r"(r[3]) : "r"(addr));
}
__device__ __forceinline__ void ldsm_x4t(uint32_t addr, uint32_t r[4]){
    asm volatile("ldmatrix.sync.aligned.m8n8.x4.trans.shared.b16 {%0,%1,%2,%3}, [%4];"
        : "=r"(r[0]), "=r"(r[1]), "=r"(r[2]), "=r"(r[3]) : "r"(addr));
}
// bf16 MMA
__device__ __forceinline__ void mma16816(float c[4], const uint32_t a[4], const uint32_t b[2]){
    asm volatile("mma.sync.aligned.m16n8k16.row.col.f32.bf16.bf16.f32 "
        "{%0,%1,%2,%3}, {%4,%5,%6,%7}, {%8,%9}, {%0,%1,%2,%3};"
        : "+f"(c[0]), "+f"(c[1]), "+f"(c[2]), "+f"(c[3])
        : "r"(a[0]), "r"(a[1]), "r"(a[2]), "r"(a[3]), "r"(b[0]), "r"(b[1]));
}
// fp16 MMA
__device__ __forceinline__ void mma16816h(float c[4], const uint32_t a[4], const uint32_t b[2]){
    asm volatile("mma.sync.aligned.m16n8k16.row.col.f32.f16.f16.f32 "
        "{%0,%1,%2,%3}, {%4,%5,%6,%7}, {%8,%9}, {%0,%1,%2,%3};"
        : "+f"(c[0]), "+f"(c[1]), "+f"(c[2]), "+f"(c[3])
        : "r"(a[0]), "r"(a[1]), "r"(a[2]), "r"(a[3]), "r"(b[0]), "r"(b[1]));
}
__device__ __forceinline__ uint32_t b2u(__nv_bfloat162 v){ return *reinterpret_cast<uint32_t*>(&v); }
__device__ __forceinline__ uint32_t h2u(__half2 v){ return *reinterpret_cast<uint32_t*>(&v); }
__device__ __forceinline__ void cp16(uint32_t dst, const void* src){
    asm volatile("cp.async.cg.shared.global [%0], [%1], 16;" :: "r"(dst), "l"(src));
}
#define CP_COMMIT asm volatile("cp.async.commit_group;" ::: "memory")
#define CP_WAIT1  asm volatile("cp.async.wait_group 1;" ::: "memory")
#define CP_WAIT0  asm volatile("cp.async.wait_group 0;" ::: "memory")

__device__ __forceinline__ float ex2(float x){
    float r; asm("ex2.approx.ftz.f32 %0, %1;" : "=f"(r) : "f"(x)); return r;
}
__device__ __forceinline__ void pack2(float vx, float vy, uint32_t& hi, uint32_t& lo){
    __nv_bfloat162 h = __floats2bfloat162_rn(vx, vy);
    __nv_bfloat162 l = __floats2bfloat162_rn(vx - __low2float(h), vy - __high2float(h));
    hi = b2u(h); lo = b2u(l);
}
__device__ __forceinline__ void pack2h(float vx, float vy, uint32_t& hi, uint32_t& lo){
    __half2 h = __floats2half2_rn(vx, vy);
    __half2 l = __floats2half2_rn(vx - __low2float(h), vy - __high2float(h));
    hi = h2u(h); lo = h2u(l);
}

// ================= fp32 -> bf16/fp16 hi/lo conversion =================
#define XC ((MTOT*DD)/4)
#define WC (WELEM/4)
__global__ void convert_kernel(const float* __restrict__ x,
                               const float* __restrict__ Wq, const float* __restrict__ Wk,
                               const float* __restrict__ Wv, const float* __restrict__ Wo)
{
    int i = blockIdx.x * blockDim.x + threadIdx.x;
    if (i < XC) {
        float4 v = ((const float4*)x)[i];
        uint2 uh, ul;
        pack2(v.x, v.y, uh.x, ul.x);
        pack2(v.z, v.w, uh.y, ul.y);
        *(uint2*)&g_xh[4*(size_t)i] = uh;
        *(uint2*)&g_xl[4*(size_t)i] = ul;
        return;
    }
    int j = i - XC;
    int w = j >> 16;          // / WC
    int off = j & (WC - 1);
    if (w < 3) {
        const float* src = (w == 0) ? Wq : (w == 1) ? Wk : Wv;
        float4 v = ((const float4*)src)[off];
        uint2 uh, ul;
        pack2(v.x, v.y, uh.x, ul.x);
        pack2(v.z, v.w, uh.y, ul.y);
        *(uint2*)&g_Wh[(size_t)w * WELEM + 4*(size_t)off] = uh;
        *(uint2*)&g_Wl[(size_t)w * WELEM + 4*(size_t)off] = ul;
    } else {
        float4 v = ((const float4*)Wo)[off];
        uint2 uh, ul;
        pack2h(v.x, v.y, uh.x, ul.x);
        pack2h(v.z, v.w, uh.y, ul.y);
        *(uint2*)&g_Woh[4*(size_t)off] = uh;
        *(uint2*)&g_Wol[4*(size_t)off] = ul;
    }
}

// ================= QKV GEMM staging (2 stages x 40960 B) =================
#define AS 40
#define GB_AH 0
#define GB_AL 10240
#define GB_WH 20480
#define GB_WL 30720
#define STG   40960
#define GEMM_SMEM (2*STG)

__device__ __forceinline__ void gemm_stage(
    uint32_t sb, int stage, int t, int m0, int o0, int k0,
    const __nv_bfloat16* Ahg, const __nv_bfloat16* Alg,
    const __nv_bfloat16* Whg, const __nv_bfloat16* Wlg)
{
    uint32_t sa = sb + (uint32_t)stage * STG;
#pragma unroll
    for (int i = 0; i < 2; i++) {
        int c   = t + i * 256;
        int row = c >> 2;
        int ce  = (c & 3) << 3;
        uint32_t so = (uint32_t)(row * AS + ce) * 2u;
        cp16(sa + GB_AH + so, Ahg + (size_t)(m0 + row) * DD + k0 + ce);
        cp16(sa + GB_AL + so, Alg + (size_t)(m0 + row) * DD + k0 + ce);
        cp16(sa + GB_WH + so, Whg + (size_t)(o0 + row) * DD + k0 + ce);
        cp16(sa + GB_WL + so, Wlg + (size_t)(o0 + row) * DD + k0 + ce);
    }
    CP_COMMIT;
}

__device__ __forceinline__ void gemm_compute(
    uint32_t sb, int stage, float Cs[4][4][4],
    int wm, int wn, int a_r, int a_c8, int b_r, int b_c8, int b_r16)
{
    uint32_t sa = sb + (uint32_t)stage * STG;
#pragma unroll
    for (int ks = 0; ks < 2; ks++) {
        uint32_t Ah[4][4], Al[4][4], WH[2][4], WL[2][4];
#pragma unroll
        for (int mb = 0; mb < 4; mb++) {
            uint32_t ad = sa + (uint32_t)(((wm*64 + mb*16 + a_r) * AS + ks*16 + a_c8) * 2);
            ldsm_x4(ad + GB_AH, Ah[mb]);
            ldsm_x4(ad + GB_AL, Al[mb]);
        }
#pragma unroll
        for (int j = 0; j < 2; j++) {
            uint32_t wd = sa + (uint32_t)(((wn*32 + j*16 + b_r + b_r16) * AS + ks*16 + b_c8) * 2);
            ldsm_x4(wd + GB_WH, WH[j]);
            ldsm_x4(wd + GB_WL, WL[j]);
        }
#pragma unroll
        for (int mb = 0; mb < 4; mb++)
#pragma unroll
            for (int nb = 0; nb < 4; nb++) {
                const uint32_t* bh = &WH[nb>>1][(nb&1)*2];
                const uint32_t* bl = &WL[nb>>1][(nb&1)*2];
                mma16816(Cs[mb][nb], Ah[mb], bh);
                mma16816(Cs[mb][nb], Ah[mb], bl);
                mma16816(Cs[mb][nb], Al[mb], bh);
            }
    }
}

// ================= fused QKV projection (bf16x3 in, fp16 hi/lo out) =================
__global__ __launch_bounds__(256, 2) void qkv_mma_kernel(
    const float* __restrict__ bq, const float* __restrict__ bk, const float* __restrict__ bv)
{
    extern __shared__ char smem[];
    uint32_t sb = smem_u32(smem);
    const int t    = threadIdx.x;
    const int lane = t & 31;
    const int w    = t >> 5;
    const int wm   = w >> 2;
    const int wn   = w & 3;
    const int m0   = blockIdx.y * 128;
    const int o0   = blockIdx.x * 128;
    const int z    = blockIdx.z;

    const __nv_bfloat16* Whg = g_Wh + (size_t)z * WELEM;
    const __nv_bfloat16* Wlg = g_Wl + (size_t)z * WELEM;
    const float* bias = (z == 0) ? bq : (z == 1) ? bk : bv;
    __half* dh = (z == 0) ? g_Qh : (z == 1) ? g_Kh : g_Vh;
    __half* dl = (z == 0) ? g_Ql : (z == 1) ? g_Kl : g_Vl;
    const float scale = (z == 0) ? 0.125f * LOG2E : 1.0f;
    const int   ld    = (z == 2) ? HD : DA;

    float Cs[4][4][4];
#pragma unroll
    for (int mb = 0; mb < 4; mb++)
#pragma unroll
        for (int nb = 0; nb < 4; nb++)
#pragma unroll
            for (int i = 0; i < 4; i++) Cs[mb][nb][i] = 0.f;

    const int a_r   = (lane & 7) + ((lane & 8) ? 8 : 0);
    const int a_c8  = (lane & 16) ? 8 : 0;
    const int b_r   = lane & 7;
    const int b_c8  = (lane & 8) ? 8 : 0;
    const int b_r16 = (lane & 16) ? 8 : 0;

    gemm_stage(sb, 0, t, m0, o0, 0, g_xh, g_xl, Whg, Wlg);
    for (int kk = 0; kk < 16; kk++) {
        if (kk + 1 < 16) {
            gemm_stage(sb, (kk+1)&1, t, m0, o0, (kk+1)*32, g_xh, g_xl, Whg, Wlg);
            CP_WAIT1;
        } else {
            CP_WAIT0;
        }
        __syncthreads();
        gemm_compute(sb, kk & 1, Cs, wm, wn, a_r, a_c8, b_r, b_c8, b_r16);
        __syncthreads();
    }

    const int r0l = lane >> 2;
    const int c0l = (lane & 3) * 2;
#pragma unroll
    for (int mb = 0; mb < 4; mb++) {
#pragma unroll
        for (int nb = 0; nb < 4; nb++) {
            int gc = o0 + wn*32 + nb*8 + c0l;
            float2 bbv = *(const float2*)&bias[gc];
            int h  = gc >> 6;
            int hd = gc & 63;
#pragma unroll
            for (int half = 0; half < 2; half++) {
                int gr = m0 + wm*64 + mb*16 + r0l + half*8;
                float vx = (Cs[mb][nb][half*2+0] + bbv.x) * scale;
                float vy = (Cs[mb][nb][half*2+1] + bbv.y) * scale;
                uint32_t hi, lo;
                pack2h(vx, vy, hi, lo);
                int b  = gr >> 11;
                int n  = gr & 2047;
                size_t off = ((size_t)((b*HH + h) * NN + n)) * ld + hd;
                *(uint32_t*)&dh[off] = hi;
                *(uint32_t*)&dl[off] = lo;
            }
        }
    }
}

// ================= output projection (fp16 single A x fp16x2 W) =================
#define OB_A  0
#define OB_WH 10240
#define OB_WL 20480
#define OSTG  30720
#define OPROJ_SMEM (2*OSTG)

__global__ __launch_bounds__(256, 2) void oproj_mma_kernel(
    const float* __restrict__ bias, float* __restrict__ out)
{
    extern __shared__ char smem[];
    uint32_t sb = smem_u32(smem);
    const int t    = threadIdx.x;
    const int lane = t & 31;
    const int w    = t >> 5;
    const int wm   = w >> 2;
    const int wn   = w & 3;
    const int m0   = blockIdx.y * 128;
    const int o0   = blockIdx.x * 128;

    float Cs[4][4][4];
#pragma unroll
    for (int mb = 0; mb < 4; mb++)
#pragma unroll
        for (int nb = 0; nb < 4; nb++)
#pragma unroll
            for (int i = 0; i < 4; i++) Cs[mb][nb][i] = 0.f;

    const int a_r   = (lane & 7) + ((lane & 8) ? 8 : 0);
    const int a_c8  = (lane & 16) ? 8 : 0;
    const int b_r   = lane & 7;
    const int b_c8  = (lane & 8) ? 8 : 0;
    const int b_r16 = (lane & 16) ? 8 : 0;

    auto stage = [&](int stg, int k0){
        uint32_t sa = sb + (uint32_t)stg * OSTG;
#pragma unroll
        for (int i = 0; i < 2; i++) {
            int c   = t + i * 256;
            int row = c >> 2;
            int ce  = (c & 3) << 3;
            uint32_t so = (uint32_t)(row * AS + ce) * 2u;
            cp16(sa + OB_A  + so, g_att + (size_t)(m0 + row) * DD + k0 + ce);
            cp16(sa + OB_WH + so, g_Woh + (size_t)(o0 + row) * DD + k0 + ce);
            cp16(sa + OB_WL + so, g_Wol + (size_t)(o0 + row) * DD + k0 + ce);
        }
        CP_COMMIT;
    };

    stage(0, 0);
    for (int kk = 0; kk < 16; kk++) {
        if (kk + 1 < 16) {
            stage((kk+1)&1, (kk+1)*32);
            CP_WAIT1;
        } else {
            CP_WAIT0;
        }
        __syncthreads();
        uint32_t sa = sb + (uint32_t)(kk & 1) * OSTG;
#pragma unroll
        for (int ks = 0; ks < 2; ks++) {
            uint32_t Ah[4][4], WH[2][4], WL[2][4];
#pragma unroll
            for (int mb = 0; mb < 4; mb++) {
                uint32_t ad = sa + OB_A + (uint32_t)(((wm*64 + mb*16 + a_r) * AS + ks*16 + a_c8) * 2);
                ldsm_x4(ad, Ah[mb]);
            }
#pragma unroll
            for (int j = 0; j < 2; j++) {
                uint32_t wd = sa + (uint32_t)(((wn*32 + j*16 + b_r + b_r16) * AS + ks*16 + b_c8) * 2);
                ldsm_x4(wd + OB_WH, WH[j]);
                ldsm_x4(wd + OB_WL, WL[j]);
            }
#pragma unroll
            for (int mb = 0; mb < 4; mb++)
#pragma unroll
                for (int nb = 0; nb < 4; nb++) {
                    const uint32_t* bh = &WH[nb>>1][(nb&1)*2];
                    const uint32_t* bl = &WL[nb>>1][(nb&1)*2];
                    mma16816h(Cs[mb][nb], Ah[mb], bh);
                    mma16816h(Cs[mb][nb], Ah[mb], bl);
                }
        }
        __syncthreads();
    }

    const int r0l = lane >> 2;
    const int c0l = (lane & 3) * 2;
#pragma unroll
    for (int mb = 0; mb < 4; mb++) {
#pragma unroll
        for (int nb = 0; nb < 4; nb++) {
            int gc = o0 + wn*32 + nb*8 + c0l;
            float2 bbv = *(const float2*)&bias[gc];
#pragma unroll
            for (int half = 0; half < 2; half++) {
                int gr = m0 + wm*64 + mb*16 + r0l + half*8;
                float2 v;
                v.x = Cs[mb][nb][half*2+0] + bbv.x;
                v.y = Cs[mb][nb][half*2+1] + bbv.y;
                *(float2*)&out[(size_t)gr * DD + gc] = v;
            }
        }
    }
}

// ---------------- phase augmentation fill (fp16 hi/lo) ----------------
__device__ __forceinline__ void pack8h(const float* v, uint4& hi, uint4& lo){
    uint32_t h[4], l[4];
#pragma unroll
    for (int i = 0; i < 4; i++) pack2h(v[2*i], v[2*i+1], h[i], l[i]);
    hi.x = h[0]; hi.y = h[1]; hi.z = h[2]; hi.w = h[3];
    lo.x = l[0]; lo.y = l[1]; lo.z = l[2]; lo.w = l[3];
}

__global__ void phase_fill_kernel(const float* __restrict__ pc,
                                  const float* __restrict__ pb)
{
    int tid = blockIdx.x * blockDim.x + threadIdx.x;
    if (tid >= BB * NN * HH) return;
    int h  = tid >> 12;
    int bn = tid & 4095;

    float c[FF], s[FF], wc[FF], ws[FF];
#pragma unroll
    for (int f = 0; f < FF; f++)
        __sincosf(pc[(size_t)bn * FF + f], &s[f], &c[f]);
#pragma unroll
    for (int f = 0; f < FF; f++) {
        float wv = pb[h*FF + f] * LOG2E;
        wc[f] = wv * c[f];
        ws[f] = wv * s[f];
    }

    int b = bn >> 11, n = bn & 2047;
    size_t base = ((size_t)((b*HH + h) * NN + n)) * DA + 64;

    uint4 hi, lo;
    pack8h(c,  hi, lo); *(uint4*)&g_Kh[base]   = hi; *(uint4*)&g_Kl[base]   = lo;
    pack8h(s,  hi, lo); *(uint4*)&g_Kh[base+8] = hi; *(uint4*)&g_Kl[base+8] = lo;
    pack8h(wc, hi, lo); *(uint4*)&g_Qh[base]   = hi; *(uint4*)&g_Ql[base]   = lo;
    pack8h(ws, hi, lo); *(uint4*)&g_Qh[base+8] = hi; *(uint4*)&g_Ql[base+8] = lo;
}

// =============== BQ=128 x BK=128 fp16 warp-MMA flash attention ===============
// QK: fp16x3.  PV: P fp16 single x V fp16 hi/lo (2 MMAs).
#define QS 88
#define VS 72
#define K_L   (128*QS*2)          // 22528
#define KSTG  (2*K_L)             // 45056
#define VBASE (2*KSTG)            // 90112
#define V_L   (128*VS*2)          // 18432
#define VSTG  (2*V_L)             // 36864
#define ATTN_SMEM (VBASE + 2*VSTG)  // 163840

__global__ __launch_bounds__(256, 1) void attn_mma_kernel()
{
    extern __shared__ char smem[];
    uint32_t sb = smem_u32(smem);
    const int t    = threadIdx.x;
    const int lane = t & 31;
    const int w    = t >> 5;
    const int q0   = blockIdx.x * BQ;
    const int bh   = blockIdx.y;

    const __half* Qgh = g_Qh + (size_t)bh * NN * DA + (size_t)q0 * DA;
    const __half* Qgl = g_Ql + (size_t)bh * NN * DA + (size_t)q0 * DA;
    const __half* Kgh = g_Kh + (size_t)bh * NN * DA;
    const __half* Kgl = g_Kl + (size_t)bh * NN * DA;
    const __half* Vgh = g_Vh + (size_t)bh * NN * HD;
    const __half* Vgl = g_Vl + (size_t)bh * NN * HD;

    auto prefetch = [&](int kt){
        uint32_t ka = sb + (uint32_t)(kt & 1) * KSTG;
        uint32_t va = sb + VBASE + (uint32_t)(kt & 1) * VSTG;
        int k0 = kt * BK;
#pragma unroll
        for (int i = 0; i < 5; i++) {
            int idx = t + i * 256;
            int row = idx / 10;
            int c8  = (idx % 10) * 8;
            uint32_t so = (uint32_t)(row * QS + c8) * 2u;
            const size_t g = (size_t)(k0 + row) * DA + c8;
            cp16(ka + so, Kgh + g);
            cp16(ka + K_L + so, Kgl + g);
        }
#pragma unroll
        for (int i = 0; i < 4; i++) {
            int idx = t + i * 256;
            int row = idx >> 3;
            int c8  = (idx & 7) * 8;
            uint32_t so = (uint32_t)(row * VS + c8) * 2u;
            const size_t g = (size_t)(k0 + row) * HD + c8;
            cp16(va + so, Vgh + g);
            cp16(va + V_L + so, Vgl + g);
        }
        CP_COMMIT;
    };

    prefetch(0);
    {
        uint32_t qh_off = KSTG;
        uint32_t ql_off = KSTG + K_L;
#pragma unroll
        for (int i = 0; i < 5; i++) {
            int idx = t + i * 256;
            int row = idx / 10;
            int c8  = (idx % 10) * 8;
            uint32_t soff = (uint32_t)(row * QS + c8) * 2u;
            *(uint4*)(smem + qh_off + soff) = *(const uint4*)(Qgh + (size_t)row * DA + c8);
            *(uint4*)(smem + ql_off + soff) = *(const uint4*)(Qgl + (size_t)row * DA + c8);
        }
    }
    __syncthreads();

    const int a_r   = (lane & 7) + ((lane & 8) ? 8 : 0);
    const int a_c8  = (lane & 16) ? 8 : 0;
    const int b_r   = lane & 7;
    const int b_c8  = (lane & 8) ? 8 : 0;
    const int b_r16 = (lane & 16) ? 8 : 0;
    const int v_r8  = (lane & 8) ? 8 : 0;

    uint32_t Qfh[5][4], Qfl[5][4];
#pragma unroll
    for (int s = 0; s < 5; s++) {
        uint32_t ad = sb + KSTG + (uint32_t)(((w*16 + a_r) * QS + s*16 + a_c8) * 2);
        ldsm_x4(ad, Qfh[s]);
        ldsm_x4(ad + K_L, Qfl[s]);
    }
    __syncthreads();

    float mrow[2] = {-1e30f, -1e30f};
    float lrow[2] = {0.f, 0.f};
    float Od[8][4];
#pragma unroll
    for (int db = 0; db < 8; db++)
#pragma unroll
        for (int i = 0; i < 4; i++) Od[db][i] = 0.f;

#pragma unroll 1
    for (int kt = 0; kt < NT2; kt++) {
        if (kt + 1 < NT2) {
            prefetch(kt + 1);
            CP_WAIT1;
        } else {
            CP_WAIT0;
        }
        __syncthreads();
        uint32_t ka = sb + (uint32_t)(kt & 1) * KSTG;
        uint32_t va = sb + VBASE + (uint32_t)(kt & 1) * VSTG;

        // ---- S = Q . K^T over 128 keys (fp16x3) ----
        float Cs[16][4];
#pragma unroll
        for (int nb = 0; nb < 16; nb++)
#pragma unroll
            for (int i = 0; i < 4; i++) Cs[nb][i] = 0.f;

#pragma unroll
        for (int s = 0; s < 5; s++) {
#pragma unroll
            for (int j = 0; j < 8; j++) {
                uint32_t kd = ka + (uint32_t)(((j*16 + b_r + b_r16) * QS + s*16 + b_c8) * 2);
                uint32_t h4[4], l4[4];
                ldsm_x4(kd, h4);
                ldsm_x4(kd + K_L, l4);
                mma16816h(Cs[2*j],   Qfh[s], h4+0);
                mma16816h(Cs[2*j],   Qfh[s], l4+0);
                mma16816h(Cs[2*j],   Qfl[s], h4+0);
                mma16816h(Cs[2*j+1], Qfh[s], h4+2);
                mma16816h(Cs[2*j+1], Qfh[s], l4+2);
                mma16816h(Cs[2*j+1], Qfl[s], h4+2);
            }
        }

        // ---- joint max over all 128 keys ----
        float mx0 = -1e30f, mx1 = -1e30f;
#pragma unroll
        for (int nb = 0; nb < 16; nb++) {
            mx0 = fmaxf(mx0, fmaxf(Cs[nb][0], Cs[nb][1]));
            mx1 = fmaxf(mx1, fmaxf(Cs[nb][2], Cs[nb][3]));
        }
        mx0 = fmaxf(mx0, __shfl_xor_sync(0xffffffffu, mx0, 1));
        mx0 = fmaxf(mx0, __shfl_xor_sync(0xffffffffu, mx0, 2));
        mx1 = fmaxf(mx1, __shfl_xor_sync(0xffffffffu, mx1, 1));
        mx1 = fmaxf(mx1, __shfl_xor_sync(0xffffffffu, mx1, 2));
        float mn0 = fmaxf(mrow[0], mx0);
        float mn1 = fmaxf(mrow[1], mx1);
        float f0  = ex2(mrow[0] - mn0);
        float f1  = ex2(mrow[1] - mn1);
        mrow[0] = mn0; mrow[1] = mn1;

#pragma unroll
        for (int db = 0; db < 8; db++) {
            Od[db][0] *= f0; Od[db][1] *= f0;
            Od[db][2] *= f1; Od[db][3] *= f1;
        }

        float s0 = 0.f, s1 = 0.f;
        // ---- two 64-key halves: softmax(h) then PV(h) ----
#pragma unroll
        for (int h = 0; h < 2; h++) {
            uint32_t Ph[4][4];
#pragma unroll
            for (int ks = 0; ks < 4; ks++) {
#pragma unroll
                for (int hf = 0; hf < 2; hf++) {
                    int nb = h*8 + 2*ks + hf;
                    float p0 = ex2(Cs[nb][0] - mn0);
                    float p1 = ex2(Cs[nb][1] - mn0);
                    float p2 = ex2(Cs[nb][2] - mn1);
                    float p3 = ex2(Cs[nb][3] - mn1);
                    s0 += p0 + p1;
                    s1 += p2 + p3;
                    Ph[ks][hf*2+0] = h2u(__floats2half2_rn(p0, p1));
                    Ph[ks][hf*2+1] = h2u(__floats2half2_rn(p2, p3));
                }
            }
#pragma unroll
            for (int ks = 0; ks < 4; ks++) {
#pragma unroll
                for (int j = 0; j < 4; j++) {
                    uint32_t vd = va + (uint32_t)(((h*64 + ks*16 + b_r + v_r8) * VS + j*16 + b_r16) * 2);
                    uint32_t h4[4], l4[4];
                    ldsm_x4t(vd, h4);
                    ldsm_x4t(vd + V_L, l4);
                    mma16816h(Od[2*j],   Ph[ks], h4+0);
                    mma16816h(Od[2*j],   Ph[ks], l4+0);
                    mma16816h(Od[2*j+1], Ph[ks], h4+2);
                    mma16816h(Od[2*j+1], Ph[ks], l4+2);
                }
            }
        }

        s0 += __shfl_xor_sync(0xffffffffu, s0, 1);
        s0 += __shfl_xor_sync(0xffffffffu, s0, 2);
        s1 += __shfl_xor_sync(0xffffffffu, s1, 1);
        s1 += __shfl_xor_sync(0xffffffffu, s1, 2);
        lrow[0] = lrow[0] * f0 + s0;
        lrow[1] = lrow[1] * f1 + s1;
        __syncthreads();
    }

    // ---- epilogue: write att as fp16 single ----
    float i0 = 1.0f / lrow[0];
    float i1 = 1.0f / lrow[1];
    int b = bh >> 3, h = bh & 7;
    int r0l = w*16 + (lane >> 2);
    int c0l = (lane & 3) * 2;
#pragma unroll
    for (int db = 0; db < 8; db++) {
        int gc = h*64 + db*8 + c0l;
        uint32_t v0 = h2u(__floats2half2_rn(Od[db][0] * i0, Od[db][1] * i0));
        uint32_t v1 = h2u(__floats2half2_rn(Od[db][2] * i1, Od[db][3] * i1));
        size_t o0r = ((size_t)(b*NN + q0 + r0l)) * DD + gc;
        size_t o1r = ((size_t)(b*NN + q0 + r0l + 8)) * DD + gc;
        *(uint32_t*)&g_att[o0r] = v0;
        *(uint32_t*)&g_att[o1r] = v1;
    }
}

// ---------------- launch ----------------
extern "C" void kernel_launch(void* const* d_in, const int* in_sizes, int n_in,
                              void* d_out, int out_size)
{
    const float* x   = (const float*)d_in[0];
    const float* pc  = (const float*)d_in[1];
    const float* Wq  = (const float*)d_in[2];
    const float* bq  = (const float*)d_in[3];
    const float* Wk  = (const float*)d_in[4];
    const float* bk  = (const float*)d_in[5];
    const float* Wv  = (const float*)d_in[6];
    const float* bv  = (const float*)d_in[7];
    const float* Wo  = (const float*)d_in[8];
    const float* bo  = (const float*)d_in[9];
    const float* pb  = (const float*)d_in[10];
    float* out = (float*)d_out;

    cudaFuncSetAttribute(attn_mma_kernel,  cudaFuncAttributeMaxDynamicSharedMemorySize, ATTN_SMEM);
    cudaFuncSetAttribute(qkv_mma_kernel,   cudaFuncAttributeMaxDynamicSharedMemorySize, GEMM_SMEM);
    cudaFuncSetAttribute(oproj_mma_kernel, cudaFuncAttributeMaxDynamicSharedMemorySize, OPROJ_SMEM);

    int totc = XC + 4*WC;
    convert_kernel<<<(totc + 255)/256, 256>>>(x, Wq, Wk, Wv, Wo);

    dim3 qgrid(4, 32, 3);
    qkv_mma_kernel<<<qgrid, 256, GEMM_SMEM>>>(bq, bk, bv);

    phase_fill_kernel<<<(BB*NN*HH + 255)/256, 256>>>(pc, pb);

    dim3 agrid(NN/BQ, BB*HH);   // (16, 16)
    attn_mma_kernel<<<agrid, 256, ATTN_SMEM>>>();

    dim3 ggrid(4, 32);
    oproj_mma_kernel<<<ggrid, 256, OPROJ_SMEM>>>(bo, out);
}

// round 15
// speedup vs baseline: 4.8288x; 1.1235x over previous
#include <cuda_runtime.h>
#include <cuda_bf16.h>
#include <cuda_fp16.h>
#include <cstdint>
#include <math.h>

// Problem constants
#define BB 2
#define NN 2048
#define DD 512
#define HH 8
#define FF 8
#define HD 64
#define DA 80   // augmented head dim: 64 (Q/K) + 8 (cos) + 8 (sin)
#define BQ 128  // q rows per CTA (attention)
#define BK 128  // keys per mainloop iteration
#define NT2 (NN/BK)   // 16 iterations

#define MTOT (BB*NN)          // 4096
#define WELEM (DD*DD)         // 262144
#define LOG2E 1.4426950408889634f

// ---------------- scratch (device globals; no allocation) ----------------
__device__ __nv_bfloat16 g_xh[MTOT*DD], g_xl[MTOT*DD];
__device__ __nv_bfloat16 g_Wh[3*WELEM], g_Wl[3*WELEM];     // Wq,Wk,Wv (bf16 x3 path)
__device__ __half g_Woh[WELEM], g_Wol[WELEM];              // Wo (fp16 x2 path)
__device__ __half g_Qh[BB*HH*NN*DA], g_Ql[BB*HH*NN*DA];
__device__ __half g_Kh[BB*HH*NN*DA], g_Kl[BB*HH*NN*DA];
__device__ __half g_V [BB*HH*NN*HD];                       // V single fp16 (storage only)
__device__ __half g_att[MTOT*DD];                          // attended, fp16 single

// ======================= helpers =======================
__device__ __forceinline__ uint32_t smem_u32(const void* p){
    uint32_t a;
    asm("{ .reg .u64 t; cvta.to.shared.u64 t, %1; cvt.u32.u64 %0, t; }" : "=r"(a) : "l"(p));
    return a;
}
__device__ __forceinline__ void ldsm_x4(uint32_t addr, uint32_t r[4]){
    asm volatile("ldmatrix.sync.aligned.m8n8.x4.shared.b16 {%0,%1,%2,%3}, [%4];"
        : "=r"(r[0]), "=r"(r[1]), "=r"(r[2]), "=r"(r[3]) : "r"(addr));
}
__device__ __forceinline__ void ldsm_x4t(uint32_t addr, uint32_t r[4]){
    asm volatile("ldmatrix.sync.aligned.m8n8.x4.trans.shared.b16 {%0,%1,%2,%3}, [%4];"
        : "=r"(r[0]), "=r"(r[1]), "=r"(r[2]), "=r"(r[3]) : "r"(addr));
}
// bf16 MMA
__device__ __forceinline__ void mma16816(float c[4], const uint32_t a[4], const uint32_t b[2]){
    asm volatile("mma.sync.aligned.m16n8k16.row.col.f32.bf16.bf16.f32 "
        "{%0,%1,%2,%3}, {%4,%5,%6,%7}, {%8,%9}, {%0,%1,%2,%3};"
        : "+f"(c[0]), "+f"(c[1]), "+f"(c[2]), "+f"(c[3])
        : "r"(a[0]), "r"(a[1]), "r"(a[2]), "r"(a[3]), "r"(b[0]), "r"(b[1]));
}
// fp16 MMA
__device__ __forceinline__ void mma16816h(float c[4], const uint32_t a[4], const uint32_t b[2]){
    asm volatile("mma.sync.aligned.m16n8k16.row.col.f32.f16.f16.f32 "
        "{%0,%1,%2,%3}, {%4,%5,%6,%7}, {%8,%9}, {%0,%1,%2,%3};"
        : "+f"(c[0]), "+f"(c[1]), "+f"(c[2]), "+f"(c[3])
        : "r"(a[0]), "r"(a[1]), "r"(a[2]), "r"(a[3]), "r"(b[0]), "r"(b[1]));
}
__device__ __forceinline__ uint32_t b2u(__nv_bfloat162 v){ return *reinterpret_cast<uint32_t*>(&v); }
__device__ __forceinline__ uint32_t h2u(__half2 v){ return *reinterpret_cast<uint32_t*>(&v); }
__device__ __forceinline__ void cp16(uint32_t dst, const void* src){
    asm volatile("cp.async.cg.shared.global [%0], [%1], 16;" :: "r"(dst), "l"(src));
}
#define CP_COMMIT asm volatile("cp.async.commit_group;" ::: "memory")
#define CP_WAIT1  asm volatile("cp.async.wait_group 1;" ::: "memory")
#define CP_WAIT0  asm volatile("cp.async.wait_group 0;" ::: "memory")

__device__ __forceinline__ float ex2(float x){
    float r; asm("ex2.approx.ftz.f32 %0, %1;" : "=f"(r) : "f"(x)); return r;
}
__device__ __forceinline__ void pack2(float vx, float vy, uint32_t& hi, uint32_t& lo){
    __nv_bfloat162 h = __floats2bfloat162_rn(vx, vy);
    __nv_bfloat162 l = __floats2bfloat162_rn(vx - __low2float(h), vy - __high2float(h));
    hi = b2u(h); lo = b2u(l);
}
__device__ __forceinline__ void pack2h(float vx, float vy, uint32_t& hi, uint32_t& lo){
    __half2 h = __floats2half2_rn(vx, vy);
    __half2 l = __floats2half2_rn(vx - __low2float(h), vy - __high2float(h));
    hi = h2u(h); lo = h2u(l);
}

// ================= fp32 -> bf16/fp16 hi/lo conversion =================
#define XC ((MTOT*DD)/4)
#define WC (WELEM/4)
__global__ void convert_kernel(const float* __restrict__ x,
                               const float* __restrict__ Wq, const float* __restrict__ Wk,
                               const float* __restrict__ Wv, const float* __restrict__ Wo)
{
    int i = blockIdx.x * blockDim.x + threadIdx.x;
    if (i < XC) {
        float4 v = ((const float4*)x)[i];
        uint2 uh, ul;
        pack2(v.x, v.y, uh.x, ul.x);
        pack2(v.z, v.w, uh.y, ul.y);
        *(uint2*)&g_xh[4*(size_t)i] = uh;
        *(uint2*)&g_xl[4*(size_t)i] = ul;
        return;
    }
    int j = i - XC;
    int w = j >> 16;          // / WC
    int off = j & (WC - 1);
    if (w < 3) {
        const float* src = (w == 0) ? Wq : (w == 1) ? Wk : Wv;
        float4 v = ((const float4*)src)[off];
        uint2 uh, ul;
        pack2(v.x, v.y, uh.x, ul.x);
        pack2(v.z, v.w, uh.y, ul.y);
        *(uint2*)&g_Wh[(size_t)w * WELEM + 4*(size_t)off] = uh;
        *(uint2*)&g_Wl[(size_t)w * WELEM + 4*(size_t)off] = ul;
    } else {
        float4 v = ((const float4*)Wo)[off];
        uint2 uh, ul;
        pack2h(v.x, v.y, uh.x, ul.x);
        pack2h(v.z, v.w, uh.y, ul.y);
        *(uint2*)&g_Woh[4*(size_t)off] = uh;
        *(uint2*)&g_Wol[4*(size_t)off] = ul;
    }
}

// ================= QKV GEMM staging (2 stages x 40960 B) =================
#define AS 40
#define GB_AH 0
#define GB_AL 10240
#define GB_WH 20480
#define GB_WL 30720
#define STG   40960
#define GEMM_SMEM (2*STG)

__device__ __forceinline__ void gemm_stage(
    uint32_t sb, int stage, int t, int m0, int o0, int k0,
    const __nv_bfloat16* Ahg, const __nv_bfloat16* Alg,
    const __nv_bfloat16* Whg, const __nv_bfloat16* Wlg)
{
    uint32_t sa = sb + (uint32_t)stage * STG;
#pragma unroll
    for (int i = 0; i < 2; i++) {
        int c   = t + i * 256;
        int row = c >> 2;
        int ce  = (c & 3) << 3;
        uint32_t so = (uint32_t)(row * AS + ce) * 2u;
        cp16(sa + GB_AH + so, Ahg + (size_t)(m0 + row) * DD + k0 + ce);
        cp16(sa + GB_AL + so, Alg + (size_t)(m0 + row) * DD + k0 + ce);
        cp16(sa + GB_WH + so, Whg + (size_t)(o0 + row) * DD + k0 + ce);
        cp16(sa + GB_WL + so, Wlg + (size_t)(o0 + row) * DD + k0 + ce);
    }
    CP_COMMIT;
}

__device__ __forceinline__ void gemm_compute(
    uint32_t sb, int stage, float Cs[4][4][4],
    int wm, int wn, int a_r, int a_c8, int b_r, int b_c8, int b_r16)
{
    uint32_t sa = sb + (uint32_t)stage * STG;
#pragma unroll
    for (int ks = 0; ks < 2; ks++) {
        uint32_t Ah[4][4], Al[4][4], WH[2][4], WL[2][4];
#pragma unroll
        for (int mb = 0; mb < 4; mb++) {
            uint32_t ad = sa + (uint32_t)(((wm*64 + mb*16 + a_r) * AS + ks*16 + a_c8) * 2);
            ldsm_x4(ad + GB_AH, Ah[mb]);
            ldsm_x4(ad + GB_AL, Al[mb]);
        }
#pragma unroll
        for (int j = 0; j < 2; j++) {
            uint32_t wd = sa + (uint32_t)(((wn*32 + j*16 + b_r + b_r16) * AS + ks*16 + b_c8) * 2);
            ldsm_x4(wd + GB_WH, WH[j]);
            ldsm_x4(wd + GB_WL, WL[j]);
        }
#pragma unroll
        for (int mb = 0; mb < 4; mb++)
#pragma unroll
            for (int nb = 0; nb < 4; nb++) {
                const uint32_t* bh = &WH[nb>>1][(nb&1)*2];
                const uint32_t* bl = &WL[nb>>1][(nb&1)*2];
                mma16816(Cs[mb][nb], Ah[mb], bh);
                mma16816(Cs[mb][nb], Ah[mb], bl);
                mma16816(Cs[mb][nb], Al[mb], bh);
            }
    }
}

// ================= fused QKV projection (bf16x3 in, fp16 out) =================
__global__ __launch_bounds__(256, 2) void qkv_mma_kernel(
    const float* __restrict__ bq, const float* __restrict__ bk, const float* __restrict__ bv)
{
    extern __shared__ char smem[];
    uint32_t sb = smem_u32(smem);
    const int t    = threadIdx.x;
    const int lane = t & 31;
    const int w    = t >> 5;
    const int wm   = w >> 2;
    const int wn   = w & 3;
    const int m0   = blockIdx.y * 128;
    const int o0   = blockIdx.x * 128;
    const int z    = blockIdx.z;

    const __nv_bfloat16* Whg = g_Wh + (size_t)z * WELEM;
    const __nv_bfloat16* Wlg = g_Wl + (size_t)z * WELEM;
    const float* bias = (z == 0) ? bq : (z == 1) ? bk : bv;
    const float scale = (z == 0) ? 0.125f * LOG2E : 1.0f;
    const bool  isV   = (z == 2);

    float Cs[4][4][4];
#pragma unroll
    for (int mb = 0; mb < 4; mb++)
#pragma unroll
        for (int nb = 0; nb < 4; nb++)
#pragma unroll
            for (int i = 0; i < 4; i++) Cs[mb][nb][i] = 0.f;

    const int a_r   = (lane & 7) + ((lane & 8) ? 8 : 0);
    const int a_c8  = (lane & 16) ? 8 : 0;
    const int b_r   = lane & 7;
    const int b_c8  = (lane & 8) ? 8 : 0;
    const int b_r16 = (lane & 16) ? 8 : 0;

    gemm_stage(sb, 0, t, m0, o0, 0, g_xh, g_xl, Whg, Wlg);
    for (int kk = 0; kk < 16; kk++) {
        if (kk + 1 < 16) {
            gemm_stage(sb, (kk+1)&1, t, m0, o0, (kk+1)*32, g_xh, g_xl, Whg, Wlg);
            CP_WAIT1;
        } else {
            CP_WAIT0;
        }
        __syncthreads();
        gemm_compute(sb, kk & 1, Cs, wm, wn, a_r, a_c8, b_r, b_c8, b_r16);
        __syncthreads();
    }

    const int r0l = lane >> 2;
    const int c0l = (lane & 3) * 2;
#pragma unroll
    for (int mb = 0; mb < 4; mb++) {
#pragma unroll
        for (int nb = 0; nb < 4; nb++) {
            int gc = o0 + wn*32 + nb*8 + c0l;
            float2 bbv = *(const float2*)&bias[gc];
            int h  = gc >> 6;
            int hd = gc & 63;
#pragma unroll
            for (int half = 0; half < 2; half++) {
                int gr = m0 + wm*64 + mb*16 + r0l + half*8;
                float vx = (Cs[mb][nb][half*2+0] + bbv.x) * scale;
                float vy = (Cs[mb][nb][half*2+1] + bbv.y) * scale;
                int b  = gr >> 11;
                int n  = gr & 2047;
                if (isV) {
                    size_t off = ((size_t)((b*HH + h) * NN + n)) * HD + hd;
                    *(uint32_t*)&g_V[off] = h2u(__floats2half2_rn(vx, vy));
                } else {
                    uint32_t hi, lo;
                    pack2h(vx, vy, hi, lo);
                    size_t off = ((size_t)((b*HH + h) * NN + n)) * DA + hd;
                    __half* dh = (z == 0) ? g_Qh : g_Kh;
                    __half* dl = (z == 0) ? g_Ql : g_Kl;
                    *(uint32_t*)&dh[off] = hi;
                    *(uint32_t*)&dl[off] = lo;
                }
            }
        }
    }
}

// ================= output projection (fp16 single A x fp16x2 W) =================
#define OB_A  0
#define OB_WH 10240
#define OB_WL 20480
#define OSTG  30720
#define OPROJ_SMEM (2*OSTG)

__global__ __launch_bounds__(256, 2) void oproj_mma_kernel(
    const float* __restrict__ bias, float* __restrict__ out)
{
    extern __shared__ char smem[];
    uint32_t sb = smem_u32(smem);
    const int t    = threadIdx.x;
    const int lane = t & 31;
    const int w    = t >> 5;
    const int wm   = w >> 2;
    const int wn   = w & 3;
    const int m0   = blockIdx.y * 128;
    const int o0   = blockIdx.x * 128;

    float Cs[4][4][4];
#pragma unroll
    for (int mb = 0; mb < 4; mb++)
#pragma unroll
        for (int nb = 0; nb < 4; nb++)
#pragma unroll
            for (int i = 0; i < 4; i++) Cs[mb][nb][i] = 0.f;

    const int a_r   = (lane & 7) + ((lane & 8) ? 8 : 0);
    const int a_c8  = (lane & 16) ? 8 : 0;
    const int b_r   = lane & 7;
    const int b_c8  = (lane & 8) ? 8 : 0;
    const int b_r16 = (lane & 16) ? 8 : 0;

    auto stage = [&](int stg, int k0){
        uint32_t sa = sb + (uint32_t)stg * OSTG;
#pragma unroll
        for (int i = 0; i < 2; i++) {
            int c   = t + i * 256;
            int row = c >> 2;
            int ce  = (c & 3) << 3;
            uint32_t so = (uint32_t)(row * AS + ce) * 2u;
            cp16(sa + OB_A  + so, g_att + (size_t)(m0 + row) * DD + k0 + ce);
            cp16(sa + OB_WH + so, g_Woh + (size_t)(o0 + row) * DD + k0 + ce);
            cp16(sa + OB_WL + so, g_Wol + (size_t)(o0 + row) * DD + k0 + ce);
        }
        CP_COMMIT;
    };

    stage(0, 0);
    for (int kk = 0; kk < 16; kk++) {
        if (kk + 1 < 16) {
            stage((kk+1)&1, (kk+1)*32);
            CP_WAIT1;
        } else {
            CP_WAIT0;
        }
        __syncthreads();
        uint32_t sa = sb + (uint32_t)(kk & 1) * OSTG;
#pragma unroll
        for (int ks = 0; ks < 2; ks++) {
            uint32_t Ah[4][4], WH[2][4], WL[2][4];
#pragma unroll
            for (int mb = 0; mb < 4; mb++) {
                uint32_t ad = sa + OB_A + (uint32_t)(((wm*64 + mb*16 + a_r) * AS + ks*16 + a_c8) * 2);
                ldsm_x4(ad, Ah[mb]);
            }
#pragma unroll
            for (int j = 0; j < 2; j++) {
                uint32_t wd = sa + (uint32_t)(((wn*32 + j*16 + b_r + b_r16) * AS + ks*16 + b_c8) * 2);
                ldsm_x4(wd + OB_WH, WH[j]);
                ldsm_x4(wd + OB_WL, WL[j]);
            }
#pragma unroll
            for (int mb = 0; mb < 4; mb++)
#pragma unroll
                for (int nb = 0; nb < 4; nb++) {
                    const uint32_t* bh = &WH[nb>>1][(nb&1)*2];
                    const uint32_t* bl = &WL[nb>>1][(nb&1)*2];
                    mma16816h(Cs[mb][nb], Ah[mb], bh);
                    mma16816h(Cs[mb][nb], Ah[mb], bl);
                }
        }
        __syncthreads();
    }

    const int r0l = lane >> 2;
    const int c0l = (lane & 3) * 2;
#pragma unroll
    for (int mb = 0; mb < 4; mb++) {
#pragma unroll
        for (int nb = 0; nb < 4; nb++) {
            int gc = o0 + wn*32 + nb*8 + c0l;
            float2 bbv = *(const float2*)&bias[gc];
#pragma unroll
            for (int half = 0; half < 2; half++) {
                int gr = m0 + wm*64 + mb*16 + r0l + half*8;
                float2 v;
                v.x = Cs[mb][nb][half*2+0] + bbv.x;
                v.y = Cs[mb][nb][half*2+1] + bbv.y;
                *(float2*)&out[(size_t)gr * DD + gc] = v;
            }
        }
    }
}

// ---------------- phase augmentation fill (fp16 hi/lo) ----------------
__device__ __forceinline__ void pack8h(const float* v, uint4& hi, uint4& lo){
    uint32_t h[4], l[4];
#pragma unroll
    for (int i = 0; i < 4; i++) pack2h(v[2*i], v[2*i+1], h[i], l[i]);
    hi.x = h[0]; hi.y = h[1]; hi.z = h[2]; hi.w = h[3];
    lo.x = l[0]; lo.y = l[1]; lo.z = l[2]; lo.w = l[3];
}

__global__ void phase_fill_kernel(const float* __restrict__ pc,
                                  const float* __restrict__ pb)
{
    int tid = blockIdx.x * blockDim.x + threadIdx.x;
    if (tid >= BB * NN * HH) return;
    int h  = tid >> 12;
    int bn = tid & 4095;

    float c[FF], s[FF], wc[FF], ws[FF];
#pragma unroll
    for (int f = 0; f < FF; f++)
        __sincosf(pc[(size_t)bn * FF + f], &s[f], &c[f]);
#pragma unroll
    for (int f = 0; f < FF; f++) {
        float wv = pb[h*FF + f] * LOG2E;
        wc[f] = wv * c[f];
        ws[f] = wv * s[f];
    }

    int b = bn >> 11, n = bn & 2047;
    size_t base = ((size_t)((b*HH + h) * NN + n)) * DA + 64;

    uint4 hi, lo;
    pack8h(c,  hi, lo); *(uint4*)&g_Kh[base]   = hi; *(uint4*)&g_Kl[base]   = lo;
    pack8h(s,  hi, lo); *(uint4*)&g_Kh[base+8] = hi; *(uint4*)&g_Kl[base+8] = lo;
    pack8h(wc, hi, lo); *(uint4*)&g_Qh[base]   = hi; *(uint4*)&g_Ql[base]   = lo;
    pack8h(ws, hi, lo); *(uint4*)&g_Qh[base+8] = hi; *(uint4*)&g_Ql[base+8] = lo;
}

// =============== BQ=128 x BK=128 fp16 warp-MMA flash attention ===============
// QK: fp16x3.  PV: P fp16 single x V fp16 single (1 MMA).
#define QS 88
#define VS 72
#define K_L   (128*QS*2)          // 22528
#define KSTG  (2*K_L)             // 45056
#define VBASE (2*KSTG)            // 90112
#define VSTG  (128*VS*2)          // 18432 (single V, no lo part)
#define ATTN_SMEM (VBASE + 2*VSTG)  // 126976

__global__ __launch_bounds__(256, 1) void attn_mma_kernel()
{
    extern __shared__ char smem[];
    uint32_t sb = smem_u32(smem);
    const int t    = threadIdx.x;
    const int lane = t & 31;
    const int w    = t >> 5;
    const int q0   = blockIdx.x * BQ;
    const int bh   = blockIdx.y;

    const __half* Qgh = g_Qh + (size_t)bh * NN * DA + (size_t)q0 * DA;
    const __half* Qgl = g_Ql + (size_t)bh * NN * DA + (size_t)q0 * DA;
    const __half* Kgh = g_Kh + (size_t)bh * NN * DA;
    const __half* Kgl = g_Kl + (size_t)bh * NN * DA;
    const __half* Vg  = g_V  + (size_t)bh * NN * HD;

    auto prefetch = [&](int kt){
        uint32_t ka = sb + (uint32_t)(kt & 1) * KSTG;
        uint32_t va = sb + VBASE + (uint32_t)(kt & 1) * VSTG;
        int k0 = kt * BK;
#pragma unroll
        for (int i = 0; i < 5; i++) {
            int idx = t + i * 256;
            int row = idx / 10;
            int c8  = (idx % 10) * 8;
            uint32_t so = (uint32_t)(row * QS + c8) * 2u;
            const size_t g = (size_t)(k0 + row) * DA + c8;
            cp16(ka + so, Kgh + g);
            cp16(ka + K_L + so, Kgl + g);
        }
#pragma unroll
        for (int i = 0; i < 4; i++) {
            int idx = t + i * 256;
            int row = idx >> 3;
            int c8  = (idx & 7) * 8;
            uint32_t so = (uint32_t)(row * VS + c8) * 2u;
            cp16(va + so, Vg + (size_t)(k0 + row) * HD + c8);
        }
        CP_COMMIT;
    };

    prefetch(0);
    {
        uint32_t qh_off = KSTG;
        uint32_t ql_off = KSTG + K_L;
#pragma unroll
        for (int i = 0; i < 5; i++) {
            int idx = t + i * 256;
            int row = idx / 10;
            int c8  = (idx % 10) * 8;
            uint32_t soff = (uint32_t)(row * QS + c8) * 2u;
            *(uint4*)(smem + qh_off + soff) = *(const uint4*)(Qgh + (size_t)row * DA + c8);
            *(uint4*)(smem + ql_off + soff) = *(const uint4*)(Qgl + (size_t)row * DA + c8);
        }
    }
    __syncthreads();

    const int a_r   = (lane & 7) + ((lane & 8) ? 8 : 0);
    const int a_c8  = (lane & 16) ? 8 : 0;
    const int b_r   = lane & 7;
    const int b_c8  = (lane & 8) ? 8 : 0;
    const int b_r16 = (lane & 16) ? 8 : 0;
    const int v_r8  = (lane & 8) ? 8 : 0;

    uint32_t Qfh[5][4], Qfl[5][4];
#pragma unroll
    for (int s = 0; s < 5; s++) {
        uint32_t ad = sb + KSTG + (uint32_t)(((w*16 + a_r) * QS + s*16 + a_c8) * 2);
        ldsm_x4(ad, Qfh[s]);
        ldsm_x4(ad + K_L, Qfl[s]);
    }
    __syncthreads();

    float mrow[2] = {-1e30f, -1e30f};
    float lrow[2] = {0.f, 0.f};
    float Od[8][4];
#pragma unroll
    for (int db = 0; db < 8; db++)
#pragma unroll
        for (int i = 0; i < 4; i++) Od[db][i] = 0.f;

#pragma unroll 1
    for (int kt = 0; kt < NT2; kt++) {
        if (kt + 1 < NT2) {
            prefetch(kt + 1);
            CP_WAIT1;
        } else {
            CP_WAIT0;
        }
        __syncthreads();
        uint32_t ka = sb + (uint32_t)(kt & 1) * KSTG;
        uint32_t va = sb + VBASE + (uint32_t)(kt & 1) * VSTG;

        // ---- S = Q . K^T over 128 keys (fp16x3) ----
        float Cs[16][4];
#pragma unroll
        for (int nb = 0; nb < 16; nb++)
#pragma unroll
            for (int i = 0; i < 4; i++) Cs[nb][i] = 0.f;

#pragma unroll
        for (int s = 0; s < 5; s++) {
#pragma unroll
            for (int j = 0; j < 8; j++) {
                uint32_t kd = ka + (uint32_t)(((j*16 + b_r + b_r16) * QS + s*16 + b_c8) * 2);
                uint32_t h4[4], l4[4];
                ldsm_x4(kd, h4);
                ldsm_x4(kd + K_L, l4);
                mma16816h(Cs[2*j],   Qfh[s], h4+0);
                mma16816h(Cs[2*j],   Qfh[s], l4+0);
                mma16816h(Cs[2*j],   Qfl[s], h4+0);
                mma16816h(Cs[2*j+1], Qfh[s], h4+2);
                mma16816h(Cs[2*j+1], Qfh[s], l4+2);
                mma16816h(Cs[2*j+1], Qfl[s], h4+2);
            }
        }

        // ---- joint max over all 128 keys ----
        float mx0 = -1e30f, mx1 = -1e30f;
#pragma unroll
        for (int nb = 0; nb < 16; nb++) {
            mx0 = fmaxf(mx0, fmaxf(Cs[nb][0], Cs[nb][1]));
            mx1 = fmaxf(mx1, fmaxf(Cs[nb][2], Cs[nb][3]));
        }
        mx0 = fmaxf(mx0, __shfl_xor_sync(0xffffffffu, mx0, 1));
        mx0 = fmaxf(mx0, __shfl_xor_sync(0xffffffffu, mx0, 2));
        mx1 = fmaxf(mx1, __shfl_xor_sync(0xffffffffu, mx1, 1));
        mx1 = fmaxf(mx1, __shfl_xor_sync(0xffffffffu, mx1, 2));
        float mn0 = fmaxf(mrow[0], mx0);
        float mn1 = fmaxf(mrow[1], mx1);
        float f0  = ex2(mrow[0] - mn0);
        float f1  = ex2(mrow[1] - mn1);
        mrow[0] = mn0; mrow[1] = mn1;

#pragma unroll
        for (int db = 0; db < 8; db++) {
            Od[db][0] *= f0; Od[db][1] *= f0;
            Od[db][2] *= f1; Od[db][3] *= f1;
        }

        float s0 = 0.f, s1 = 0.f;
        // ---- two 64-key halves: softmax(h) then PV(h) ----
#pragma unroll
        for (int h = 0; h < 2; h++) {
            uint32_t Ph[4][4];
#pragma unroll
            for (int ks = 0; ks < 4; ks++) {
#pragma unroll
                for (int hf = 0; hf < 2; hf++) {
                    int nb = h*8 + 2*ks + hf;
                    float p0 = ex2(Cs[nb][0] - mn0);
                    float p1 = ex2(Cs[nb][1] - mn0);
                    float p2 = ex2(Cs[nb][2] - mn1);
                    float p3 = ex2(Cs[nb][3] - mn1);
                    s0 += p0 + p1;
                    s1 += p2 + p3;
                    Ph[ks][hf*2+0] = h2u(__floats2half2_rn(p0, p1));
                    Ph[ks][hf*2+1] = h2u(__floats2half2_rn(p2, p3));
                }
            }
#pragma unroll
            for (int ks = 0; ks < 4; ks++) {
#pragma unroll
                for (int j = 0; j < 4; j++) {
                    uint32_t vd = va + (uint32_t)(((h*64 + ks*16 + b_r + v_r8) * VS + j*16 + b_r16) * 2);
                    uint32_t h4[4];
                    ldsm_x4t(vd, h4);
                    mma16816h(Od[2*j],   Ph[ks], h4+0);
                    mma16816h(Od[2*j+1], Ph[ks], h4+2);
                }
            }
        }

        s0 += __shfl_xor_sync(0xffffffffu, s0, 1);
        s0 += __shfl_xor_sync(0xffffffffu, s0, 2);
        s1 += __shfl_xor_sync(0xffffffffu, s1, 1);
        s1 += __shfl_xor_sync(0xffffffffu, s1, 2);
        lrow[0] = lrow[0] * f0 + s0;
        lrow[1] = lrow[1] * f1 + s1;
        __syncthreads();
    }

    // ---- epilogue: write att as fp16 single ----
    float i0 = 1.0f / lrow[0];
    float i1 = 1.0f / lrow[1];
    int b = bh >> 3, h = bh & 7;
    int r0l = w*16 + (lane >> 2);
    int c0l = (lane & 3) * 2;
#pragma unroll
    for (int db = 0; db < 8; db++) {
        int gc = h*64 + db*8 + c0l;
        uint32_t v0 = h2u(__floats2half2_rn(Od[db][0] * i0, Od[db][1] * i0));
        uint32_t v1 = h2u(__floats2half2_rn(Od[db][2] * i1, Od[db][3] * i1));
        size_t o0r = ((size_t)(b*NN + q0 + r0l)) * DD + gc;
        size_t o1r = ((size_t)(b*NN + q0 + r0l + 8)) * DD + gc;
        *(uint32_t*)&g_att[o0r] = v0;
        *(uint32_t*)&g_att[o1r] = v1;
    }
}

// ---------------- launch ----------------
extern "C" void kernel_launch(void* const* d_in, const int* in_sizes, int n_in,
                              void* d_out, int out_size)
{
    const float* x   = (const float*)d_in[0];
    const float* pc  = (const float*)d_in[1];
    const float* Wq  = (const float*)d_in[2];
    const float* bq  = (const float*)d_in[3];
    const float* Wk  = (const float*)d_in[4];
    const float* bk  = (const float*)d_in[5];
    const float* Wv  = (const float*)d_in[6];
    const float* bv  = (const float*)d_in[7];
    const float* Wo  = (const float*)d_in[8];
    const float* bo  = (const float*)d_in[9];
    const float* pb  = (const float*)d_in[10];
    float* out = (float*)d_out;

    cudaFuncSetAttribute(attn_mma_kernel,  cudaFuncAttributeMaxDynamicSharedMemorySize, ATTN_SMEM);
    cudaFuncSetAttribute(qkv_mma_kernel,   cudaFuncAttributeMaxDynamicSharedMemorySize, GEMM_SMEM);
    cudaFuncSetAttribute(oproj_mma_kernel, cudaFuncAttributeMaxDynamicSharedMemorySize, OPROJ_SMEM);

    int totc = XC + 4*WC;
    convert_kernel<<<(totc + 255)/256, 256>>>(x, Wq, Wk, Wv, Wo);

    dim3 qgrid(4, 32, 3);
    qkv_mma_kernel<<<qgrid, 256, GEMM_SMEM>>>(bq, bk, bv);

    phase_fill_kernel<<<(BB*NN*HH + 255)/256, 256>>>(pc, pb);

    dim3 agrid(NN/BQ, BB*HH);   // (16, 16)
    attn_mma_kernel<<<agrid, 256, ATTN_SMEM>>>();

    dim3 ggrid(4, 32);
    oproj_mma_kernel<<<ggrid, 256, OPROJ_SMEM>>>(bo, out);
}

// round 17
// speedup vs baseline: 6.2414x; 1.2925x over previous
#include <cuda_runtime.h>
#include <cuda_bf16.h>
#include <cuda_fp16.h>
#include <cstdint>
#include <math.h>

// Problem constants
#define BB 2
#define NN 2048
#define DD 512
#define HH 8
#define FF 8
#define HD 64
#define DA 80   // augmented head dim: 64 (Q/K) + 8 (cos) + 8 (sin)
#define BQ 128  // q rows per CTA (attention)
#define BK 128  // keys per mainloop iteration
#define NT2 (NN/BK)   // 16 iterations

#define MTOT (BB*NN)          // 4096
#define WELEM (DD*DD)         // 262144
#define LOG2E 1.4426950408889634f

// ---------------- scratch (device globals; no allocation) ----------------
__device__ __nv_bfloat16 g_xh[MTOT*DD], g_xl[MTOT*DD];
__device__ __nv_bfloat16 g_Wh[3*WELEM], g_Wl[3*WELEM];     // Wq,Wk,Wv (bf16 x3 path)
__device__ __half g_Woh[WELEM], g_Wol[WELEM];              // Wo (fp16 x2 path)
__device__ __half g_Q[BB*HH*NN*DA];                        // Q single fp16
__device__ __half g_K[BB*HH*NN*DA];                        // K single fp16
__device__ __half g_V[BB*HH*NN*HD];                        // V single fp16
__device__ __half g_att[MTOT*DD];                          // attended, fp16 single

// ======================= helpers =======================
__device__ __forceinline__ uint32_t smem_u32(const void* p){
    uint32_t a;
    asm("{ .reg .u64 t; cvta.to.shared.u64 t, %1; cvt.u32.u64 %0, t; }" : "=r"(a) : "l"(p));
    return a;
}
__device__ __forceinline__ void ldsm_x4(uint32_t addr, uint32_t r[4]){
    asm volatile("ldmatrix.sync.aligned.m8n8.x4.shared.b16 {%0,%1,%2,%3}, [%4];"
        : "=r"(r[0]), "=r"(r[1]), "=r"(r[2]), "=r"(r[3]) : "r"(addr));
}
__device__ __forceinline__ void ldsm_x4t(uint32_t addr, uint32_t r[4]){
    asm volatile("ldmatrix.sync.aligned.m8n8.x4.trans.shared.b16 {%0,%1,%2,%3}, [%4];"
        : "=r"(r[0]), "=r"(r[1]), "=r"(r[2]), "=r"(r[3]) : "r"(addr));
}
// bf16 MMA
__device__ __forceinline__ void mma16816(float c[4], const uint32_t a[4], const uint32_t b[2]){
    asm volatile("mma.sync.aligned.m16n8k16.row.col.f32.bf16.bf16.f32 "
        "{%0,%1,%2,%3}, {%4,%5,%6,%7}, {%8,%9}, {%0,%1,%2,%3};"
        : "+f"(c[0]), "+f"(c[1]), "+f"(c[2]), "+f"(c[3])
        : "r"(a[0]), "r"(a[1]), "r"(a[2]), "r"(a[3]), "r"(b[0]), "r"(b[1]));
}
// fp16 MMA
__device__ __forceinline__ void mma16816h(float c[4], const uint32_t a[4], const uint32_t b[2]){
    asm volatile("mma.sync.aligned.m16n8k16.row.col.f32.f16.f16.f32 "
        "{%0,%1,%2,%3}, {%4,%5,%6,%7}, {%8,%9}, {%0,%1,%2,%3};"
        : "+f"(c[0]), "+f"(c[1]), "+f"(c[2]), "+f"(c[3])
        : "r"(a[0]), "r"(a[1]), "r"(a[2]), "r"(a[3]), "r"(b[0]), "r"(b[1]));
}
__device__ __forceinline__ uint32_t b2u(__nv_bfloat162 v){ return *reinterpret_cast<uint32_t*>(&v); }
__device__ __forceinline__ uint32_t h2u(__half2 v){ return *reinterpret_cast<uint32_t*>(&v); }
__device__ __forceinline__ void cp16(uint32_t dst, const void* src){
    asm volatile("cp.async.cg.shared.global [%0], [%1], 16;" :: "r"(dst), "l"(src));
}
#define CP_COMMIT asm volatile("cp.async.commit_group;" ::: "memory")
#define CP_WAIT1  asm volatile("cp.async.wait_group 1;" ::: "memory")
#define CP_WAIT0  asm volatile("cp.async.wait_group 0;" ::: "memory")

__device__ __forceinline__ float ex2(float x){
    float r; asm("ex2.approx.ftz.f32 %0, %1;" : "=f"(r) : "f"(x)); return r;
}
__device__ __forceinline__ void pack2(float vx, float vy, uint32_t& hi, uint32_t& lo){
    __nv_bfloat162 h = __floats2bfloat162_rn(vx, vy);
    __nv_bfloat162 l = __floats2bfloat162_rn(vx - __low2float(h), vy - __high2float(h));
    hi = b2u(h); lo = b2u(l);
}
__device__ __forceinline__ void pack2h(float vx, float vy, uint32_t& hi, uint32_t& lo){
    __half2 h = __floats2half2_rn(vx, vy);
    __half2 l = __floats2half2_rn(vx - __low2float(h), vy - __high2float(h));
    hi = h2u(h); lo = h2u(l);
}

// ================= fp32 -> bf16/fp16 conversion =================
#define XC ((MTOT*DD)/4)
#define WC (WELEM/4)
__global__ void convert_kernel(const float* __restrict__ x,
                               const float* __restrict__ Wq, const float* __restrict__ Wk,
                               const float* __restrict__ Wv, const float* __restrict__ Wo)
{
    int i = blockIdx.x * blockDim.x + threadIdx.x;
    if (i < XC) {
        float4 v = ((const float4*)x)[i];
        uint2 uh, ul;
        pack2(v.x, v.y, uh.x, ul.x);
        pack2(v.z, v.w, uh.y, ul.y);
        *(uint2*)&g_xh[4*(size_t)i] = uh;
        *(uint2*)&g_xl[4*(size_t)i] = ul;
        return;
    }
    int j = i - XC;
    int w = j >> 16;          // / WC
    int off = j & (WC - 1);
    if (w < 3) {
        const float* src = (w == 0) ? Wq : (w == 1) ? Wk : Wv;
        float4 v = ((const float4*)src)[off];
        uint2 uh, ul;
        pack2(v.x, v.y, uh.x, ul.x);
        pack2(v.z, v.w, uh.y, ul.y);
        *(uint2*)&g_Wh[(size_t)w * WELEM + 4*(size_t)off] = uh;
        *(uint2*)&g_Wl[(size_t)w * WELEM + 4*(size_t)off] = ul;
    } else {
        float4 v = ((const float4*)Wo)[off];
        uint2 uh, ul;
        pack2h(v.x, v.y, uh.x, ul.x);
        pack2h(v.z, v.w, uh.y, ul.y);
        *(uint2*)&g_Woh[4*(size_t)off] = uh;
        *(uint2*)&g_Wol[4*(size_t)off] = ul;
    }
}

// ================= QKV GEMM staging (2 stages x 40960 B) =================
#define AS 40
#define GB_AH 0
#define GB_AL 10240
#define GB_WH 20480
#define GB_WL 30720
#define STG   40960
#define GEMM_SMEM (2*STG)

__device__ __forceinline__ void gemm_stage(
    uint32_t sb, int stage, int t, int m0, int o0, int k0,
    const __nv_bfloat16* Ahg, const __nv_bfloat16* Alg,
    const __nv_bfloat16* Whg, const __nv_bfloat16* Wlg)
{
    uint32_t sa = sb + (uint32_t)stage * STG;
#pragma unroll
    for (int i = 0; i < 2; i++) {
        int c   = t + i * 256;
        int row = c >> 2;
        int ce  = (c & 3) << 3;
        uint32_t so = (uint32_t)(row * AS + ce) * 2u;
        cp16(sa + GB_AH + so, Ahg + (size_t)(m0 + row) * DD + k0 + ce);
        cp16(sa + GB_AL + so, Alg + (size_t)(m0 + row) * DD + k0 + ce);
        cp16(sa + GB_WH + so, Whg + (size_t)(o0 + row) * DD + k0 + ce);
        cp16(sa + GB_WL + so, Wlg + (size_t)(o0 + row) * DD + k0 + ce);
    }
    CP_COMMIT;
}

__device__ __forceinline__ void gemm_compute(
    uint32_t sb, int stage, float Cs[4][4][4],
    int wm, int wn, int a_r, int a_c8, int b_r, int b_c8, int b_r16)
{
    uint32_t sa = sb + (uint32_t)stage * STG;
#pragma unroll
    for (int ks = 0; ks < 2; ks++) {
        uint32_t Ah[4][4], Al[4][4], WH[2][4], WL[2][4];
#pragma unroll
        for (int mb = 0; mb < 4; mb++) {
            uint32_t ad = sa + (uint32_t)(((wm*64 + mb*16 + a_r) * AS + ks*16 + a_c8) * 2);
            ldsm_x4(ad + GB_AH, Ah[mb]);
            ldsm_x4(ad + GB_AL, Al[mb]);
        }
#pragma unroll
        for (int j = 0; j < 2; j++) {
            uint32_t wd = sa + (uint32_t)(((wn*32 + j*16 + b_r + b_r16) * AS + ks*16 + b_c8) * 2);
            ldsm_x4(wd + GB_WH, WH[j]);
            ldsm_x4(wd + GB_WL, WL[j]);
        }
#pragma unroll
        for (int mb = 0; mb < 4; mb++)
#pragma unroll
            for (int nb = 0; nb < 4; nb++) {
                const uint32_t* bh = &WH[nb>>1][(nb&1)*2];
                const uint32_t* bl = &WL[nb>>1][(nb&1)*2];
                mma16816(Cs[mb][nb], Ah[mb], bh);
                mma16816(Cs[mb][nb], Ah[mb], bl);
                mma16816(Cs[mb][nb], Al[mb], bh);
            }
    }
}

// ================= fused QKV projection (bf16x3 in, fp16 single out) =================
__global__ __launch_bounds__(256, 2) void qkv_mma_kernel(
    const float* __restrict__ bq, const float* __restrict__ bk, const float* __restrict__ bv)
{
    extern __shared__ char smem[];
    uint32_t sb = smem_u32(smem);
    const int t    = threadIdx.x;
    const int lane = t & 31;
    const int w    = t >> 5;
    const int wm   = w >> 2;
    const int wn   = w & 3;
    const int m0   = blockIdx.y * 128;
    const int o0   = blockIdx.x * 128;
    const int z    = blockIdx.z;

    const __nv_bfloat16* Whg = g_Wh + (size_t)z * WELEM;
    const __nv_bfloat16* Wlg = g_Wl + (size_t)z * WELEM;
    const float* bias = (z == 0) ? bq : (z == 1) ? bk : bv;
    __half* dst = (z == 0) ? g_Q : (z == 1) ? g_K : g_V;
    const float scale = (z == 0) ? 0.125f * LOG2E : 1.0f;
    const int   ld    = (z == 2) ? HD : DA;

    float Cs[4][4][4];
#pragma unroll
    for (int mb = 0; mb < 4; mb++)
#pragma unroll
        for (int nb = 0; nb < 4; nb++)
#pragma unroll
            for (int i = 0; i < 4; i++) Cs[mb][nb][i] = 0.f;

    const int a_r   = (lane & 7) + ((lane & 8) ? 8 : 0);
    const int a_c8  = (lane & 16) ? 8 : 0;
    const int b_r   = lane & 7;
    const int b_c8  = (lane & 8) ? 8 : 0;
    const int b_r16 = (lane & 16) ? 8 : 0;

    gemm_stage(sb, 0, t, m0, o0, 0, g_xh, g_xl, Whg, Wlg);
    for (int kk = 0; kk < 16; kk++) {
        if (kk + 1 < 16) {
            gemm_stage(sb, (kk+1)&1, t, m0, o0, (kk+1)*32, g_xh, g_xl, Whg, Wlg);
            CP_WAIT1;
        } else {
            CP_WAIT0;
        }
        __syncthreads();
        gemm_compute(sb, kk & 1, Cs, wm, wn, a_r, a_c8, b_r, b_c8, b_r16);
        __syncthreads();
    }

    const int r0l = lane >> 2;
    const int c0l = (lane & 3) * 2;
#pragma unroll
    for (int mb = 0; mb < 4; mb++) {
#pragma unroll
        for (int nb = 0; nb < 4; nb++) {
            int gc = o0 + wn*32 + nb*8 + c0l;
            float2 bbv = *(const float2*)&bias[gc];
            int h  = gc >> 6;
            int hd = gc & 63;
#pragma unroll
            for (int half = 0; half < 2; half++) {
                int gr = m0 + wm*64 + mb*16 + r0l + half*8;
                float vx = (Cs[mb][nb][half*2+0] + bbv.x) * scale;
                float vy = (Cs[mb][nb][half*2+1] + bbv.y) * scale;
                int b  = gr >> 11;
                int n  = gr & 2047;
                size_t off = ((size_t)((b*HH + h) * NN + n)) * ld + hd;
                *(uint32_t*)&dst[off] = h2u(__floats2half2_rn(vx, vy));
            }
        }
    }
}

// ================= output projection (fp16 single A x fp16x2 W) =================
#define OB_A  0
#define OB_WH 10240
#define OB_WL 20480
#define OSTG  30720
#define OPROJ_SMEM (2*OSTG)

__global__ __launch_bounds__(256, 2) void oproj_mma_kernel(
    const float* __restrict__ bias, float* __restrict__ out)
{
    extern __shared__ char smem[];
    uint32_t sb = smem_u32(smem);
    const int t    = threadIdx.x;
    const int lane = t & 31;
    const int w    = t >> 5;
    const int wm   = w >> 2;
    const int wn   = w & 3;
    const int m0   = blockIdx.y * 128;
    const int o0   = blockIdx.x * 128;

    float Cs[4][4][4];
#pragma unroll
    for (int mb = 0; mb < 4; mb++)
#pragma unroll
        for (int nb = 0; nb < 4; nb++)
#pragma unroll
            for (int i = 0; i < 4; i++) Cs[mb][nb][i] = 0.f;

    const int a_r   = (lane & 7) + ((lane & 8) ? 8 : 0);
    const int a_c8  = (lane & 16) ? 8 : 0;
    const int b_r   = lane & 7;
    const int b_c8  = (lane & 8) ? 8 : 0;
    const int b_r16 = (lane & 16) ? 8 : 0;

    auto stage = [&](int stg, int k0){
        uint32_t sa = sb + (uint32_t)stg * OSTG;
#pragma unroll
        for (int i = 0; i < 2; i++) {
            int c   = t + i * 256;
            int row = c >> 2;
            int ce  = (c & 3) << 3;
            uint32_t so = (uint32_t)(row * AS + ce) * 2u;
            cp16(sa + OB_A  + so, g_att + (size_t)(m0 + row) * DD + k0 + ce);
            cp16(sa + OB_WH + so, g_Woh + (size_t)(o0 + row) * DD + k0 + ce);
            cp16(sa + OB_WL + so, g_Wol + (size_t)(o0 + row) * DD + k0 + ce);
        }
        CP_COMMIT;
    };

    stage(0, 0);
    for (int kk = 0; kk < 16; kk++) {
        if (kk + 1 < 16) {
            stage((kk+1)&1, (kk+1)*32);
            CP_WAIT1;
        } else {
            CP_WAIT0;
        }
        __syncthreads();
        uint32_t sa = sb + (uint32_t)(kk & 1) * OSTG;
#pragma unroll
        for (int ks = 0; ks < 2; ks++) {
            uint32_t Ah[4][4], WH[2][4], WL[2][4];
#pragma unroll
            for (int mb = 0; mb < 4; mb++) {
                uint32_t ad = sa + OB_A + (uint32_t)(((wm*64 + mb*16 + a_r) * AS + ks*16 + a_c8) * 2);
                ldsm_x4(ad, Ah[mb]);
            }
#pragma unroll
            for (int j = 0; j < 2; j++) {
                uint32_t wd = sa + (uint32_t)(((wn*32 + j*16 + b_r + b_r16) * AS + ks*16 + b_c8) * 2);
                ldsm_x4(wd + OB_WH, WH[j]);
                ldsm_x4(wd + OB_WL, WL[j]);
            }
#pragma unroll
            for (int mb = 0; mb < 4; mb++)
#pragma unroll
                for (int nb = 0; nb < 4; nb++) {
                    const uint32_t* bh = &WH[nb>>1][(nb&1)*2];
                    const uint32_t* bl = &WL[nb>>1][(nb&1)*2];
                    mma16816h(Cs[mb][nb], Ah[mb], bh);
                    mma16816h(Cs[mb][nb], Ah[mb], bl);
                }
        }
        __syncthreads();
    }

    const int r0l = lane >> 2;
    const int c0l = (lane & 3) * 2;
#pragma unroll
    for (int mb = 0; mb < 4; mb++) {
#pragma unroll
        for (int nb = 0; nb < 4; nb++) {
            int gc = o0 + wn*32 + nb*8 + c0l;
            float2 bbv = *(const float2*)&bias[gc];
#pragma unroll
            for (int half = 0; half < 2; half++) {
                int gr = m0 + wm*64 + mb*16 + r0l + half*8;
                float2 v;
                v.x = Cs[mb][nb][half*2+0] + bbv.x;
                v.y = Cs[mb][nb][half*2+1] + bbv.y;
                *(float2*)&out[(size_t)gr * DD + gc] = v;
            }
        }
    }
}

// ---------------- phase augmentation fill (fp16 single) ----------------
__device__ __forceinline__ uint4 pack8s(const float* v){
    uint4 r;
    r.x = h2u(__floats2half2_rn(v[0], v[1]));
    r.y = h2u(__floats2half2_rn(v[2], v[3]));
    r.z = h2u(__floats2half2_rn(v[4], v[5]));
    r.w = h2u(__floats2half2_rn(v[6], v[7]));
    return r;
}

__global__ void phase_fill_kernel(const float* __restrict__ pc,
                                  const float* __restrict__ pb)
{
    int tid = blockIdx.x * blockDim.x + threadIdx.x;
    if (tid >= BB * NN * HH) return;
    int h  = tid >> 12;
    int bn = tid & 4095;

    float c[FF], s[FF], wc[FF], ws[FF];
#pragma unroll
    for (int f = 0; f < FF; f++)
        __sincosf(pc[(size_t)bn * FF + f], &s[f], &c[f]);
#pragma unroll
    for (int f = 0; f < FF; f++) {
        float wv = pb[h*FF + f] * LOG2E;
        wc[f] = wv * c[f];
        ws[f] = wv * s[f];
    }

    int b = bn >> 11, n = bn & 2047;
    size_t base = ((size_t)((b*HH + h) * NN + n)) * DA + 64;

    *(uint4*)&g_K[base]   = pack8s(c);
    *(uint4*)&g_K[base+8] = pack8s(s);
    *(uint4*)&g_Q[base]   = pack8s(wc);
    *(uint4*)&g_Q[base+8] = pack8s(ws);
}

// =============== BQ=128 x BK=128 fp16 warp-MMA flash attention ===============
// QK: Q single x K single (1 MMA).  PV: P single x V single (1 MMA).
#define QS 88
#define VS 72
#define KSTG  (128*QS*2)          // 22528 per K stage (single fp16)
#define VBASE (2*KSTG)            // 45056
#define VSTG  (128*VS*2)          // 18432
#define ATTN_SMEM (VBASE + 2*VSTG)  // 81920

__global__ __launch_bounds__(256, 1) void attn_mma_kernel()
{
    extern __shared__ char smem[];
    uint32_t sb = smem_u32(smem);
    const int t    = threadIdx.x;
    const int lane = t & 31;
    const int w    = t >> 5;
    const int q0   = blockIdx.x * BQ;
    const int bh   = blockIdx.y;

    const __half* Qg = g_Q + (size_t)bh * NN * DA + (size_t)q0 * DA;
    const __half* Kg = g_K + (size_t)bh * NN * DA;
    const __half* Vg = g_V + (size_t)bh * NN * HD;

    auto prefetch = [&](int kt){
        uint32_t ka = sb + (uint32_t)(kt & 1) * KSTG;
        uint32_t va = sb + VBASE + (uint32_t)(kt & 1) * VSTG;
        int k0 = kt * BK;
#pragma unroll
        for (int i = 0; i < 5; i++) {
            int idx = t + i * 256;      // 0..1279 (128 rows x 10 chunks)
            int row = idx / 10;
            int c8  = (idx % 10) * 8;
            uint32_t so = (uint32_t)(row * QS + c8) * 2u;
            cp16(ka + so, Kg + (size_t)(k0 + row) * DA + c8);
        }
#pragma unroll
        for (int i = 0; i < 4; i++) {
            int idx = t + i * 256;      // 0..1023 (128 rows x 8 chunks)
            int row = idx >> 3;
            int c8  = (idx & 7) * 8;
            uint32_t so = (uint32_t)(row * VS + c8) * 2u;
            cp16(va + so, Vg + (size_t)(k0 + row) * HD + c8);
        }
        CP_COMMIT;
    };

    // prefetch tile 0 into stage 0; stage Q (128 x 80 fp16) into K stage 1 area
    prefetch(0);
#pragma unroll
    for (int i = 0; i < 5; i++) {
        int idx = t + i * 256;
        int row = idx / 10;
        int c8  = (idx % 10) * 8;
        uint32_t soff = (uint32_t)(row * QS + c8) * 2u;
        *(uint4*)(smem + KSTG + soff) = *(const uint4*)(Qg + (size_t)row * DA + c8);
    }
    __syncthreads();

    const int a_r   = (lane & 7) + ((lane & 8) ? 8 : 0);
    const int a_c8  = (lane & 16) ? 8 : 0;
    const int b_r   = lane & 7;
    const int b_c8  = (lane & 8) ? 8 : 0;
    const int b_r16 = (lane & 16) ? 8 : 0;
    const int v_r8  = (lane & 8) ? 8 : 0;

    uint32_t Qf[5][4];
#pragma unroll
    for (int s = 0; s < 5; s++) {
        uint32_t ad = sb + KSTG + (uint32_t)(((w*16 + a_r) * QS + s*16 + a_c8) * 2);
        ldsm_x4(ad, Qf[s]);
    }
    __syncthreads();   // Q area free before prefetch(1) overwrites K stage 1

    float mrow[2] = {-1e30f, -1e30f};
    float lrow[2] = {0.f, 0.f};
    float Od[8][4];
#pragma unroll
    for (int db = 0; db < 8; db++)
#pragma unroll
        for (int i = 0; i < 4; i++) Od[db][i] = 0.f;

#pragma unroll 1
    for (int kt = 0; kt < NT2; kt++) {
        if (kt + 1 < NT2) {
            prefetch(kt + 1);
            CP_WAIT1;
        } else {
            CP_WAIT0;
        }
        __syncthreads();
        uint32_t ka = sb + (uint32_t)(kt & 1) * KSTG;
        uint32_t va = sb + VBASE + (uint32_t)(kt & 1) * VSTG;

        // ---- S = Q . K^T over 128 keys (single fp16, 1 MMA per fragment) ----
        float Cs[16][4];
#pragma unroll
        for (int nb = 0; nb < 16; nb++)
#pragma unroll
            for (int i = 0; i < 4; i++) Cs[nb][i] = 0.f;

#pragma unroll
        for (int s = 0; s < 5; s++) {
#pragma unroll
            for (int j = 0; j < 8; j++) {
                uint32_t kd = ka + (uint32_t)(((j*16 + b_r + b_r16) * QS + s*16 + b_c8) * 2);
                uint32_t h4[4];
                ldsm_x4(kd, h4);
                mma16816h(Cs[2*j],   Qf[s], h4+0);
                mma16816h(Cs[2*j+1], Qf[s], h4+2);
            }
        }

        // ---- joint max over all 128 keys ----
        float mx0 = -1e30f, mx1 = -1e30f;
#pragma unroll
        for (int nb = 0; nb < 16; nb++) {
            mx0 = fmaxf(mx0, fmaxf(Cs[nb][0], Cs[nb][1]));
            mx1 = fmaxf(mx1, fmaxf(Cs[nb][2], Cs[nb][3]));
        }
        mx0 = fmaxf(mx0, __shfl_xor_sync(0xffffffffu, mx0, 1));
        mx0 = fmaxf(mx0, __shfl_xor_sync(0xffffffffu, mx0, 2));
        mx1 = fmaxf(mx1, __shfl_xor_sync(0xffffffffu, mx1, 1));
        mx1 = fmaxf(mx1, __shfl_xor_sync(0xffffffffu, mx1, 2));
        float mn0 = fmaxf(mrow[0], mx0);
        float mn1 = fmaxf(mrow[1], mx1);
        float f0  = ex2(mrow[0] - mn0);
        float f1  = ex2(mrow[1] - mn1);
        mrow[0] = mn0; mrow[1] = mn1;

#pragma unroll
        for (int db = 0; db < 8; db++) {
            Od[db][0] *= f0; Od[db][1] *= f0;
            Od[db][2] *= f1; Od[db][3] *= f1;
        }

        float s0 = 0.f, s1 = 0.f;
        // ---- two 64-key halves: softmax(h) then PV(h) ----
#pragma unroll
        for (int h = 0; h < 2; h++) {
            uint32_t Ph[4][4];
#pragma unroll
            for (int ks = 0; ks < 4; ks++) {
#pragma unroll
                for (int hf = 0; hf < 2; hf++) {
                    int nb = h*8 + 2*ks + hf;
                    float p0 = ex2(Cs[nb][0] - mn0);
                    float p1 = ex2(Cs[nb][1] - mn0);
                    float p2 = ex2(Cs[nb][2] - mn1);
                    float p3 = ex2(Cs[nb][3] - mn1);
                    s0 += p0 + p1;
                    s1 += p2 + p3;
                    Ph[ks][hf*2+0] = h2u(__floats2half2_rn(p0, p1));
                    Ph[ks][hf*2+1] = h2u(__floats2half2_rn(p2, p3));
                }
            }
#pragma unroll
            for (int ks = 0; ks < 4; ks++) {
#pragma unroll
                for (int j = 0; j < 4; j++) {
                    uint32_t vd = va + (uint32_t)(((h*64 + ks*16 + b_r + v_r8) * VS + j*16 + b_r16) * 2);
                    uint32_t h4[4];
                    ldsm_x4t(vd, h4);
                    mma16816h(Od[2*j],   Ph[ks], h4+0);
                    mma16816h(Od[2*j+1], Ph[ks], h4+2);
                }
            }
        }

        s0 += __shfl_xor_sync(0xffffffffu, s0, 1);
        s0 += __shfl_xor_sync(0xffffffffu, s0, 2);
        s1 += __shfl_xor_sync(0xffffffffu, s1, 1);
        s1 += __shfl_xor_sync(0xffffffffu, s1, 2);
        lrow[0] = lrow[0] * f0 + s0;
        lrow[1] = lrow[1] * f1 + s1;
        __syncthreads();
    }

    // ---- epilogue: write att as fp16 single ----
    float i0 = 1.0f / lrow[0];
    float i1 = 1.0f / lrow[1];
    int b = bh >> 3, h = bh & 7;
    int r0l = w*16 + (lane >> 2);
    int c0l = (lane & 3) * 2;
#pragma unroll
    for (int db = 0; db < 8; db++) {
        int gc = h*64 + db*8 + c0l;
        uint32_t v0 = h2u(__floats2half2_rn(Od[db][0] * i0, Od[db][1] * i0));
        uint32_t v1 = h2u(__floats2half2_rn(Od[db][2] * i1, Od[db][3] * i1));
        size_t o0r = ((size_t)(b*NN + q0 + r0l)) * DD + gc;
        size_t o1r = ((size_t)(b*NN + q0 + r0l + 8)) * DD + gc;
        *(uint32_t*)&g_att[o0r] = v0;
        *(uint32_t*)&g_att[o1r] = v1;
    }
}

// ---------------- launch ----------------
extern "C" void kernel_launch(void* const* d_in, const int* in_sizes, int n_in,
                              void* d_out, int out_size)
{
    const float* x   = (const float*)d_in[0];
    const float* pc  = (const float*)d_in[1];
    const float* Wq  = (const float*)d_in[2];
    const float* bq  = (const float*)d_in[3];
    const float* Wk  = (const float*)d_in[4];
    const float* bk  = (const float*)d_in[5];
    const float* Wv  = (const float*)d_in[6];
    const float* bv  = (const float*)d_in[7];
    const float* Wo  = (const float*)d_in[8];
    const float* bo  = (const float*)d_in[9];
    const float* pb  = (const float*)d_in[10];
    float* out = (float*)d_out;

    cudaFuncSetAttribute(attn_mma_kernel,  cudaFuncAttributeMaxDynamicSharedMemorySize, ATTN_SMEM);
    cudaFuncSetAttribute(qkv_mma_kernel,   cudaFuncAttributeMaxDynamicSharedMemorySize, GEMM_SMEM);
    cudaFuncSetAttribute(oproj_mma_kernel, cudaFuncAttributeMaxDynamicSharedMemorySize, OPROJ_SMEM);

    int totc = XC + 4*WC;
    convert_kernel<<<(totc + 255)/256, 256>>>(x, Wq, Wk, Wv, Wo);

    dim3 qgrid(4, 32, 3);
    qkv_mma_kernel<<<qgrid, 256, GEMM_SMEM>>>(bq, bk, bv);

    phase_fill_kernel<<<(BB*NN*HH + 255)/256, 256>>>(pc, pb);

    dim3 agrid(NN/BQ, BB*HH);   // (16, 16)
    attn_mma_kernel<<<agrid, 256, ATTN_SMEM>>>();

    dim3 ggrid(4, 32);
    oproj_mma_kernel<<<ggrid, 256, OPROJ_SMEM>>>(bo, out);
}